// round 1
// baseline (speedup 1.0000x reference)
#include <cuda_runtime.h>
#include <math.h>

#define Bb 4
#define Ll 1024
#define Dd 1024
#define Hh 16
#define Ff 4096
#define Ss 4

// ---------------- scratch (static device globals; no allocations) ----------------
__device__ float g_xp[Bb*(Ll+4)*Dd];      // padded input for dilated conv
__device__ float g_xc[Bb*Ll*Dd];          // conv output (scale 0)
__device__ float g_sc1[Bb*512*Dd];
__device__ float g_sc2[Bb*256*Dd];
__device__ float g_sc3[Bb*128*Dd];
__device__ float g_q[Bb*Ll*Dd];
__device__ float g_k[Bb*Ll*Dd];
__device__ float g_v[Bb*Ll*Dd];
__device__ float g_ctx[Bb*Ll*Dd];         // aggregated attention context (pre-Wo)
__device__ float g_x1[Bb*Ll*Dd];
__device__ float g_ffn[Bb*Ll*Ff];
__device__ float g_tmp[Bb*Ll*Dd];         // maha / ffn2 output
__device__ float g_wt_dc[3*Dd*Dd];        // W_dc transposed to [k][in][out]
__device__ float g_wt_dec[3*2*Dd*Dd];     // W_dec transposed to [s][k][in][out]
__device__ float g_w[Ss];                 // softmax(agg_logits)

// ---------------- generic tiled GEMM: C[M,N] (+)= Arows @ B[K,N] ----------------
// A row r lives at: A + (r/lseg)*segStride + (r%lseg)*rowStride + offA   (floats)
// epi: 0 none, 1 relu, 2 exact gelu.  bias: per-column, nullptr if none.
__global__ __launch_bounds__(256) void gemm64(
    const float* __restrict__ A, const float* __restrict__ Bm,
    float* __restrict__ C, const float* __restrict__ bias,
    int M, int N, int K,
    int lseg, long long segStride, int rowStride, long long offA,
    int accum, int epi)
{
    __shared__ float As[16][68];   // [k][m]
    __shared__ float Bs[16][68];   // [k][n]
    int tid = threadIdx.x;
    int rA = tid >> 4;             // 0..15
    int cA = tid & 15;             // 0..15
    int m0 = blockIdx.y * 64;
    int n0 = blockIdx.x * 64;

    const float* aptr[4];
#pragma unroll
    for (int j = 0; j < 4; j++) {
        int r = m0 + rA + 16*j;
        aptr[j] = A + (long long)(r / lseg) * segStride
                    + (long long)(r % lseg) * rowStride + offA;
    }
    const float* bptr = Bm + (long long)rA * N + n0 + cA*4;

    float acc[4][4];
#pragma unroll
    for (int i = 0; i < 4; i++)
#pragma unroll
        for (int j = 0; j < 4; j++) acc[i][j] = 0.f;

    for (int kt = 0; kt < K; kt += 16) {
#pragma unroll
        for (int j = 0; j < 4; j++)
            As[cA][rA + 16*j] = aptr[j][kt + cA];
        float4 bv = *(const float4*)(bptr + (long long)kt * N);
        *(float4*)&Bs[rA][cA*4] = bv;
        __syncthreads();
#pragma unroll
        for (int kk = 0; kk < 16; kk++) {
            float4 av = *(const float4*)&As[kk][rA*4];
            float4 bw = *(const float4*)&Bs[kk][cA*4];
            acc[0][0] += av.x*bw.x; acc[0][1] += av.x*bw.y; acc[0][2] += av.x*bw.z; acc[0][3] += av.x*bw.w;
            acc[1][0] += av.y*bw.x; acc[1][1] += av.y*bw.y; acc[1][2] += av.y*bw.z; acc[1][3] += av.y*bw.w;
            acc[2][0] += av.z*bw.x; acc[2][1] += av.z*bw.y; acc[2][2] += av.z*bw.z; acc[2][3] += av.z*bw.w;
            acc[3][0] += av.w*bw.x; acc[3][1] += av.w*bw.y; acc[3][2] += av.w*bw.z; acc[3][3] += av.w*bw.w;
        }
        __syncthreads();
    }

#pragma unroll
    for (int i = 0; i < 4; i++) {
        long long row = m0 + rA*4 + i;
        float* crow = C + row * N + n0 + cA*4;
#pragma unroll
        for (int j = 0; j < 4; j++) {
            float v = acc[i][j];
            if (accum) v += crow[j];
            if (bias)  v += bias[n0 + cA*4 + j];
            if (epi == 1)      v = fmaxf(v, 0.f);
            else if (epi == 2) v = 0.5f * v * (1.f + erff(v * 0.70710678118654752f));
            crow[j] = v;
        }
    }
}

// ---------------- fused flash attention (64 q-tile, 32 k-tile, dh=64) ----------------
// ctx[b,q,h*64+d] (first ? = : +=) w[s] * softmax(QK^T/8) @ V
__global__ __launch_bounds__(256) void attn64(
    const float* __restrict__ Q, const float* __restrict__ Km,
    const float* __restrict__ V, float* __restrict__ ctx,
    const float* __restrict__ gw, int s, int Ls, int first)
{
    __shared__ float sQ[64][68];   // [d][q]
    __shared__ float sK[64][34];   // [d][k]
    __shared__ float sV[32][68];   // [k][d]
    __shared__ float sP[64][34];   // [q][k]

    int tid = threadIdx.x;
    int b = blockIdx.z, h = blockIdx.y;
    int q0 = blockIdx.x * 64;
    int ty = tid >> 4, tx = tid & 15;

    for (int l = tid; l < 64*64; l += 256) {
        int qq = l >> 6, d = l & 63;
        sQ[d][qq] = Q[((long long)(b*Ll + q0 + qq))*Dd + h*64 + d];
    }

    float m[4], lsum[4], o[4][4];
#pragma unroll
    for (int i = 0; i < 4; i++) {
        m[i] = -1e30f; lsum[i] = 0.f;
#pragma unroll
        for (int j = 0; j < 4; j++) o[i][j] = 0.f;
    }
    __syncthreads();

    for (int k0 = 0; k0 < Ls; k0 += 32) {
        for (int l = tid; l < 32*64; l += 256) {
            int kk = l >> 6, d = l & 63;
            long long gi = ((long long)(b*Ls + k0 + kk))*Dd + h*64 + d;
            sK[d][kk] = Km[gi];
            sV[kk][d] = V[gi];
        }
        __syncthreads();

        float sc[4][2];
#pragma unroll
        for (int i = 0; i < 4; i++) { sc[i][0] = 0.f; sc[i][1] = 0.f; }
#pragma unroll 16
        for (int d = 0; d < 64; d++) {
            float4 qv = *(const float4*)&sQ[d][ty*4];
            float2 kv = *(const float2*)&sK[d][tx*2];
            sc[0][0] += qv.x*kv.x; sc[0][1] += qv.x*kv.y;
            sc[1][0] += qv.y*kv.x; sc[1][1] += qv.y*kv.y;
            sc[2][0] += qv.z*kv.x; sc[2][1] += qv.z*kv.y;
            sc[3][0] += qv.w*kv.x; sc[3][1] += qv.w*kv.y;
        }
#pragma unroll
        for (int i = 0; i < 4; i++) {
            sc[i][0] *= 0.125f; sc[i][1] *= 0.125f;
            float tm = fmaxf(sc[i][0], sc[i][1]);
#pragma unroll
            for (int off = 1; off < 16; off <<= 1)
                tm = fmaxf(tm, __shfl_xor_sync(0xffffffffu, tm, off));
            float mn  = fmaxf(m[i], tm);
            float fac = __expf(m[i] - mn);
            float p0 = __expf(sc[i][0] - mn);
            float p1 = __expf(sc[i][1] - mn);
            float ts = p0 + p1;
#pragma unroll
            for (int off = 1; off < 16; off <<= 1)
                ts += __shfl_xor_sync(0xffffffffu, ts, off);
            lsum[i] = lsum[i]*fac + ts;
            m[i] = mn;
            o[i][0]*=fac; o[i][1]*=fac; o[i][2]*=fac; o[i][3]*=fac;
            float2 pv; pv.x = p0; pv.y = p1;
            *(float2*)&sP[ty*4+i][tx*2] = pv;
        }
        __syncthreads();
#pragma unroll 8
        for (int kk = 0; kk < 32; kk++) {
            float4 vv = *(const float4*)&sV[kk][tx*4];
#pragma unroll
            for (int i = 0; i < 4; i++) {
                float p = sP[ty*4+i][kk];
                o[i][0] += p*vv.x; o[i][1] += p*vv.y; o[i][2] += p*vv.z; o[i][3] += p*vv.w;
            }
        }
        __syncthreads();
    }

    float w = gw[s];
#pragma unroll
    for (int i = 0; i < 4; i++) {
        float inv = w / lsum[i];
        long long base = ((long long)(b*Ll + q0 + ty*4 + i))*Dd + h*64 + tx*4;
#pragma unroll
        for (int j = 0; j < 4; j++) {
            float val = o[i][j] * inv;
            if (first) ctx[base + j] = val;
            else       ctx[base + j] += val;
        }
    }
}

// ---------------- LayerNorm over last dim (D=1024): out = LN(a + r) ----------------
__global__ __launch_bounds__(256) void ln_kernel(
    const float* __restrict__ a, const float* __restrict__ r,
    const float* __restrict__ gamma, const float* __restrict__ beta,
    float* __restrict__ out)
{
    __shared__ float red[8], red2[8];
    __shared__ float smu, sinv;
    int row = blockIdx.x, tid = threadIdx.x;
    long long base = (long long)row * Dd;
    float4 va = ((const float4*)(a + base))[tid];
    float4 vr = ((const float4*)(r + base))[tid];
    float x0 = va.x+vr.x, x1 = va.y+vr.y, x2 = va.z+vr.z, x3 = va.w+vr.w;
    float s  = x0+x1+x2+x3;
    float s2 = x0*x0 + x1*x1 + x2*x2 + x3*x3;
#pragma unroll
    for (int off = 16; off >= 1; off >>= 1) {
        s  += __shfl_xor_sync(0xffffffffu, s,  off);
        s2 += __shfl_xor_sync(0xffffffffu, s2, off);
    }
    int w = tid >> 5, lane = tid & 31;
    if (lane == 0) { red[w] = s; red2[w] = s2; }
    __syncthreads();
    if (tid == 0) {
        float S = 0.f, S2 = 0.f;
        for (int i = 0; i < 8; i++) { S += red[i]; S2 += red2[i]; }
        float mu = S * (1.f/Dd);
        smu = mu;
        sinv = rsqrtf(S2 * (1.f/Dd) - mu*mu + 1e-5f);
    }
    __syncthreads();
    float mu = smu, inv = sinv;
    float4 gg = ((const float4*)gamma)[tid];
    float4 bb = ((const float4*)beta)[tid];
    float4 y;
    y.x = (x0-mu)*inv*gg.x + bb.x;
    y.y = (x1-mu)*inv*gg.y + bb.y;
    y.z = (x2-mu)*inv*gg.z + bb.z;
    y.w = (x3-mu)*inv*gg.w + bb.w;
    ((float4*)(out + base))[tid] = y;
}

// ---------------- small helpers ----------------
__global__ void pad_kernel(const float* __restrict__ x)
{
    const long long total = (long long)Bb*(Ll+4)*Dd;
    for (long long i = blockIdx.x*256LL + threadIdx.x; i < total; i += (long long)gridDim.x*256LL) {
        int d = (int)(i % Dd);
        long long t = i / Dd;
        int p = (int)(t % (Ll+4));
        int b = (int)(t / (Ll+4));
        float v = 0.f;
        if (p >= 2 && p < Ll+2)
            v = x[((long long)b*Ll + (p-2))*Dd + d];
        g_xp[i] = v;
    }
}

__global__ void tdc_kernel(const float* __restrict__ W)   // W[o][i][k] -> [k][i][o]
{
    const long long total = 3LL*Dd*Dd;
    for (long long idx = blockIdx.x*256LL + threadIdx.x; idx < total; idx += (long long)gridDim.x*256LL) {
        int k = (int)(idx / ((long long)Dd*Dd));
        long long rem = idx % ((long long)Dd*Dd);
        int i = (int)(rem / Dd), o = (int)(rem % Dd);
        g_wt_dc[idx] = W[((long long)o*Dd + i)*3 + k];
    }
}

__global__ void tdec_kernel(const float* __restrict__ W)  // W[s][o][i][k] -> [s][k][i][o]
{
    const long long total = 6LL*Dd*Dd;
    for (long long idx = blockIdx.x*256LL + threadIdx.x; idx < total; idx += (long long)gridDim.x*256LL) {
        int sk = (int)(idx / ((long long)Dd*Dd));
        int s = sk >> 1, k = sk & 1;
        long long rem = idx % ((long long)Dd*Dd);
        int i = (int)(rem / Dd), o = (int)(rem % Dd);
        g_wt_dec[idx] = W[(((long long)s*Dd + o)*Dd + i)*2 + k];
    }
}

__global__ void agg_kernel(const float* __restrict__ logits, float* __restrict__ aux)
{
    float mx = -1e30f;
    for (int s = 0; s < Ss; s++) mx = fmaxf(mx, logits[s]);
    float e[Ss], sum = 0.f;
    for (int s = 0; s < Ss; s++) { e[s] = expf(logits[s] - mx); sum += e[s]; }
    float ent = 0.f;
    for (int s = 0; s < Ss; s++) {
        float w = e[s] / sum;
        g_w[s] = w;
        ent -= w * logf(w + 1e-9f);
    }
    if (aux) *aux = ent;
}

__global__ void fill0_kernel(float* p, long long n)
{
    for (long long i = blockIdx.x*256LL + threadIdx.x; i < n; i += (long long)gridDim.x*256LL)
        p[i] = 0.f;
}

// ---------------- launch ----------------
extern "C" void kernel_launch(void* const* d_in, const int* in_sizes, int n_in,
                              void* d_out, int out_size)
{
    const float* x     = (const float*)d_in[0];
    const float* W_dc  = (const float*)d_in[1];
    const float* b_dc  = (const float*)d_in[2];
    const float* W_dec = (const float*)d_in[3];
    const float* Wq    = (const float*)d_in[4];
    const float* Wk    = (const float*)d_in[5];
    const float* Wv    = (const float*)d_in[6];
    const float* Wo    = (const float*)d_in[7];
    const float* aggl  = (const float*)d_in[8];
    const float* g1    = (const float*)d_in[9];
    const float* be1   = (const float*)d_in[10];
    const float* g2    = (const float*)d_in[11];
    const float* be2   = (const float*)d_in[12];
    const float* W1    = (const float*)d_in[13];
    const float* b1    = (const float*)d_in[14];
    const float* W2    = (const float*)d_in[15];
    const float* b2    = (const float*)d_in[16];
    float* out = (float*)d_out;

    float *xp,*xc,*sc1,*sc2,*sc3,*q,*k,*v,*ctx,*x1,*ffn,*tmp,*wtdc,*wtdec,*gw;
    cudaGetSymbolAddress((void**)&xp,    g_xp);
    cudaGetSymbolAddress((void**)&xc,    g_xc);
    cudaGetSymbolAddress((void**)&sc1,   g_sc1);
    cudaGetSymbolAddress((void**)&sc2,   g_sc2);
    cudaGetSymbolAddress((void**)&sc3,   g_sc3);
    cudaGetSymbolAddress((void**)&q,     g_q);
    cudaGetSymbolAddress((void**)&k,     g_k);
    cudaGetSymbolAddress((void**)&v,     g_v);
    cudaGetSymbolAddress((void**)&ctx,   g_ctx);
    cudaGetSymbolAddress((void**)&x1,    g_x1);
    cudaGetSymbolAddress((void**)&ffn,   g_ffn);
    cudaGetSymbolAddress((void**)&tmp,   g_tmp);
    cudaGetSymbolAddress((void**)&wtdc,  g_wt_dc);
    cudaGetSymbolAddress((void**)&wtdec, g_wt_dec);
    cudaGetSymbolAddress((void**)&gw,    g_w);

    const long long DD = (long long)Dd*Dd;
    const int BLD = Bb*Ll*Dd;

    // weight transposes + input padding + aggregation weights / aux
    tdc_kernel <<<2048, 256>>>(W_dc);
    tdec_kernel<<<2048, 256>>>(W_dec);
    pad_kernel <<<4096, 256>>>(x);
    if (out_size > BLD) {
        long long gap = (long long)out_size - BLD;
        fill0_kernel<<<256, 256>>>(out + BLD, gap);
        agg_kernel<<<1, 1>>>(aggl, out + out_size - 1);
    } else {
        agg_kernel<<<1, 1>>>(aggl, (float*)0);
    }

    auto gemm = [&](const float* A, const float* Bm, float* C, const float* bias,
                    int M, int N, int K, int lseg, long long segStride,
                    int rowStride, long long offA, int accum, int epi) {
        dim3 g(N/64, M/64);
        gemm64<<<g, 256>>>(A, Bm, C, bias, M, N, K, lseg, segStride, rowStride, offA, accum, epi);
    };

    // 1. dilated conv (k=3, dil=2): 3 shifted GEMMs over padded input; ReLU+bias on last
    for (int kk = 0; kk < 3; kk++)
        gemm(xp, wtdc + kk*DD, xc, (kk == 2) ? b_dc : (const float*)0,
             Bb*Ll, Dd, Dd, Ll, (long long)(Ll+4)*Dd, Dd, (long long)(2*kk)*Dd,
             kk > 0, (kk == 2) ? 1 : 0);

    // 2. hierarchical decomposition: stride-2, k=2 convs (2 GEMMs each)
    {
        const float* ins[3]  = {xc, sc1, sc2};
        float*       outs[3] = {sc1, sc2, sc3};
        int          Lin[3]  = {1024, 512, 256};
        for (int s = 0; s < 3; s++)
            for (int kk = 0; kk < 2; kk++)
                gemm(ins[s], wtdec + (s*2 + kk)*DD, outs[s], (const float*)0,
                     Bb*(Lin[s]/2), Dd, Dd, Lin[s]/2, (long long)Lin[s]*Dd,
                     2*Dd, (long long)kk*Dd, kk > 0, 0);
    }

    // 3. multiscale attention, aggregated into ctx (pre-Wo, weighted by softmax(agg_logits))
    {
        const float* scs[4] = {xc, sc1, sc2, sc3};
        int Lss[4] = {1024, 512, 256, 128};
        for (int s = 0; s < 4; s++) {
            gemm(xc,     Wq + (long long)s*DD, q, (const float*)0, Bb*Ll,     Dd, Dd, Bb*Ll,     0, Dd, 0, 0, 0);
            gemm(scs[s], Wk + (long long)s*DD, k, (const float*)0, Bb*Lss[s], Dd, Dd, Bb*Lss[s], 0, Dd, 0, 0, 0);
            gemm(scs[s], Wv,                   v, (const float*)0, Bb*Lss[s], Dd, Dd, Bb*Lss[s], 0, Dd, 0, 0, 0);
            dim3 ag(Ll/64, Hh, Bb);
            attn64<<<ag, 256>>>(q, k, v, ctx, gw, s, Lss[s], s == 0);
        }
    }

    // 4. output projection (shared Wo applied once to aggregated ctx)
    gemm(ctx, Wo, tmp, (const float*)0, Bb*Ll, Dd, Dd, Bb*Ll, 0, Dd, 0, 0, 0);

    // 5. residual + LN1
    ln_kernel<<<Bb*Ll, 256>>>(x, tmp, g1, be1, x1);

    // 6. FFN: GELU fused into first GEMM epilogue
    gemm(x1,  W1, ffn, b1, Bb*Ll, Ff, Dd, Bb*Ll, 0, Dd, 0, 0, 2);
    gemm(ffn, W2, tmp, b2, Bb*Ll, Dd, Ff, Bb*Ll, 0, Ff, 0, 0, 0);

    // 7. residual + LN2 -> output
    ln_kernel<<<Bb*Ll, 256>>>(x1, tmp, g2, be2, out);
}

// round 3
// speedup vs baseline: 1.9248x; 1.9248x over previous
#include <cuda_runtime.h>
#include <cuda_bf16.h>
#include <math.h>
#include <stdint.h>

#define Bb 4
#define Ll 1024
#define Dd 1024
#define Hh 16
#define Ff 4096
#define Ss 4
#define DDc (1024LL*1024LL)

// ================= static scratch (no allocations) =================
__device__ __align__(256) __nv_bfloat16 g_xph[Bb*(Ll+4)*Dd], g_xpl[Bb*(Ll+4)*Dd];
__device__ __align__(256) __nv_bfloat16 g_xch[Bb*Ll*Dd],     g_xcl[Bb*Ll*Dd];
__device__ __align__(256) __nv_bfloat16 g_s1h[Bb*512*Dd],    g_s1l[Bb*512*Dd];
__device__ __align__(256) __nv_bfloat16 g_s2h[Bb*256*Dd],    g_s2l[Bb*256*Dd];
__device__ __align__(256) __nv_bfloat16 g_s3h[Bb*128*Dd],    g_s3l[Bb*128*Dd];
__device__ __align__(256) __nv_bfloat16 g_ctxh[Bb*Ll*Dd],    g_ctxl[Bb*Ll*Dd];
__device__ __align__(256) __nv_bfloat16 g_x1h[Bb*Ll*Dd],     g_x1l[Bb*Ll*Dd];
__device__ __align__(256) __nv_bfloat16 g_ffnh[Bb*Ll*Ff],    g_ffnl[Bb*Ll*Ff];
__device__ __align__(256) __nv_bfloat16 g_wdcth[3*1024*1024],  g_wdctl[3*1024*1024];
__device__ __align__(256) __nv_bfloat16 g_wdecth[6*1024*1024], g_wdectl[6*1024*1024];
__device__ __align__(256) __nv_bfloat16 g_wqth[4*1024*1024],   g_wqtl[4*1024*1024];
__device__ __align__(256) __nv_bfloat16 g_wkth[4*1024*1024],   g_wktl[4*1024*1024];
__device__ __align__(256) __nv_bfloat16 g_wvth[1024*1024],     g_wvtl[1024*1024];
__device__ __align__(256) __nv_bfloat16 g_woth[1024*1024],     g_wotl[1024*1024];
__device__ __align__(256) __nv_bfloat16 g_w1th[1024*4096],     g_w1tl[1024*4096];
__device__ __align__(256) __nv_bfloat16 g_w2th[4096*1024],     g_w2tl[4096*1024];
__device__ __align__(256) float g_q[Bb*Ll*Dd];
__device__ __align__(256) float g_k[Bb*Ll*Dd];
__device__ __align__(256) float g_v[Bb*Ll*Dd];
__device__ __align__(256) float g_ctx[Bb*Ll*Dd];
__device__ __align__(256) float g_x1[Bb*Ll*Dd];
__device__ __align__(256) float g_tmp[Bb*Ll*Dd];
__device__ float g_w[Ss];

// ================= PTX helpers (base features only) =================
#define CP16(dst, src)    asm volatile("cp.async.cg.shared.global [%0], [%1], 16;" :: "r"(dst), "l"(src) : "memory")
#define CP_COMMIT()       asm volatile("cp.async.commit_group;" ::: "memory")
#define CP_WAIT1()        asm volatile("cp.async.wait_group 1;" ::: "memory")
#define CP_WAIT0()        asm volatile("cp.async.wait_group 0;" ::: "memory")

#define LDSM4(r0,r1,r2,r3,addr) \
    asm volatile("ldmatrix.sync.aligned.m8n8.x4.shared.b16 {%0,%1,%2,%3}, [%4];" \
        : "=r"(r0),"=r"(r1),"=r"(r2),"=r"(r3) : "r"(addr))
#define LDSM2(r0,r1,addr) \
    asm volatile("ldmatrix.sync.aligned.m8n8.x2.shared.b16 {%0,%1}, [%2];" \
        : "=r"(r0),"=r"(r1) : "r"(addr))
#define MMA16816(d, a, b) \
    asm volatile("mma.sync.aligned.m16n8k16.row.col.f32.bf16.bf16.f32 " \
        "{%0,%1,%2,%3}, {%4,%5,%6,%7}, {%8,%9}, {%0,%1,%2,%3};" \
        : "+f"((d)[0]),"+f"((d)[1]),"+f"((d)[2]),"+f"((d)[3]) \
        : "r"((a)[0]),"r"((a)[1]),"r"((a)[2]),"r"((a)[3]), "r"((b)[0]),"r"((b)[1]))

__device__ __forceinline__ uint32_t smem_u32(const void* p) {
    uint32_t a;
    asm("{ .reg .u64 t; cvta.to.shared.u64 t, %1; cvt.u32.u64 %0, t; }" : "=r"(a) : "l"(p));
    return a;
}

__device__ __forceinline__ void split2(float x, __nv_bfloat16& h, __nv_bfloat16& l) {
    h = __float2bfloat16(x);
    l = __float2bfloat16(x - __bfloat162float(h));
}

// ================= mma.sync split-bf16 GEMM =================
// C[M,N] = sum_tap Arows(tap) @ B[tap]; A row r at (r/lseg)*segStride + (r%lseg)*rowStride + offA
// B layout [tap][N][K] bf16 hi/lo (K-major). Outputs fp32 Cf and/or split bf16 Oh/Ol.
// epi: 0 none, 1 relu, 2 exact gelu. 128x128 block tile, K-chunks of 64.
__global__ __launch_bounds__(256, 1) void gemmM(
    const __nv_bfloat16* __restrict__ Ah, const __nv_bfloat16* __restrict__ Al,
    const __nv_bfloat16* __restrict__ Bh, const __nv_bfloat16* __restrict__ Bl,
    float* __restrict__ Cf, __nv_bfloat16* __restrict__ Oh, __nv_bfloat16* __restrict__ Ol,
    const float* __restrict__ bias,
    int N, int K, int taps, long long tapStrideA,
    int lseg, long long segStride, int rowStride, long long offA, int epi)
{
    extern __shared__ char smem[];
    uint32_t sb = smem_u32(smem);
    const int tid = threadIdx.x;
    const int wid = tid >> 5, lane = tid & 31;
    const int m0 = blockIdx.y * 128, n0 = blockIdx.x * 128;

    // ---- cp.async load mapping: row r = tid/2, half = tid&1 (64B each) ----
    const int r = tid >> 1, half = tid & 1;
    const long long mrow = m0 + r;
    const long long aoff0 = (mrow / lseg) * segStride + (mrow % lseg) * (long long)rowStride + offA + half * 32;
    const long long boff0 = (long long)(n0 + r) * K + half * 32;
    uint32_t dstOff[4];
#pragma unroll
    for (int j = 0; j < 4; j++) {
        uint32_t off = (uint32_t)(r * 128 + half * 64 + j * 16);
        dstOff[j] = off ^ ((off >> 3) & 0x70);
    }
    const uint32_t bufBase[2] = { sb, sb + 65536 };
    const int NCk = K >> 6;
    const int NC = NCk * taps;
    const long long tapStrideB = (long long)N * K;

    // ---- mma fragment addressing ----
    const int wm = wid & 1, wn = wid >> 1;                // 2x4 warp grid
    const int arow = wm * 64 + (lane & 15);
    const uint32_t aRowOff = (uint32_t)(arow * 128);
    const uint32_t aXb = (uint32_t)((arow & 7) << 4);
    const uint32_t aHalf = (uint32_t)((lane >> 4) * 16);
    const uint32_t bRowOff = (uint32_t)((wn * 32 + (lane & 7)) * 128);
    const uint32_t bXb = (uint32_t)((lane & 7) << 4);
    const uint32_t bHalf = (uint32_t)(((lane >> 3) & 1) * 16);

    float acc[4][4][4];
#pragma unroll
    for (int i = 0; i < 4; i++)
#pragma unroll
        for (int j = 0; j < 4; j++)
#pragma unroll
            for (int e = 0; e < 4; e++) acc[i][j][e] = 0.f;

    // ---- prologue: issue chunks 0,1 ----
#pragma unroll 1
    for (int c = 0; c < 2 && c < NC; c++) {
        int tap = c / NCk, kc = c % NCk;
        long long ao = aoff0 + (long long)tap * tapStrideA + kc * 64;
        long long bo = boff0 + (long long)tap * tapStrideB + kc * 64;
        uint32_t bs = bufBase[c & 1];
#pragma unroll
        for (int j = 0; j < 4; j++) {
            CP16(bs +         dstOff[j], Ah + ao + j * 8);
            CP16(bs + 16384 + dstOff[j], Al + ao + j * 8);
            CP16(bs + 32768 + dstOff[j], Bh + bo + j * 8);
            CP16(bs + 49152 + dstOff[j], Bl + bo + j * 8);
        }
        CP_COMMIT();
    }

#pragma unroll 1
    for (int c = 0; c < NC; c++) {
        const int buf = c & 1;
        if (c >= NC - 2) { if (c == NC - 1) CP_WAIT0(); else CP_WAIT1(); }
        else CP_WAIT1();
        __syncthreads();

        const uint32_t bs = bufBase[buf];
#pragma unroll
        for (int k16 = 0; k16 < 4; k16++) {
            const uint32_t aoff = aRowOff + ((k16 * 32 + aHalf) ^ aXb);
            const uint32_t boff = bRowOff + ((k16 * 32 + bHalf) ^ bXb);
            uint32_t ah[4][4], al_[4][4], bh[4][2], bl[4][2];
#pragma unroll
            for (int i = 0; i < 4; i++) {
                LDSM4(ah[i][0], ah[i][1], ah[i][2], ah[i][3], bs + i * 2048 + aoff);
                LDSM4(al_[i][0], al_[i][1], al_[i][2], al_[i][3], bs + 16384 + i * 2048 + aoff);
            }
#pragma unroll
            for (int j = 0; j < 4; j++) {
                LDSM2(bh[j][0], bh[j][1], bs + 32768 + j * 1024 + boff);
                LDSM2(bl[j][0], bl[j][1], bs + 49152 + j * 1024 + boff);
            }
#pragma unroll
            for (int i = 0; i < 4; i++)
#pragma unroll
                for (int j = 0; j < 4; j++) {
                    MMA16816(acc[i][j], ah[i],  bh[j]);
                    MMA16816(acc[i][j], al_[i], bh[j]);
                    MMA16816(acc[i][j], ah[i],  bl[j]);
                }
        }
        __syncthreads();

        if (c + 2 < NC) {
            int cc = c + 2;
            int tap = cc / NCk, kc = cc % NCk;
            long long ao = aoff0 + (long long)tap * tapStrideA + kc * 64;
            long long bo = boff0 + (long long)tap * tapStrideB + kc * 64;
#pragma unroll
            for (int j = 0; j < 4; j++) {
                CP16(bs +         dstOff[j], Ah + ao + j * 8);
                CP16(bs + 16384 + dstOff[j], Al + ao + j * 8);
                CP16(bs + 32768 + dstOff[j], Bh + bo + j * 8);
                CP16(bs + 49152 + dstOff[j], Bl + bo + j * 8);
            }
            CP_COMMIT();
        }
    }

    // ---- epilogue ----
#pragma unroll
    for (int i = 0; i < 4; i++)
#pragma unroll
        for (int j = 0; j < 4; j++)
#pragma unroll
            for (int p = 0; p < 2; p++) {
                int rr = m0 + wm * 64 + i * 16 + (lane >> 2) + p * 8;
                int cc = n0 + wn * 32 + j * 8 + (lane & 3) * 2;
                float v0 = acc[i][j][p * 2];
                float v1 = acc[i][j][p * 2 + 1];
                if (bias) { v0 += bias[cc]; v1 += bias[cc + 1]; }
                if (epi == 1) { v0 = fmaxf(v0, 0.f); v1 = fmaxf(v1, 0.f); }
                else if (epi == 2) {
                    v0 = 0.5f * v0 * (1.f + erff(v0 * 0.70710678118654752f));
                    v1 = 0.5f * v1 * (1.f + erff(v1 * 0.70710678118654752f));
                }
                long long idx = (long long)rr * N + cc;
                if (Cf) { float2 f; f.x = v0; f.y = v1; *(float2*)(Cf + idx) = f; }
                if (Oh) {
                    __nv_bfloat16 h0, l0, h1, l1;
                    split2(v0, h0, l0); split2(v1, h1, l1);
                    __nv_bfloat162 hh; hh.x = h0; hh.y = h1;
                    __nv_bfloat162 ll; ll.x = l0; ll.y = l1;
                    *(__nv_bfloat162*)(Oh + idx) = hh;
                    *(__nv_bfloat162*)(Ol + idx) = ll;
                }
            }
}

// ================= flash attention (fp32) =================
__global__ __launch_bounds__(256) void attn64(
    const float* __restrict__ Q, const float* __restrict__ Km,
    const float* __restrict__ V, float* __restrict__ ctx,
    const float* __restrict__ gw, int s, int Ls, int first)
{
    __shared__ float sQ[64][68];
    __shared__ float sK[64][34];
    __shared__ float sV[32][68];
    __shared__ float sP[64][34];

    int tid = threadIdx.x;
    int b = blockIdx.z, h = blockIdx.y;
    int q0 = blockIdx.x * 64;
    int ty = tid >> 4, tx = tid & 15;

    for (int l = tid; l < 64*64; l += 256) {
        int qq = l >> 6, d = l & 63;
        sQ[d][qq] = Q[((long long)(b*Ll + q0 + qq))*Dd + h*64 + d];
    }
    float m[4], lsum[4], o[4][4];
#pragma unroll
    for (int i = 0; i < 4; i++) {
        m[i] = -1e30f; lsum[i] = 0.f;
#pragma unroll
        for (int j = 0; j < 4; j++) o[i][j] = 0.f;
    }
    __syncthreads();

    for (int k0 = 0; k0 < Ls; k0 += 32) {
        for (int l = tid; l < 32*64; l += 256) {
            int kk = l >> 6, d = l & 63;
            long long gi = ((long long)(b*Ls + k0 + kk))*Dd + h*64 + d;
            sK[d][kk] = Km[gi];
            sV[kk][d] = V[gi];
        }
        __syncthreads();
        float sc[4][2];
#pragma unroll
        for (int i = 0; i < 4; i++) { sc[i][0] = 0.f; sc[i][1] = 0.f; }
#pragma unroll 16
        for (int d = 0; d < 64; d++) {
            float4 qv = *(const float4*)&sQ[d][ty*4];
            float2 kv = *(const float2*)&sK[d][tx*2];
            sc[0][0] += qv.x*kv.x; sc[0][1] += qv.x*kv.y;
            sc[1][0] += qv.y*kv.x; sc[1][1] += qv.y*kv.y;
            sc[2][0] += qv.z*kv.x; sc[2][1] += qv.z*kv.y;
            sc[3][0] += qv.w*kv.x; sc[3][1] += qv.w*kv.y;
        }
#pragma unroll
        for (int i = 0; i < 4; i++) {
            sc[i][0] *= 0.125f; sc[i][1] *= 0.125f;
            float tm = fmaxf(sc[i][0], sc[i][1]);
#pragma unroll
            for (int off = 1; off < 16; off <<= 1)
                tm = fmaxf(tm, __shfl_xor_sync(0xffffffffu, tm, off));
            float mn  = fmaxf(m[i], tm);
            float fac = __expf(m[i] - mn);
            float p0 = __expf(sc[i][0] - mn);
            float p1 = __expf(sc[i][1] - mn);
            float ts = p0 + p1;
#pragma unroll
            for (int off = 1; off < 16; off <<= 1)
                ts += __shfl_xor_sync(0xffffffffu, ts, off);
            lsum[i] = lsum[i]*fac + ts;
            m[i] = mn;
            o[i][0]*=fac; o[i][1]*=fac; o[i][2]*=fac; o[i][3]*=fac;
            float2 pv; pv.x = p0; pv.y = p1;
            *(float2*)&sP[ty*4+i][tx*2] = pv;
        }
        __syncthreads();
#pragma unroll 8
        for (int kk = 0; kk < 32; kk++) {
            float4 vv = *(const float4*)&sV[kk][tx*4];
#pragma unroll
            for (int i = 0; i < 4; i++) {
                float p = sP[ty*4+i][kk];
                o[i][0] += p*vv.x; o[i][1] += p*vv.y; o[i][2] += p*vv.z; o[i][3] += p*vv.w;
            }
        }
        __syncthreads();
    }
    float w = gw[s];
#pragma unroll
    for (int i = 0; i < 4; i++) {
        float inv = w / lsum[i];
        long long base = ((long long)(b*Ll + q0 + ty*4 + i))*Dd + h*64 + tx*4;
#pragma unroll
        for (int j = 0; j < 4; j++) {
            float val = o[i][j] * inv;
            if (first) ctx[base + j] = val;
            else       ctx[base + j] += val;
        }
    }
}

// ================= LayerNorm: out = LN(a + r), optional split bf16 =================
__global__ __launch_bounds__(256) void ln_kernel(
    const float* __restrict__ a, const float* __restrict__ rr,
    const float* __restrict__ gamma, const float* __restrict__ beta,
    float* __restrict__ out, __nv_bfloat16* __restrict__ oh, __nv_bfloat16* __restrict__ ol)
{
    __shared__ float red[8], red2[8];
    __shared__ float smu, sinv;
    int row = blockIdx.x, tid = threadIdx.x;
    long long base = (long long)row * Dd;
    float4 va = ((const float4*)(a + base))[tid];
    float4 vr = ((const float4*)(rr + base))[tid];
    float x0 = va.x+vr.x, x1 = va.y+vr.y, x2 = va.z+vr.z, x3 = va.w+vr.w;
    float s  = x0+x1+x2+x3;
    float s2 = x0*x0 + x1*x1 + x2*x2 + x3*x3;
#pragma unroll
    for (int off = 16; off >= 1; off >>= 1) {
        s  += __shfl_xor_sync(0xffffffffu, s,  off);
        s2 += __shfl_xor_sync(0xffffffffu, s2, off);
    }
    int w = tid >> 5, lane = tid & 31;
    if (lane == 0) { red[w] = s; red2[w] = s2; }
    __syncthreads();
    if (tid == 0) {
        float S = 0.f, S2 = 0.f;
        for (int i = 0; i < 8; i++) { S += red[i]; S2 += red2[i]; }
        float mu = S * (1.f/Dd);
        smu = mu;
        sinv = rsqrtf(S2 * (1.f/Dd) - mu*mu + 1e-5f);
    }
    __syncthreads();
    float mu = smu, inv = sinv;
    float4 gg = ((const float4*)gamma)[tid];
    float4 bb = ((const float4*)beta)[tid];
    float y0 = (x0-mu)*inv*gg.x + bb.x;
    float y1 = (x1-mu)*inv*gg.y + bb.y;
    float y2 = (x2-mu)*inv*gg.z + bb.z;
    float y3 = (x3-mu)*inv*gg.w + bb.w;
    float4 y; y.x=y0; y.y=y1; y.z=y2; y.w=y3;
    ((float4*)(out + base))[tid] = y;
    if (oh) {
        __nv_bfloat16 h0,l0,h1,l1,h2,l2,h3,l3;
        split2(y0,h0,l0); split2(y1,h1,l1); split2(y2,h2,l2); split2(y3,h3,l3);
        __nv_bfloat162 a01; a01.x=h0; a01.y=h1;
        __nv_bfloat162 a23; a23.x=h2; a23.y=h3;
        __nv_bfloat162 b01; b01.x=l0; b01.y=l1;
        __nv_bfloat162 b23; b23.x=l2; b23.y=l3;
        ((__nv_bfloat162*)(oh + base))[tid*2]   = a01;
        ((__nv_bfloat162*)(oh + base))[tid*2+1] = a23;
        ((__nv_bfloat162*)(ol + base))[tid*2]   = b01;
        ((__nv_bfloat162*)(ol + base))[tid*2+1] = b23;
    }
}

// ================= preprocessing kernels =================
__global__ void pad_split_kernel(const float* __restrict__ x)
{
    const long long total = (long long)Bb*(Ll+4)*Dd;
    for (long long i = blockIdx.x*256LL + threadIdx.x; i < total; i += (long long)gridDim.x*256LL) {
        int d = (int)(i % Dd);
        long long t = i / Dd;
        int p = (int)(t % (Ll+4));
        int b = (int)(t / (Ll+4));
        float v = 0.f;
        if (p >= 2 && p < Ll+2)
            v = x[((long long)b*Ll + (p-2))*Dd + d];
        __nv_bfloat16 h, l; split2(v, h, l);
        g_xph[i] = h; g_xpl[i] = l;
    }
}

__global__ void split_act_kernel(const float* __restrict__ in,
                                 __nv_bfloat16* __restrict__ oh, __nv_bfloat16* __restrict__ ol,
                                 long long n)
{
    for (long long i = blockIdx.x*256LL + threadIdx.x; i < n; i += (long long)gridDim.x*256LL) {
        __nv_bfloat16 h, l; split2(in[i], h, l);
        oh[i] = h; ol[i] = l;
    }
}

__global__ void tdc_split(const float* __restrict__ W)
{
    const long long total = 3LL*Dd*Dd;
    for (long long idx = blockIdx.x*256LL + threadIdx.x; idx < total; idx += (long long)gridDim.x*256LL) {
        int tap = (int)(idx / (Dd*(long long)Dd));
        long long rem = idx % (Dd*(long long)Dd);
        int o = (int)(rem / Dd), i = (int)(rem % Dd);
        float v = W[((long long)o*Dd + i)*3 + tap];
        __nv_bfloat16 h, l; split2(v, h, l);
        g_wdcth[idx] = h; g_wdctl[idx] = l;
    }
}

__global__ void tdec_split(const float* __restrict__ W)
{
    const long long total = 6LL*Dd*Dd;
    for (long long idx = blockIdx.x*256LL + threadIdx.x; idx < total; idx += (long long)gridDim.x*256LL) {
        int st = (int)(idx / (Dd*(long long)Dd));
        int s = st >> 1, tap = st & 1;
        long long rem = idx % (Dd*(long long)Dd);
        int o = (int)(rem / Dd), i = (int)(rem % Dd);
        float v = W[(((long long)s*Dd + o)*Dd + i)*2 + tap];
        __nv_bfloat16 h, l; split2(v, h, l);
        g_wdecth[idx] = h; g_wdectl[idx] = l;
    }
}

__global__ void transpose_split(const float* __restrict__ W,
                                __nv_bfloat16* __restrict__ oh, __nv_bfloat16* __restrict__ ol,
                                int K, int N)
{
    __shared__ float t[32][33];
    int bx = blockIdx.x * 32;
    int by = blockIdx.y * 32;
    long long bz = blockIdx.z;
    const float* Wb = W + bz * (long long)K * N;
    int tx = threadIdx.x, ty = threadIdx.y;
    for (int i = ty; i < 32; i += 8)
        t[i][tx] = Wb[(long long)(by + i) * N + bx + tx];
    __syncthreads();
    long long ob = bz * (long long)N * K;
    for (int i = ty; i < 32; i += 8) {
        float v = t[tx][i];
        __nv_bfloat16 h, l; split2(v, h, l);
        long long oidx = ob + (long long)(bx + i) * K + by + tx;
        oh[oidx] = h; ol[oidx] = l;
    }
}

__global__ void agg_kernel(const float* __restrict__ logits, float* __restrict__ aux)
{
    float mx = -1e30f;
    for (int s = 0; s < Ss; s++) mx = fmaxf(mx, logits[s]);
    float e[Ss], sum = 0.f;
    for (int s = 0; s < Ss; s++) { e[s] = expf(logits[s] - mx); sum += e[s]; }
    float ent = 0.f;
    for (int s = 0; s < Ss; s++) {
        float w = e[s] / sum;
        g_w[s] = w;
        ent -= w * logf(w + 1e-9f);
    }
    if (aux) *aux = ent;
}

__global__ void fill0_kernel(float* p, long long n)
{
    for (long long i = blockIdx.x*256LL + threadIdx.x; i < n; i += (long long)gridDim.x*256LL)
        p[i] = 0.f;
}

// ================= launch =================
extern "C" void kernel_launch(void* const* d_in, const int* in_sizes, int n_in,
                              void* d_out, int out_size)
{
    const float* x     = (const float*)d_in[0];
    const float* W_dc  = (const float*)d_in[1];
    const float* b_dc  = (const float*)d_in[2];
    const float* W_dec = (const float*)d_in[3];
    const float* Wq    = (const float*)d_in[4];
    const float* Wk    = (const float*)d_in[5];
    const float* Wv    = (const float*)d_in[6];
    const float* Wo    = (const float*)d_in[7];
    const float* aggl  = (const float*)d_in[8];
    const float* g1    = (const float*)d_in[9];
    const float* be1   = (const float*)d_in[10];
    const float* g2    = (const float*)d_in[11];
    const float* be2   = (const float*)d_in[12];
    const float* W1    = (const float*)d_in[13];
    const float* b1    = (const float*)d_in[14];
    const float* W2    = (const float*)d_in[15];
    const float* b2    = (const float*)d_in[16];
    float* out = (float*)d_out;

    static int smem_set = 0;
    const int GEMM_SMEM = 2 * 65536;
    if (!smem_set) {
        cudaFuncSetAttribute(gemmM, cudaFuncAttributeMaxDynamicSharedMemorySize, GEMM_SMEM);
        smem_set = 1;
    }

#define SYM(v, s) cudaGetSymbolAddress((void**)&v, s)
    __nv_bfloat16 *xph,*xpl,*xch,*xcl,*s1h,*s1l,*s2h,*s2l,*s3h,*s3l,*ctxh,*ctxl,*x1h,*x1l,*ffnh,*ffnl;
    __nv_bfloat16 *wdcth,*wdctl,*wdecth,*wdectl,*wqth,*wqtl,*wkth,*wktl,*wvth,*wvtl,*woth,*wotl,*w1th,*w1tl,*w2th,*w2tl;
    float *q,*k,*v,*ctx,*x1,*tmp,*gw;
    SYM(xph,g_xph); SYM(xpl,g_xpl); SYM(xch,g_xch); SYM(xcl,g_xcl);
    SYM(s1h,g_s1h); SYM(s1l,g_s1l); SYM(s2h,g_s2h); SYM(s2l,g_s2l); SYM(s3h,g_s3h); SYM(s3l,g_s3l);
    SYM(ctxh,g_ctxh); SYM(ctxl,g_ctxl); SYM(x1h,g_x1h); SYM(x1l,g_x1l); SYM(ffnh,g_ffnh); SYM(ffnl,g_ffnl);
    SYM(wdcth,g_wdcth); SYM(wdctl,g_wdctl); SYM(wdecth,g_wdecth); SYM(wdectl,g_wdectl);
    SYM(wqth,g_wqth); SYM(wqtl,g_wqtl); SYM(wkth,g_wkth); SYM(wktl,g_wktl);
    SYM(wvth,g_wvth); SYM(wvtl,g_wvtl); SYM(woth,g_woth); SYM(wotl,g_wotl);
    SYM(w1th,g_w1th); SYM(w1tl,g_w1tl); SYM(w2th,g_w2th); SYM(w2tl,g_w2tl);
    SYM(q,g_q); SYM(k,g_k); SYM(v,g_v); SYM(ctx,g_ctx); SYM(x1,g_x1); SYM(tmp,g_tmp); SYM(gw,g_w);
#undef SYM

    const int BLD = Bb*Ll*Dd;

    // ---- preprocessing ----
    tdc_split <<<1024, 256>>>(W_dc);
    tdec_split<<<2048, 256>>>(W_dec);
    {
        dim3 blk(32, 8);
        transpose_split<<<dim3(Dd/32, Dd/32, 4), blk>>>(Wq, wqth, wqtl, Dd, Dd);
        transpose_split<<<dim3(Dd/32, Dd/32, 4), blk>>>(Wk, wkth, wktl, Dd, Dd);
        transpose_split<<<dim3(Dd/32, Dd/32, 1), blk>>>(Wv, wvth, wvtl, Dd, Dd);
        transpose_split<<<dim3(Dd/32, Dd/32, 1), blk>>>(Wo, woth, wotl, Dd, Dd);
        transpose_split<<<dim3(Ff/32, Dd/32, 1), blk>>>(W1, w1th, w1tl, Dd, Ff);
        transpose_split<<<dim3(Dd/32, Ff/32, 1), blk>>>(W2, w2th, w2tl, Ff, Dd);
    }
    pad_split_kernel<<<4096, 256>>>(x);
    if (out_size > BLD) {
        long long gap = (long long)out_size - BLD;
        fill0_kernel<<<256, 256>>>(out + BLD, gap);
        agg_kernel<<<1, 1>>>(aggl, out + out_size - 1);
    } else {
        agg_kernel<<<1, 1>>>(aggl, (float*)0);
    }

    auto gemm = [&](const __nv_bfloat16* Ah, const __nv_bfloat16* Al,
                    const __nv_bfloat16* Bh, const __nv_bfloat16* Bl,
                    float* Cf, __nv_bfloat16* Oh, __nv_bfloat16* Ol, const float* bias,
                    int M, int N, int K, int taps, long long tapStrideA,
                    int lseg, long long segStride, int rowStride, long long offA, int epi) {
        dim3 g(N/128, M/128);
        gemmM<<<g, 256, GEMM_SMEM>>>(Ah, Al, Bh, Bl, Cf, Oh, Ol, bias,
                                     N, K, taps, tapStrideA, lseg, segStride, rowStride, offA, epi);
    };

    // 1. dilated conv (k=3, dil=2) + bias + ReLU -> xc split
    gemm(xph, xpl, wdcth, wdctl, 0, xch, xcl, b_dc,
         Bb*Ll, Dd, Dd, 3, 2LL*Dd, Ll, (long long)(Ll+4)*Dd, Dd, 0, 1);

    // 2. hierarchical decomposition (stride-2, k=2)
    {
        const __nv_bfloat16* ih[3] = {xch, s1h, s2h};
        const __nv_bfloat16* il[3] = {xcl, s1l, s2l};
        __nv_bfloat16* oh[3] = {s1h, s2h, s3h};
        __nv_bfloat16* ol[3] = {s1l, s2l, s3l};
        int Lin[3] = {1024, 512, 256};
        for (int s = 0; s < 3; s++)
            gemm(ih[s], il[s], wdecth + (long long)s*2*DDc, wdectl + (long long)s*2*DDc,
                 0, oh[s], ol[s], 0,
                 Bb*(Lin[s]/2), Dd, Dd, 2, (long long)Dd,
                 Lin[s]/2, (long long)Lin[s]*Dd, 2*Dd, 0, 0);
    }

    // 3. multiscale attention -> ctx (weighted accumulation, pre-Wo)
    {
        const __nv_bfloat16* sh[4] = {xch, s1h, s2h, s3h};
        const __nv_bfloat16* sl[4] = {xcl, s1l, s2l, s3l};
        int Lss[4] = {1024, 512, 256, 128};
        for (int s = 0; s < 4; s++) {
            int Ms = Bb*Lss[s];
            gemm(xch, xcl, wqth + (long long)s*DDc, wqtl + (long long)s*DDc,
                 q, 0, 0, 0, Bb*Ll, Dd, Dd, 1, 0, Bb*Ll, 0, Dd, 0, 0);
            gemm(sh[s], sl[s], wkth + (long long)s*DDc, wktl + (long long)s*DDc,
                 k, 0, 0, 0, Ms, Dd, Dd, 1, 0, Ms, 0, Dd, 0, 0);
            gemm(sh[s], sl[s], wvth, wvtl,
                 v, 0, 0, 0, Ms, Dd, Dd, 1, 0, Ms, 0, Dd, 0, 0);
            dim3 ag(Ll/64, Hh, Bb);
            attn64<<<ag, 256>>>(q, k, v, ctx, gw, s, Lss[s], s == 0);
        }
    }

    // 4. split ctx, apply Wo
    split_act_kernel<<<4096, 256>>>(ctx, ctxh, ctxl, (long long)BLD);
    gemm(ctxh, ctxl, woth, wotl, tmp, 0, 0, 0, Bb*Ll, Dd, Dd, 1, 0, Bb*Ll, 0, Dd, 0, 0);

    // 5. residual + LN1 (emit fp32 + split)
    ln_kernel<<<Bb*Ll, 256>>>(x, tmp, g1, be1, x1, x1h, x1l);

    // 6. FFN (GELU fused, split intermediate)
    gemm(x1h, x1l, w1th, w1tl, 0, ffnh, ffnl, b1, Bb*Ll, Ff, Dd, 1, 0, Bb*Ll, 0, Dd, 0, 2);
    gemm(ffnh, ffnl, w2th, w2tl, tmp, 0, 0, b2, Bb*Ll, Dd, Ff, 1, 0, Bb*Ll, 0, Ff, 0, 0);

    // 7. residual + LN2 -> out
    ln_kernel<<<Bb*Ll, 256>>>(x1, tmp, g2, be2, out, (__nv_bfloat16*)0, (__nv_bfloat16*)0);
}

// round 4
// speedup vs baseline: 2.3154x; 1.2029x over previous
#include <cuda_runtime.h>
#include <cuda_bf16.h>
#include <math.h>
#include <stdint.h>

#define Bb 4
#define Ll 1024
#define Dd 1024
#define Hh 16
#define Ff 4096
#define Ss 4
#define DDc (1024LL*1024LL)

// ================= static scratch (no allocations) =================
__device__ __align__(256) __nv_bfloat16 g_xph[Bb*(Ll+4)*Dd], g_xpl[Bb*(Ll+4)*Dd];
__device__ __align__(256) __nv_bfloat16 g_xch[Bb*Ll*Dd],     g_xcl[Bb*Ll*Dd];
__device__ __align__(256) __nv_bfloat16 g_s1h[Bb*512*Dd],    g_s1l[Bb*512*Dd];
__device__ __align__(256) __nv_bfloat16 g_s2h[Bb*256*Dd],    g_s2l[Bb*256*Dd];
__device__ __align__(256) __nv_bfloat16 g_s3h[Bb*128*Dd],    g_s3l[Bb*128*Dd];
__device__ __align__(256) __nv_bfloat16 g_qh[Bb*Ll*Dd],      g_ql[Bb*Ll*Dd];
__device__ __align__(256) __nv_bfloat16 g_kh[Bb*Ll*Dd],      g_kl[Bb*Ll*Dd];
__device__ __align__(256) __nv_bfloat16 g_vh[Bb*Ll*Dd],      g_vl[Bb*Ll*Dd];
__device__ __align__(256) __nv_bfloat16 g_ctxh[Bb*Ll*Dd],    g_ctxl[Bb*Ll*Dd];
__device__ __align__(256) __nv_bfloat16 g_x1h[Bb*Ll*Dd],     g_x1l[Bb*Ll*Dd];
__device__ __align__(256) __nv_bfloat16 g_ffnh[Bb*Ll*Ff],    g_ffnl[Bb*Ll*Ff];
__device__ __align__(256) __nv_bfloat16 g_wdcth[3*1024*1024],  g_wdctl[3*1024*1024];
__device__ __align__(256) __nv_bfloat16 g_wdecth[6*1024*1024], g_wdectl[6*1024*1024];
__device__ __align__(256) __nv_bfloat16 g_wqth[4*1024*1024],   g_wqtl[4*1024*1024];
__device__ __align__(256) __nv_bfloat16 g_wkth[4*1024*1024],   g_wktl[4*1024*1024];
__device__ __align__(256) __nv_bfloat16 g_wvth[1024*1024],     g_wvtl[1024*1024];
__device__ __align__(256) __nv_bfloat16 g_woth[1024*1024],     g_wotl[1024*1024];
__device__ __align__(256) __nv_bfloat16 g_w1th[1024*4096],     g_w1tl[1024*4096];
__device__ __align__(256) __nv_bfloat16 g_w2th[4096*1024],     g_w2tl[4096*1024];
__device__ __align__(256) float g_ctx[Bb*Ll*Dd];
__device__ __align__(256) float g_x1[Bb*Ll*Dd];
__device__ __align__(256) float g_tmp[Bb*Ll*Dd];
__device__ float g_w[Ss];

// ================= PTX helpers (base features only) =================
#define CP16(dst, src)    asm volatile("cp.async.cg.shared.global [%0], [%1], 16;" :: "r"(dst), "l"(src) : "memory")
#define CP_COMMIT()       asm volatile("cp.async.commit_group;" ::: "memory")
#define CP_WAIT1()        asm volatile("cp.async.wait_group 1;" ::: "memory")
#define CP_WAIT0()        asm volatile("cp.async.wait_group 0;" ::: "memory")

#define LDSM4(r0,r1,r2,r3,addr) \
    asm volatile("ldmatrix.sync.aligned.m8n8.x4.shared.b16 {%0,%1,%2,%3}, [%4];" \
        : "=r"(r0),"=r"(r1),"=r"(r2),"=r"(r3) : "r"(addr))
#define LDSM4T(r0,r1,r2,r3,addr) \
    asm volatile("ldmatrix.sync.aligned.m8n8.x4.trans.shared.b16 {%0,%1,%2,%3}, [%4];" \
        : "=r"(r0),"=r"(r1),"=r"(r2),"=r"(r3) : "r"(addr))
#define LDSM2(r0,r1,addr) \
    asm volatile("ldmatrix.sync.aligned.m8n8.x2.shared.b16 {%0,%1}, [%2];" \
        : "=r"(r0),"=r"(r1) : "r"(addr))
#define MMA16816(d, a, b) \
    asm volatile("mma.sync.aligned.m16n8k16.row.col.f32.bf16.bf16.f32 " \
        "{%0,%1,%2,%3}, {%4,%5,%6,%7}, {%8,%9}, {%0,%1,%2,%3};" \
        : "+f"((d)[0]),"+f"((d)[1]),"+f"((d)[2]),"+f"((d)[3]) \
        : "r"((a)[0]),"r"((a)[1]),"r"((a)[2]),"r"((a)[3]), "r"((b)[0]),"r"((b)[1]))

__device__ __forceinline__ uint32_t smem_u32(const void* p) {
    uint32_t a;
    asm("{ .reg .u64 t; cvta.to.shared.u64 t, %1; cvt.u32.u64 %0, t; }" : "=r"(a) : "l"(p));
    return a;
}

__device__ __forceinline__ void split2(float x, __nv_bfloat16& h, __nv_bfloat16& l) {
    h = __float2bfloat16(x);
    l = __float2bfloat16(x - __bfloat162float(h));
}

__device__ __forceinline__ uint32_t packsplit(float a, float b, uint32_t& lo) {
    __nv_bfloat16 ha = __float2bfloat16(a), hb = __float2bfloat16(b);
    __nv_bfloat16 la = __float2bfloat16(a - __bfloat162float(ha));
    __nv_bfloat16 lb = __float2bfloat16(b - __bfloat162float(hb));
    lo = ((uint32_t)__bfloat16_as_ushort(lb) << 16) | __bfloat16_as_ushort(la);
    return ((uint32_t)__bfloat16_as_ushort(hb) << 16) | __bfloat16_as_ushort(ha);
}

// ================= mma.sync split-bf16 GEMM =================
__global__ __launch_bounds__(256, 1) void gemmM(
    const __nv_bfloat16* __restrict__ Ah, const __nv_bfloat16* __restrict__ Al,
    const __nv_bfloat16* __restrict__ Bh, const __nv_bfloat16* __restrict__ Bl,
    float* __restrict__ Cf, __nv_bfloat16* __restrict__ Oh, __nv_bfloat16* __restrict__ Ol,
    const float* __restrict__ bias,
    int N, int K, int taps, long long tapStrideA,
    int lseg, long long segStride, int rowStride, long long offA, int epi)
{
    extern __shared__ char smem[];
    uint32_t sb = smem_u32(smem);
    const int tid = threadIdx.x;
    const int wid = tid >> 5, lane = tid & 31;
    const int m0 = blockIdx.y * 128, n0 = blockIdx.x * 128;

    const int r = tid >> 1, half = tid & 1;
    const long long mrow = m0 + r;
    const long long aoff0 = (mrow / lseg) * segStride + (mrow % lseg) * (long long)rowStride + offA + half * 32;
    const long long boff0 = (long long)(n0 + r) * K + half * 32;
    uint32_t dstOff[4];
#pragma unroll
    for (int j = 0; j < 4; j++) {
        uint32_t off = (uint32_t)(r * 128 + half * 64 + j * 16);
        dstOff[j] = off ^ ((off >> 3) & 0x70);
    }
    const uint32_t bufBase[2] = { sb, sb + 65536 };
    const int NCk = K >> 6;
    const int NC = NCk * taps;
    const long long tapStrideB = (long long)N * K;

    const int wm = wid & 1, wn = wid >> 1;
    const int arow = wm * 64 + (lane & 15);
    const uint32_t aRowOff = (uint32_t)(arow * 128);
    const uint32_t aXb = (uint32_t)((arow & 7) << 4);
    const uint32_t aHalf = (uint32_t)((lane >> 4) * 16);
    const uint32_t bRowOff = (uint32_t)((wn * 32 + (lane & 7)) * 128);
    const uint32_t bXb = (uint32_t)((lane & 7) << 4);
    const uint32_t bHalf = (uint32_t)(((lane >> 3) & 1) * 16);

    float acc[4][4][4];
#pragma unroll
    for (int i = 0; i < 4; i++)
#pragma unroll
        for (int j = 0; j < 4; j++)
#pragma unroll
            for (int e = 0; e < 4; e++) acc[i][j][e] = 0.f;

#pragma unroll 1
    for (int c = 0; c < 2 && c < NC; c++) {
        int tap = c / NCk, kc = c % NCk;
        long long ao = aoff0 + (long long)tap * tapStrideA + kc * 64;
        long long bo = boff0 + (long long)tap * tapStrideB + kc * 64;
        uint32_t bs = bufBase[c & 1];
#pragma unroll
        for (int j = 0; j < 4; j++) {
            CP16(bs +         dstOff[j], Ah + ao + j * 8);
            CP16(bs + 16384 + dstOff[j], Al + ao + j * 8);
            CP16(bs + 32768 + dstOff[j], Bh + bo + j * 8);
            CP16(bs + 49152 + dstOff[j], Bl + bo + j * 8);
        }
        CP_COMMIT();
    }

#pragma unroll 1
    for (int c = 0; c < NC; c++) {
        const int buf = c & 1;
        if (c == NC - 1) CP_WAIT0(); else CP_WAIT1();
        __syncthreads();

        const uint32_t bs = bufBase[buf];
#pragma unroll
        for (int k16 = 0; k16 < 4; k16++) {
            const uint32_t aoff = aRowOff + ((k16 * 32 + aHalf) ^ aXb);
            const uint32_t boff = bRowOff + ((k16 * 32 + bHalf) ^ bXb);
            uint32_t ah[4][4], al_[4][4], bh[4][2], bl[4][2];
#pragma unroll
            for (int i = 0; i < 4; i++) {
                LDSM4(ah[i][0], ah[i][1], ah[i][2], ah[i][3], bs + i * 2048 + aoff);
                LDSM4(al_[i][0], al_[i][1], al_[i][2], al_[i][3], bs + 16384 + i * 2048 + aoff);
            }
#pragma unroll
            for (int j = 0; j < 4; j++) {
                LDSM2(bh[j][0], bh[j][1], bs + 32768 + j * 1024 + boff);
                LDSM2(bl[j][0], bl[j][1], bs + 49152 + j * 1024 + boff);
            }
#pragma unroll
            for (int i = 0; i < 4; i++)
#pragma unroll
                for (int j = 0; j < 4; j++) {
                    MMA16816(acc[i][j], ah[i],  bh[j]);
                    MMA16816(acc[i][j], al_[i], bh[j]);
                    MMA16816(acc[i][j], ah[i],  bl[j]);
                }
        }
        __syncthreads();

        if (c + 2 < NC) {
            int cc = c + 2;
            int tap = cc / NCk, kc = cc % NCk;
            long long ao = aoff0 + (long long)tap * tapStrideA + kc * 64;
            long long bo = boff0 + (long long)tap * tapStrideB + kc * 64;
#pragma unroll
            for (int j = 0; j < 4; j++) {
                CP16(bs +         dstOff[j], Ah + ao + j * 8);
                CP16(bs + 16384 + dstOff[j], Al + ao + j * 8);
                CP16(bs + 32768 + dstOff[j], Bh + bo + j * 8);
                CP16(bs + 49152 + dstOff[j], Bl + bo + j * 8);
            }
            CP_COMMIT();
        }
    }

#pragma unroll
    for (int i = 0; i < 4; i++)
#pragma unroll
        for (int j = 0; j < 4; j++)
#pragma unroll
            for (int p = 0; p < 2; p++) {
                int rr = m0 + wm * 64 + i * 16 + (lane >> 2) + p * 8;
                int cc = n0 + wn * 32 + j * 8 + (lane & 3) * 2;
                float v0 = acc[i][j][p * 2];
                float v1 = acc[i][j][p * 2 + 1];
                if (bias) { v0 += bias[cc]; v1 += bias[cc + 1]; }
                if (epi == 1) { v0 = fmaxf(v0, 0.f); v1 = fmaxf(v1, 0.f); }
                else if (epi == 2) {
                    v0 = 0.5f * v0 * (1.f + erff(v0 * 0.70710678118654752f));
                    v1 = 0.5f * v1 * (1.f + erff(v1 * 0.70710678118654752f));
                }
                long long idx = (long long)rr * N + cc;
                if (Cf) { float2 f; f.x = v0; f.y = v1; *(float2*)(Cf + idx) = f; }
                if (Oh) {
                    __nv_bfloat16 h0, l0, h1, l1;
                    split2(v0, h0, l0); split2(v1, h1, l1);
                    __nv_bfloat162 hh; hh.x = h0; hh.y = h1;
                    __nv_bfloat162 ll; ll.x = l0; ll.y = l1;
                    *(__nv_bfloat162*)(Oh + idx) = hh;
                    *(__nv_bfloat162*)(Ol + idx) = ll;
                }
            }
}

// ================= tensor-core flash attention (split bf16, FA2 style) =================
// 4 warps, 64-q tile per CTA, 64-key chunks, dh=64. ctx (first ? = : +=) w[s]*softmax(QK^T/8)@V
__global__ __launch_bounds__(128, 1) void attnT(
    const __nv_bfloat16* __restrict__ Qh, const __nv_bfloat16* __restrict__ Ql,
    const __nv_bfloat16* __restrict__ Kh, const __nv_bfloat16* __restrict__ Kl,
    const __nv_bfloat16* __restrict__ Vh, const __nv_bfloat16* __restrict__ Vl,
    float* __restrict__ ctx, const float* __restrict__ gw, int s, int Ls, int first)
{
    extern __shared__ char smem[];
    uint32_t sb = smem_u32(smem);
    const int tid = threadIdx.x;
    const int w = tid >> 5, lane = tid & 31;
    const int b = blockIdx.z, h = blockIdx.y;
    const int q0 = blockIdx.x * 64;

    // cp.async mapping: r = tid>>1 in [0,64), half = tid&1 (64B each)
    const int r = tid >> 1, half = tid & 1;
    uint32_t dstOff[4];
#pragma unroll
    for (int j = 0; j < 4; j++) {
        uint32_t off = (uint32_t)(r * 128 + half * 64 + j * 16);
        dstOff[j] = off ^ ((off >> 3) & 0x70);
    }
    const uint32_t sQh = sb, sQl = sb + 8192;
    const uint32_t bufBase[2] = { sb + 16384, sb + 16384 + 32768 };
    const int NCH = Ls >> 6;

    // prologue: Q + chunk0 as group 0; chunk1 as group 1
    {
        long long qr = ((long long)(b * Ll + q0 + r)) * Dd + h * 64 + half * 32;
#pragma unroll
        for (int j = 0; j < 4; j++) {
            CP16(sQh + dstOff[j], Qh + qr + j * 8);
            CP16(sQl + dstOff[j], Ql + qr + j * 8);
        }
        long long kr = ((long long)(b * Ls + r)) * Dd + h * 64 + half * 32;
        uint32_t bs = bufBase[0];
#pragma unroll
        for (int j = 0; j < 4; j++) {
            CP16(bs +         dstOff[j], Kh + kr + j * 8);
            CP16(bs + 8192  + dstOff[j], Kl + kr + j * 8);
            CP16(bs + 16384 + dstOff[j], Vh + kr + j * 8);
            CP16(bs + 24576 + dstOff[j], Vl + kr + j * 8);
        }
        CP_COMMIT();
        kr += 64LL * Dd;
        bs = bufBase[1];
#pragma unroll
        for (int j = 0; j < 4; j++) {
            CP16(bs +         dstOff[j], Kh + kr + j * 8);
            CP16(bs + 8192  + dstOff[j], Kl + kr + j * 8);
            CP16(bs + 16384 + dstOff[j], Vh + kr + j * 8);
            CP16(bs + 24576 + dstOff[j], Vl + kr + j * 8);
        }
        CP_COMMIT();
    }

    // per-lane fragment address components
    const uint32_t qoffBase = (uint32_t)((w * 16 + (lane & 15)) * 128 + ((lane >> 4) & 1) * 16);
    const uint32_t krowb = (uint32_t)((lane & 7) + ((lane >> 4) & 1) * 8);
    const uint32_t kbyteb = (uint32_t)(((lane >> 3) & 1) * 16);
    const uint32_t vrowb = (uint32_t)((lane & 7) + ((lane >> 3) & 1) * 8);
    const uint32_t vbyteb = (uint32_t)(((lane >> 4) & 1) * 16);

    uint32_t qah[4][4], qal[4][4];
    float o[8][4];
#pragma unroll
    for (int t = 0; t < 8; t++)
#pragma unroll
        for (int e = 0; e < 4; e++) o[t][e] = 0.f;
    float m0v = -1e30f, m1v = -1e30f, l0 = 0.f, l1 = 0.f;

#pragma unroll 1
    for (int c = 0; c < NCH; c++) {
        if (c == NCH - 1) CP_WAIT0(); else CP_WAIT1();
        __syncthreads();

        if (c == 0) {
#pragma unroll
            for (int k16 = 0; k16 < 4; k16++) {
                uint32_t off = qoffBase + k16 * 32;
                off ^= (off >> 3) & 0x70;
                LDSM4(qah[k16][0], qah[k16][1], qah[k16][2], qah[k16][3], sQh + off);
                LDSM4(qal[k16][0], qal[k16][1], qal[k16][2], qal[k16][3], sQl + off);
            }
        }

        const uint32_t bs = bufBase[c & 1];
        // ---- S = Q K^T ----
        float sc[8][4];
#pragma unroll
        for (int t = 0; t < 8; t++)
#pragma unroll
            for (int e = 0; e < 4; e++) sc[t][e] = 0.f;
#pragma unroll
        for (int k16 = 0; k16 < 4; k16++) {
            uint32_t kh[8][2], kl[8][2];
#pragma unroll
            for (int t4 = 0; t4 < 4; t4++) {
                uint32_t off = (t4 * 16 + krowb) * 128 + k16 * 32 + kbyteb;
                off ^= (off >> 3) & 0x70;
                LDSM4(kh[2*t4][0], kh[2*t4][1], kh[2*t4+1][0], kh[2*t4+1][1], bs + off);
                LDSM4(kl[2*t4][0], kl[2*t4][1], kl[2*t4+1][0], kl[2*t4+1][1], bs + 8192 + off);
            }
#pragma unroll
            for (int j = 0; j < 8; j++) {
                MMA16816(sc[j], qah[k16], kh[j]);
                MMA16816(sc[j], qal[k16], kh[j]);
                MMA16816(sc[j], qah[k16], kl[j]);
            }
        }

        // ---- online softmax (rows g=lane>>2 and g+8) ----
        float rmax0 = -1e30f, rmax1 = -1e30f;
#pragma unroll
        for (int t = 0; t < 8; t++) {
            sc[t][0] *= 0.125f; sc[t][1] *= 0.125f; sc[t][2] *= 0.125f; sc[t][3] *= 0.125f;
            rmax0 = fmaxf(rmax0, fmaxf(sc[t][0], sc[t][1]));
            rmax1 = fmaxf(rmax1, fmaxf(sc[t][2], sc[t][3]));
        }
        rmax0 = fmaxf(rmax0, __shfl_xor_sync(0xffffffffu, rmax0, 1));
        rmax0 = fmaxf(rmax0, __shfl_xor_sync(0xffffffffu, rmax0, 2));
        rmax1 = fmaxf(rmax1, __shfl_xor_sync(0xffffffffu, rmax1, 1));
        rmax1 = fmaxf(rmax1, __shfl_xor_sync(0xffffffffu, rmax1, 2));
        float mn0 = fmaxf(m0v, rmax0), mn1 = fmaxf(m1v, rmax1);
        float fac0 = __expf(m0v - mn0), fac1 = __expf(m1v - mn1);
        float rs0 = 0.f, rs1 = 0.f;
#pragma unroll
        for (int t = 0; t < 8; t++) {
            sc[t][0] = __expf(sc[t][0] - mn0); sc[t][1] = __expf(sc[t][1] - mn0);
            sc[t][2] = __expf(sc[t][2] - mn1); sc[t][3] = __expf(sc[t][3] - mn1);
            rs0 += sc[t][0] + sc[t][1];
            rs1 += sc[t][2] + sc[t][3];
        }
        rs0 += __shfl_xor_sync(0xffffffffu, rs0, 1);
        rs0 += __shfl_xor_sync(0xffffffffu, rs0, 2);
        rs1 += __shfl_xor_sync(0xffffffffu, rs1, 1);
        rs1 += __shfl_xor_sync(0xffffffffu, rs1, 2);
        l0 = l0 * fac0 + rs0; l1 = l1 * fac1 + rs1;
        m0v = mn0; m1v = mn1;
#pragma unroll
        for (int t = 0; t < 8; t++) {
            o[t][0] *= fac0; o[t][1] *= fac0; o[t][2] *= fac1; o[t][3] *= fac1;
        }

        // ---- O += P V ----
#pragma unroll
        for (int k16 = 0; k16 < 4; k16++) {
            uint32_t ph[4], pl[4];
            int t = 2 * k16;
            ph[0] = packsplit(sc[t][0],   sc[t][1],   pl[0]);
            ph[1] = packsplit(sc[t][2],   sc[t][3],   pl[1]);
            ph[2] = packsplit(sc[t+1][0], sc[t+1][1], pl[2]);
            ph[3] = packsplit(sc[t+1][2], sc[t+1][3], pl[3]);
            uint32_t vh[8][2], vl[8][2];
#pragma unroll
            for (int t4 = 0; t4 < 4; t4++) {
                uint32_t off = (k16 * 16 + vrowb) * 128 + t4 * 32 + vbyteb;
                off ^= (off >> 3) & 0x70;
                LDSM4T(vh[2*t4][0], vh[2*t4][1], vh[2*t4+1][0], vh[2*t4+1][1], bs + 16384 + off);
                LDSM4T(vl[2*t4][0], vl[2*t4][1], vl[2*t4+1][0], vl[2*t4+1][1], bs + 24576 + off);
            }
#pragma unroll
            for (int t8 = 0; t8 < 8; t8++) {
                MMA16816(o[t8], ph, vh[t8]);
                MMA16816(o[t8], pl, vh[t8]);
                MMA16816(o[t8], ph, vl[t8]);
            }
        }
        __syncthreads();

        if (c + 2 < NCH) {
            long long kr = ((long long)(b * Ls + (c + 2) * 64 + r)) * Dd + h * 64 + half * 32;
            uint32_t bs2 = bufBase[c & 1];
#pragma unroll
            for (int j = 0; j < 4; j++) {
                CP16(bs2 +         dstOff[j], Kh + kr + j * 8);
                CP16(bs2 + 8192  + dstOff[j], Kl + kr + j * 8);
                CP16(bs2 + 16384 + dstOff[j], Vh + kr + j * 8);
                CP16(bs2 + 24576 + dstOff[j], Vl + kr + j * 8);
            }
            CP_COMMIT();
        }
    }

    // ---- write out ----
    float ws = gw[s];
    float inv0 = ws / l0, inv1 = ws / l1;
    int g = lane >> 2;
    int qrow0 = q0 + w * 16 + g;
    long long base0 = ((long long)(b * Ll + qrow0)) * Dd + h * 64;
    long long base1 = base0 + 8LL * Dd;
#pragma unroll
    for (int t = 0; t < 8; t++) {
        int d0 = t * 8 + (lane & 3) * 2;
        float2 v0, v1;
        v0.x = o[t][0] * inv0; v0.y = o[t][1] * inv0;
        v1.x = o[t][2] * inv1; v1.y = o[t][3] * inv1;
        if (first) {
            *(float2*)(ctx + base0 + d0) = v0;
            *(float2*)(ctx + base1 + d0) = v1;
        } else {
            float2 a0 = *(float2*)(ctx + base0 + d0);
            float2 a1 = *(float2*)(ctx + base1 + d0);
            a0.x += v0.x; a0.y += v0.y; a1.x += v1.x; a1.y += v1.y;
            *(float2*)(ctx + base0 + d0) = a0;
            *(float2*)(ctx + base1 + d0) = a1;
        }
    }
}

// ================= LayerNorm: out = LN(a + r), optional split bf16 =================
__global__ __launch_bounds__(256) void ln_kernel(
    const float* __restrict__ a, const float* __restrict__ rr,
    const float* __restrict__ gamma, const float* __restrict__ beta,
    float* __restrict__ out, __nv_bfloat16* __restrict__ oh, __nv_bfloat16* __restrict__ ol)
{
    __shared__ float red[8], red2[8];
    __shared__ float smu, sinv;
    int row = blockIdx.x, tid = threadIdx.x;
    long long base = (long long)row * Dd;
    float4 va = ((const float4*)(a + base))[tid];
    float4 vr = ((const float4*)(rr + base))[tid];
    float x0 = va.x+vr.x, x1 = va.y+vr.y, x2 = va.z+vr.z, x3 = va.w+vr.w;
    float s  = x0+x1+x2+x3;
    float s2 = x0*x0 + x1*x1 + x2*x2 + x3*x3;
#pragma unroll
    for (int off = 16; off >= 1; off >>= 1) {
        s  += __shfl_xor_sync(0xffffffffu, s,  off);
        s2 += __shfl_xor_sync(0xffffffffu, s2, off);
    }
    int w = tid >> 5, lane = tid & 31;
    if (lane == 0) { red[w] = s; red2[w] = s2; }
    __syncthreads();
    if (tid == 0) {
        float S = 0.f, S2 = 0.f;
        for (int i = 0; i < 8; i++) { S += red[i]; S2 += red2[i]; }
        float mu = S * (1.f/Dd);
        smu = mu;
        sinv = rsqrtf(S2 * (1.f/Dd) - mu*mu + 1e-5f);
    }
    __syncthreads();
    float mu = smu, inv = sinv;
    float4 gg = ((const float4*)gamma)[tid];
    float4 bb = ((const float4*)beta)[tid];
    float y0 = (x0-mu)*inv*gg.x + bb.x;
    float y1 = (x1-mu)*inv*gg.y + bb.y;
    float y2 = (x2-mu)*inv*gg.z + bb.z;
    float y3 = (x3-mu)*inv*gg.w + bb.w;
    float4 y; y.x=y0; y.y=y1; y.z=y2; y.w=y3;
    ((float4*)(out + base))[tid] = y;
    if (oh) {
        __nv_bfloat16 h0,l0,h1,l1,h2,l2,h3,l3;
        split2(y0,h0,l0); split2(y1,h1,l1); split2(y2,h2,l2); split2(y3,h3,l3);
        __nv_bfloat162 a01; a01.x=h0; a01.y=h1;
        __nv_bfloat162 a23; a23.x=h2; a23.y=h3;
        __nv_bfloat162 b01; b01.x=l0; b01.y=l1;
        __nv_bfloat162 b23; b23.x=l2; b23.y=l3;
        ((__nv_bfloat162*)(oh + base))[tid*2]   = a01;
        ((__nv_bfloat162*)(oh + base))[tid*2+1] = a23;
        ((__nv_bfloat162*)(ol + base))[tid*2]   = b01;
        ((__nv_bfloat162*)(ol + base))[tid*2+1] = b23;
    }
}

// ================= preprocessing kernels =================
__global__ void pad_split_kernel(const float* __restrict__ x)
{
    const long long total = (long long)Bb*(Ll+4)*Dd;
    for (long long i = blockIdx.x*256LL + threadIdx.x; i < total; i += (long long)gridDim.x*256LL) {
        int d = (int)(i % Dd);
        long long t = i / Dd;
        int p = (int)(t % (Ll+4));
        int b = (int)(t / (Ll+4));
        float v = 0.f;
        if (p >= 2 && p < Ll+2)
            v = x[((long long)b*Ll + (p-2))*Dd + d];
        __nv_bfloat16 h, l; split2(v, h, l);
        g_xph[i] = h; g_xpl[i] = l;
    }
}

__global__ void split_act_kernel(const float* __restrict__ in,
                                 __nv_bfloat16* __restrict__ oh, __nv_bfloat16* __restrict__ ol,
                                 long long n)
{
    for (long long i = blockIdx.x*256LL + threadIdx.x; i < n; i += (long long)gridDim.x*256LL) {
        __nv_bfloat16 h, l; split2(in[i], h, l);
        oh[i] = h; ol[i] = l;
    }
}

__global__ void tdc_split(const float* __restrict__ W)
{
    const long long total = 3LL*Dd*Dd;
    for (long long idx = blockIdx.x*256LL + threadIdx.x; idx < total; idx += (long long)gridDim.x*256LL) {
        int tap = (int)(idx / (Dd*(long long)Dd));
        long long rem = idx % (Dd*(long long)Dd);
        int o = (int)(rem / Dd), i = (int)(rem % Dd);
        float v = W[((long long)o*Dd + i)*3 + tap];
        __nv_bfloat16 h, l; split2(v, h, l);
        g_wdcth[idx] = h; g_wdctl[idx] = l;
    }
}

__global__ void tdec_split(const float* __restrict__ W)
{
    const long long total = 6LL*Dd*Dd;
    for (long long idx = blockIdx.x*256LL + threadIdx.x; idx < total; idx += (long long)gridDim.x*256LL) {
        int st = (int)(idx / (Dd*(long long)Dd));
        int s = st >> 1, tap = st & 1;
        long long rem = idx % (Dd*(long long)Dd);
        int o = (int)(rem / Dd), i = (int)(rem % Dd);
        float v = W[(((long long)s*Dd + o)*Dd + i)*2 + tap];
        __nv_bfloat16 h, l; split2(v, h, l);
        g_wdecth[idx] = h; g_wdectl[idx] = l;
    }
}

__global__ void transpose_split(const float* __restrict__ W,
                                __nv_bfloat16* __restrict__ oh, __nv_bfloat16* __restrict__ ol,
                                int K, int N)
{
    __shared__ float t[32][33];
    int bx = blockIdx.x * 32;
    int by = blockIdx.y * 32;
    long long bz = blockIdx.z;
    const float* Wb = W + bz * (long long)K * N;
    int tx = threadIdx.x, ty = threadIdx.y;
    for (int i = ty; i < 32; i += 8)
        t[i][tx] = Wb[(long long)(by + i) * N + bx + tx];
    __syncthreads();
    long long ob = bz * (long long)N * K;
    for (int i = ty; i < 32; i += 8) {
        float v = t[tx][i];
        __nv_bfloat16 h, l; split2(v, h, l);
        long long oidx = ob + (long long)(bx + i) * K + by + tx;
        oh[oidx] = h; ol[oidx] = l;
    }
}

__global__ void agg_kernel(const float* __restrict__ logits, float* __restrict__ aux)
{
    float mx = -1e30f;
    for (int s = 0; s < Ss; s++) mx = fmaxf(mx, logits[s]);
    float e[Ss], sum = 0.f;
    for (int s = 0; s < Ss; s++) { e[s] = expf(logits[s] - mx); sum += e[s]; }
    float ent = 0.f;
    for (int s = 0; s < Ss; s++) {
        float w = e[s] / sum;
        g_w[s] = w;
        ent -= w * logf(w + 1e-9f);
    }
    if (aux) *aux = ent;
}

__global__ void fill0_kernel(float* p, long long n)
{
    for (long long i = blockIdx.x*256LL + threadIdx.x; i < n; i += (long long)gridDim.x*256LL)
        p[i] = 0.f;
}

// ================= launch =================
extern "C" void kernel_launch(void* const* d_in, const int* in_sizes, int n_in,
                              void* d_out, int out_size)
{
    const float* x     = (const float*)d_in[0];
    const float* W_dc  = (const float*)d_in[1];
    const float* b_dc  = (const float*)d_in[2];
    const float* W_dec = (const float*)d_in[3];
    const float* Wq    = (const float*)d_in[4];
    const float* Wk    = (const float*)d_in[5];
    const float* Wv    = (const float*)d_in[6];
    const float* Wo    = (const float*)d_in[7];
    const float* aggl  = (const float*)d_in[8];
    const float* g1    = (const float*)d_in[9];
    const float* be1   = (const float*)d_in[10];
    const float* g2    = (const float*)d_in[11];
    const float* be2   = (const float*)d_in[12];
    const float* W1    = (const float*)d_in[13];
    const float* b1    = (const float*)d_in[14];
    const float* W2    = (const float*)d_in[15];
    const float* b2    = (const float*)d_in[16];
    float* out = (float*)d_out;

    static int smem_set = 0;
    const int GEMM_SMEM = 2 * 65536;
    const int ATTN_SMEM = 16384 + 2 * 32768;
    if (!smem_set) {
        cudaFuncSetAttribute(gemmM, cudaFuncAttributeMaxDynamicSharedMemorySize, GEMM_SMEM);
        cudaFuncSetAttribute(attnT, cudaFuncAttributeMaxDynamicSharedMemorySize, ATTN_SMEM);
        smem_set = 1;
    }

#define SYM(v, s) cudaGetSymbolAddress((void**)&v, s)
    __nv_bfloat16 *xph,*xpl,*xch,*xcl,*s1h,*s1l,*s2h,*s2l,*s3h,*s3l,*ctxh,*ctxl,*x1h,*x1l,*ffnh,*ffnl;
    __nv_bfloat16 *qh,*ql,*kh,*kl,*vh,*vl;
    __nv_bfloat16 *wdcth,*wdctl,*wdecth,*wdectl,*wqth,*wqtl,*wkth,*wktl,*wvth,*wvtl,*woth,*wotl,*w1th,*w1tl,*w2th,*w2tl;
    float *ctx,*x1,*tmp,*gw;
    SYM(xph,g_xph); SYM(xpl,g_xpl); SYM(xch,g_xch); SYM(xcl,g_xcl);
    SYM(s1h,g_s1h); SYM(s1l,g_s1l); SYM(s2h,g_s2h); SYM(s2l,g_s2l); SYM(s3h,g_s3h); SYM(s3l,g_s3l);
    SYM(qh,g_qh); SYM(ql,g_ql); SYM(kh,g_kh); SYM(kl,g_kl); SYM(vh,g_vh); SYM(vl,g_vl);
    SYM(ctxh,g_ctxh); SYM(ctxl,g_ctxl); SYM(x1h,g_x1h); SYM(x1l,g_x1l); SYM(ffnh,g_ffnh); SYM(ffnl,g_ffnl);
    SYM(wdcth,g_wdcth); SYM(wdctl,g_wdctl); SYM(wdecth,g_wdecth); SYM(wdectl,g_wdectl);
    SYM(wqth,g_wqth); SYM(wqtl,g_wqtl); SYM(wkth,g_wkth); SYM(wktl,g_wktl);
    SYM(wvth,g_wvth); SYM(wvtl,g_wvtl); SYM(woth,g_woth); SYM(wotl,g_wotl);
    SYM(w1th,g_w1th); SYM(w1tl,g_w1tl); SYM(w2th,g_w2th); SYM(w2tl,g_w2tl);
    SYM(ctx,g_ctx); SYM(x1,g_x1); SYM(tmp,g_tmp); SYM(gw,g_w);
#undef SYM

    const int BLD = Bb*Ll*Dd;

    // ---- preprocessing ----
    tdc_split <<<1024, 256>>>(W_dc);
    tdec_split<<<2048, 256>>>(W_dec);
    {
        dim3 blk(32, 8);
        transpose_split<<<dim3(Dd/32, Dd/32, 4), blk>>>(Wq, wqth, wqtl, Dd, Dd);
        transpose_split<<<dim3(Dd/32, Dd/32, 4), blk>>>(Wk, wkth, wktl, Dd, Dd);
        transpose_split<<<dim3(Dd/32, Dd/32, 1), blk>>>(Wv, wvth, wvtl, Dd, Dd);
        transpose_split<<<dim3(Dd/32, Dd/32, 1), blk>>>(Wo, woth, wotl, Dd, Dd);
        transpose_split<<<dim3(Ff/32, Dd/32, 1), blk>>>(W1, w1th, w1tl, Dd, Ff);
        transpose_split<<<dim3(Dd/32, Ff/32, 1), blk>>>(W2, w2th, w2tl, Ff, Dd);
    }
    pad_split_kernel<<<4096, 256>>>(x);
    if (out_size > BLD) {
        long long gap = (long long)out_size - BLD;
        fill0_kernel<<<256, 256>>>(out + BLD, gap);
        agg_kernel<<<1, 1>>>(aggl, out + out_size - 1);
    } else {
        agg_kernel<<<1, 1>>>(aggl, (float*)0);
    }

    auto gemm = [&](const __nv_bfloat16* Ah, const __nv_bfloat16* Al,
                    const __nv_bfloat16* Bh, const __nv_bfloat16* Bl,
                    float* Cf, __nv_bfloat16* Oh, __nv_bfloat16* Ol, const float* bias,
                    int M, int N, int K, int taps, long long tapStrideA,
                    int lseg, long long segStride, int rowStride, long long offA, int epi) {
        dim3 g(N/128, M/128);
        gemmM<<<g, 256, GEMM_SMEM>>>(Ah, Al, Bh, Bl, Cf, Oh, Ol, bias,
                                     N, K, taps, tapStrideA, lseg, segStride, rowStride, offA, epi);
    };

    // 1. dilated conv (k=3, dil=2) + bias + ReLU -> xc split
    gemm(xph, xpl, wdcth, wdctl, 0, xch, xcl, b_dc,
         Bb*Ll, Dd, Dd, 3, 2LL*Dd, Ll, (long long)(Ll+4)*Dd, Dd, 0, 1);

    // 2. hierarchical decomposition (stride-2, k=2)
    {
        const __nv_bfloat16* ih[3] = {xch, s1h, s2h};
        const __nv_bfloat16* il[3] = {xcl, s1l, s2l};
        __nv_bfloat16* oh[3] = {s1h, s2h, s3h};
        __nv_bfloat16* ol[3] = {s1l, s2l, s3l};
        int Lin[3] = {1024, 512, 256};
        for (int s = 0; s < 3; s++)
            gemm(ih[s], il[s], wdecth + (long long)s*2*DDc, wdectl + (long long)s*2*DDc,
                 0, oh[s], ol[s], 0,
                 Bb*(Lin[s]/2), Dd, Dd, 2, (long long)Dd,
                 Lin[s]/2, (long long)Lin[s]*Dd, 2*Dd, 0, 0);
    }

    // 3. multiscale attention -> ctx (weighted accumulation, pre-Wo)
    {
        const __nv_bfloat16* sh[4] = {xch, s1h, s2h, s3h};
        const __nv_bfloat16* sl[4] = {xcl, s1l, s2l, s3l};
        int Lss[4] = {1024, 512, 256, 128};
        for (int s = 0; s < 4; s++) {
            int Ms = Bb*Lss[s];
            gemm(xch, xcl, wqth + (long long)s*DDc, wqtl + (long long)s*DDc,
                 0, qh, ql, 0, Bb*Ll, Dd, Dd, 1, 0, Bb*Ll, 0, Dd, 0, 0);
            gemm(sh[s], sl[s], wkth + (long long)s*DDc, wktl + (long long)s*DDc,
                 0, kh, kl, 0, Ms, Dd, Dd, 1, 0, Ms, 0, Dd, 0, 0);
            gemm(sh[s], sl[s], wvth, wvtl,
                 0, vh, vl, 0, Ms, Dd, Dd, 1, 0, Ms, 0, Dd, 0, 0);
            dim3 ag(Ll/64, Hh, Bb);
            attnT<<<ag, 128, ATTN_SMEM>>>(qh, ql, kh, kl, vh, vl, ctx, gw, s, Lss[s], s == 0);
        }
    }

    // 4. split ctx, apply Wo
    split_act_kernel<<<4096, 256>>>(ctx, ctxh, ctxl, (long long)BLD);
    gemm(ctxh, ctxl, woth, wotl, tmp, 0, 0, 0, Bb*Ll, Dd, Dd, 1, 0, Bb*Ll, 0, Dd, 0, 0);

    // 5. residual + LN1 (emit fp32 + split)
    ln_kernel<<<Bb*Ll, 256>>>(x, tmp, g1, be1, x1, x1h, x1l);

    // 6. FFN (GELU fused, split intermediate)
    gemm(x1h, x1l, w1th, w1tl, 0, ffnh, ffnl, b1, Bb*Ll, Ff, Dd, 1, 0, Bb*Ll, 0, Dd, 0, 2);
    gemm(ffnh, ffnl, w2th, w2tl, tmp, 0, 0, b2, Bb*Ll, Dd, Ff, 1, 0, Bb*Ll, 0, Ff, 0, 0);

    // 7. residual + LN2 -> out
    ln_kernel<<<Bb*Ll, 256>>>(x1, tmp, g2, be2, out, (__nv_bfloat16*)0, (__nv_bfloat16*)0);
}

// round 5
// speedup vs baseline: 2.5271x; 1.0915x over previous
#include <cuda_runtime.h>
#include <cuda_bf16.h>
#include <math.h>
#include <stdint.h>

#define Bb 4
#define Ll 1024
#define Dd 1024
#define Hh 16
#define Ff 4096
#define Ss 4
#define DDc (1024LL*1024LL)
#define SAR 7680   // total scale-activation rows: 4096+2048+1024+512

// ================= static scratch (no allocations) =================
__device__ __align__(256) __nv_bfloat16 g_xph[Bb*(Ll+4)*Dd], g_xpl[Bb*(Ll+4)*Dd];
__device__ __align__(256) __nv_bfloat16 g_sah[SAR*Dd],       g_sal[SAR*Dd];       // xc|s1|s2|s3
__device__ __align__(256) __nv_bfloat16 g_q4h[Bb*Ll*4*Dd],   g_q4l[Bb*Ll*4*Dd];   // [4096][4096]
__device__ __align__(256) __nv_bfloat16 g_kvh[SAR*2048],     g_kvl[SAR*2048];     // [7680][2048] K|V
__device__ __align__(256) __nv_bfloat16 g_ctxh[Bb*Ll*Dd],    g_ctxl[Bb*Ll*Dd];
__device__ __align__(256) __nv_bfloat16 g_x1h[Bb*Ll*Dd],     g_x1l[Bb*Ll*Dd];
__device__ __align__(256) __nv_bfloat16 g_ffnh[Bb*Ll*Ff],    g_ffnl[Bb*Ll*Ff];
__device__ __align__(256) __nv_bfloat16 g_wdcth[3*1024*1024],  g_wdctl[3*1024*1024];
__device__ __align__(256) __nv_bfloat16 g_wdecth[6*1024*1024], g_wdectl[6*1024*1024];
__device__ __align__(256) __nv_bfloat16 g_wqth[4*1024*1024],   g_wqtl[4*1024*1024];
__device__ __align__(256) __nv_bfloat16 g_wkvth[4*2048*1024],  g_wkvtl[4*2048*1024];
__device__ __align__(256) __nv_bfloat16 g_woth[1024*1024],     g_wotl[1024*1024];
__device__ __align__(256) __nv_bfloat16 g_w1th[1024*4096],     g_w1tl[1024*4096];
__device__ __align__(256) __nv_bfloat16 g_w2th[4096*1024],     g_w2tl[4096*1024];
__device__ __align__(256) float g_x1[Bb*Ll*Dd];
__device__ __align__(256) float g_tmp[Bb*Ll*Dd];
__device__ float g_w[Ss];

// ================= PTX helpers (base features only) =================
#define CP16(dst, src)    asm volatile("cp.async.cg.shared.global [%0], [%1], 16;" :: "r"(dst), "l"(src) : "memory")
#define CP_COMMIT()       asm volatile("cp.async.commit_group;" ::: "memory")
#define CP_WAIT1()        asm volatile("cp.async.wait_group 1;" ::: "memory")
#define CP_WAIT0()        asm volatile("cp.async.wait_group 0;" ::: "memory")

#define LDSM4(r0,r1,r2,r3,addr) \
    asm volatile("ldmatrix.sync.aligned.m8n8.x4.shared.b16 {%0,%1,%2,%3}, [%4];" \
        : "=r"(r0),"=r"(r1),"=r"(r2),"=r"(r3) : "r"(addr))
#define LDSM4T(r0,r1,r2,r3,addr) \
    asm volatile("ldmatrix.sync.aligned.m8n8.x4.trans.shared.b16 {%0,%1,%2,%3}, [%4];" \
        : "=r"(r0),"=r"(r1),"=r"(r2),"=r"(r3) : "r"(addr))
#define LDSM2(r0,r1,addr) \
    asm volatile("ldmatrix.sync.aligned.m8n8.x2.shared.b16 {%0,%1}, [%2];" \
        : "=r"(r0),"=r"(r1) : "r"(addr))
#define MMA16816(d, a, b) \
    asm volatile("mma.sync.aligned.m16n8k16.row.col.f32.bf16.bf16.f32 " \
        "{%0,%1,%2,%3}, {%4,%5,%6,%7}, {%8,%9}, {%0,%1,%2,%3};" \
        : "+f"((d)[0]),"+f"((d)[1]),"+f"((d)[2]),"+f"((d)[3]) \
        : "r"((a)[0]),"r"((a)[1]),"r"((a)[2]),"r"((a)[3]), "r"((b)[0]),"r"((b)[1]))

__device__ __forceinline__ uint32_t smem_u32(const void* p) {
    uint32_t a;
    asm("{ .reg .u64 t; cvta.to.shared.u64 t, %1; cvt.u32.u64 %0, t; }" : "=r"(a) : "l"(p));
    return a;
}

__device__ __forceinline__ void split2(float x, __nv_bfloat16& h, __nv_bfloat16& l) {
    h = __float2bfloat16(x);
    l = __float2bfloat16(x - __bfloat162float(h));
}

__device__ __forceinline__ uint32_t packsplit(float a, float b, uint32_t& lo) {
    __nv_bfloat16 ha = __float2bfloat16(a), hb = __float2bfloat16(b);
    __nv_bfloat16 la = __float2bfloat16(a - __bfloat162float(ha));
    __nv_bfloat16 lb = __float2bfloat16(b - __bfloat162float(hb));
    lo = ((uint32_t)__bfloat16_as_ushort(lb) << 16) | __bfloat16_as_ushort(la);
    return ((uint32_t)__bfloat16_as_ushort(hb) << 16) | __bfloat16_as_ushort(ha);
}

// ================= mma.sync split-bf16 GEMM (seg-selectable B) =================
__global__ __launch_bounds__(256, 1) void gemmM(
    const __nv_bfloat16* __restrict__ Ah, const __nv_bfloat16* __restrict__ Al,
    const __nv_bfloat16* __restrict__ Bh, const __nv_bfloat16* __restrict__ Bl,
    float* __restrict__ Cf, __nv_bfloat16* __restrict__ Oh, __nv_bfloat16* __restrict__ Ol,
    const float* __restrict__ bias,
    int N, int K, int taps, long long tapStrideA,
    int lseg, long long segStride, int rowStride, long long offA, int epi,
    int4 segEnd, long long segUnit)
{
    extern __shared__ char smem[];
    uint32_t sb = smem_u32(smem);
    const int tid = threadIdx.x;
    const int wid = tid >> 5, lane = tid & 31;
    const int m0 = blockIdx.y * 128, n0 = blockIdx.x * 128;

    // B segment select (for merged KV projection); no-op when segUnit==0
    {
        int sidx = (m0 >= segEnd.x) + (m0 >= segEnd.y) + (m0 >= segEnd.z);
        Bh += (long long)sidx * segUnit;
        Bl += (long long)sidx * segUnit;
    }

    const int r = tid >> 1, half = tid & 1;
    const long long mrow = m0 + r;
    const long long aoff0 = (mrow / lseg) * segStride + (mrow % lseg) * (long long)rowStride + offA + half * 32;
    const long long boff0 = (long long)(n0 + r) * K + half * 32;
    uint32_t dstOff[4];
#pragma unroll
    for (int j = 0; j < 4; j++) {
        uint32_t off = (uint32_t)(r * 128 + half * 64 + j * 16);
        dstOff[j] = off ^ ((off >> 3) & 0x70);
    }
    const uint32_t bufBase[2] = { sb, sb + 65536 };
    const int NCk = K >> 6;
    const int NC = NCk * taps;
    const long long tapStrideB = (long long)N * K;

    const int wm = wid & 1, wn = wid >> 1;
    const int arow = wm * 64 + (lane & 15);
    const uint32_t aRowOff = (uint32_t)(arow * 128);
    const uint32_t aXb = (uint32_t)((arow & 7) << 4);
    const uint32_t aHalf = (uint32_t)((lane >> 4) * 16);
    const uint32_t bRowOff = (uint32_t)((wn * 32 + (lane & 7)) * 128);
    const uint32_t bXb = (uint32_t)((lane & 7) << 4);
    const uint32_t bHalf = (uint32_t)(((lane >> 3) & 1) * 16);

    float acc[4][4][4];
#pragma unroll
    for (int i = 0; i < 4; i++)
#pragma unroll
        for (int j = 0; j < 4; j++)
#pragma unroll
            for (int e = 0; e < 4; e++) acc[i][j][e] = 0.f;

#pragma unroll 1
    for (int c = 0; c < 2 && c < NC; c++) {
        int tap = c / NCk, kc = c % NCk;
        long long ao = aoff0 + (long long)tap * tapStrideA + kc * 64;
        long long bo = boff0 + (long long)tap * tapStrideB + kc * 64;
        uint32_t bs = bufBase[c & 1];
#pragma unroll
        for (int j = 0; j < 4; j++) {
            CP16(bs +         dstOff[j], Ah + ao + j * 8);
            CP16(bs + 16384 + dstOff[j], Al + ao + j * 8);
            CP16(bs + 32768 + dstOff[j], Bh + bo + j * 8);
            CP16(bs + 49152 + dstOff[j], Bl + bo + j * 8);
        }
        CP_COMMIT();
    }

#pragma unroll 1
    for (int c = 0; c < NC; c++) {
        const int buf = c & 1;
        if (c == NC - 1) CP_WAIT0(); else CP_WAIT1();
        __syncthreads();

        const uint32_t bs = bufBase[buf];
#pragma unroll
        for (int k16 = 0; k16 < 4; k16++) {
            const uint32_t aoff = aRowOff + ((k16 * 32 + aHalf) ^ aXb);
            const uint32_t boff = bRowOff + ((k16 * 32 + bHalf) ^ bXb);
            uint32_t ah[4][4], al_[4][4], bh[4][2], bl[4][2];
#pragma unroll
            for (int i = 0; i < 4; i++) {
                LDSM4(ah[i][0], ah[i][1], ah[i][2], ah[i][3], bs + i * 2048 + aoff);
                LDSM4(al_[i][0], al_[i][1], al_[i][2], al_[i][3], bs + 16384 + i * 2048 + aoff);
            }
#pragma unroll
            for (int j = 0; j < 4; j++) {
                LDSM2(bh[j][0], bh[j][1], bs + 32768 + j * 1024 + boff);
                LDSM2(bl[j][0], bl[j][1], bs + 49152 + j * 1024 + boff);
            }
#pragma unroll
            for (int i = 0; i < 4; i++)
#pragma unroll
                for (int j = 0; j < 4; j++) {
                    MMA16816(acc[i][j], ah[i],  bh[j]);
                    MMA16816(acc[i][j], al_[i], bh[j]);
                    MMA16816(acc[i][j], ah[i],  bl[j]);
                }
        }
        __syncthreads();

        if (c + 2 < NC) {
            int cc = c + 2;
            int tap = cc / NCk, kc = cc % NCk;
            long long ao = aoff0 + (long long)tap * tapStrideA + kc * 64;
            long long bo = boff0 + (long long)tap * tapStrideB + kc * 64;
#pragma unroll
            for (int j = 0; j < 4; j++) {
                CP16(bs +         dstOff[j], Ah + ao + j * 8);
                CP16(bs + 16384 + dstOff[j], Al + ao + j * 8);
                CP16(bs + 32768 + dstOff[j], Bh + bo + j * 8);
                CP16(bs + 49152 + dstOff[j], Bl + bo + j * 8);
            }
            CP_COMMIT();
        }
    }

#pragma unroll
    for (int i = 0; i < 4; i++)
#pragma unroll
        for (int j = 0; j < 4; j++)
#pragma unroll
            for (int p = 0; p < 2; p++) {
                int rr = m0 + wm * 64 + i * 16 + (lane >> 2) + p * 8;
                int cc = n0 + wn * 32 + j * 8 + (lane & 3) * 2;
                float v0 = acc[i][j][p * 2];
                float v1 = acc[i][j][p * 2 + 1];
                if (bias) { v0 += bias[cc]; v1 += bias[cc + 1]; }
                if (epi == 1) { v0 = fmaxf(v0, 0.f); v1 = fmaxf(v1, 0.f); }
                else if (epi == 2) {
                    v0 = 0.5f * v0 * (1.f + erff(v0 * 0.70710678118654752f));
                    v1 = 0.5f * v1 * (1.f + erff(v1 * 0.70710678118654752f));
                }
                long long idx = (long long)rr * N + cc;
                if (Cf) { float2 f; f.x = v0; f.y = v1; *(float2*)(Cf + idx) = f; }
                if (Oh) {
                    __nv_bfloat16 h0, l0, h1, l1;
                    split2(v0, h0, l0); split2(v1, h1, l1);
                    __nv_bfloat162 hh; hh.x = h0; hh.y = h1;
                    __nv_bfloat162 ll; ll.x = l0; ll.y = l1;
                    *(__nv_bfloat162*)(Oh + idx) = hh;
                    *(__nv_bfloat162*)(Ol + idx) = ll;
                }
            }
}

// ================= fused 4-scale tensor-core flash attention =================
// Q from q4 [4096][4096] (scale s at col s*1024), KV from [7680][2048] (K col 0, V col 1024).
// Writes weighted sum over scales directly as split bf16 into ctxh/ctxl [B*L][1024].
__global__ __launch_bounds__(128, 2) void attnF(
    const __nv_bfloat16* __restrict__ Qh4, const __nv_bfloat16* __restrict__ Ql4,
    const __nv_bfloat16* __restrict__ KVh, const __nv_bfloat16* __restrict__ KVl,
    __nv_bfloat16* __restrict__ Oh, __nv_bfloat16* __restrict__ Ol,
    const float* __restrict__ gw)
{
    extern __shared__ char smem[];
    uint32_t sb = smem_u32(smem);
    const int tid = threadIdx.x;
    const int w = tid >> 5, lane = tid & 31;
    const int b = blockIdx.z, h = blockIdx.y;
    const int q0 = blockIdx.x * 64;

    float w4[4];
#pragma unroll
    for (int s = 0; s < 4; s++) w4[s] = gw[s];

    const int r = tid >> 1, half = tid & 1;
    uint32_t dstOff[4];
#pragma unroll
    for (int j = 0; j < 4; j++) {
        uint32_t off = (uint32_t)(r * 128 + half * 64 + j * 16);
        dstOff[j] = off ^ ((off >> 3) & 0x70);
    }
    // smem: Q bufs 2x16KB (hi 0 / lo 8192), KV bufs 2x32KB (Kh0 Kl8192 Vh16384 Vl24576)
    const uint32_t sQb[2] = { sb, sb + 16384 };
    const uint32_t kvb[2] = { sb + 32768, sb + 65536 };

    const long long qrowbase = ((long long)(b * Ll + q0 + r)) * 4096 + h * 64 + half * 32;

    // KV row address for flat chunk cc
    auto kvRow = [&](int cc) -> long long {
        int s2  = (cc < 16) ? 0 : (cc < 24) ? 1 : (cc < 28) ? 2 : 3;
        int bas = (s2 == 0) ? 0 : (s2 == 1) ? 16 : (s2 == 2) ? 24 : 28;
        int Ls2 = (s2 == 0) ? 1024 : (s2 == 1) ? 512 : (s2 == 2) ? 256 : 128;
        int ro2 = (s2 == 0) ? 0 : (s2 == 1) ? 4096 : (s2 == 2) ? 6144 : 7168;
        int kc2 = cc - bas;
        return ((long long)(ro2 + b * Ls2 + kc2 * 64 + r)) * 2048 + h * 64 + half * 32;
    };

    // prologue: Q0 + KV chunk0 (group), KV chunk1 (group)
    {
#pragma unroll
        for (int j = 0; j < 4; j++) {
            CP16(sQb[0]        + dstOff[j], Qh4 + qrowbase + j * 8);
            CP16(sQb[0] + 8192 + dstOff[j], Ql4 + qrowbase + j * 8);
        }
        long long kr = kvRow(0);
#pragma unroll
        for (int j = 0; j < 4; j++) {
            CP16(kvb[0]         + dstOff[j], KVh + kr + j * 8);
            CP16(kvb[0] + 8192  + dstOff[j], KVl + kr + j * 8);
            CP16(kvb[0] + 16384 + dstOff[j], KVh + kr + 1024 + j * 8);
            CP16(kvb[0] + 24576 + dstOff[j], KVl + kr + 1024 + j * 8);
        }
        CP_COMMIT();
        kr = kvRow(1);
#pragma unroll
        for (int j = 0; j < 4; j++) {
            CP16(kvb[1]         + dstOff[j], KVh + kr + j * 8);
            CP16(kvb[1] + 8192  + dstOff[j], KVl + kr + j * 8);
            CP16(kvb[1] + 16384 + dstOff[j], KVh + kr + 1024 + j * 8);
            CP16(kvb[1] + 24576 + dstOff[j], KVl + kr + 1024 + j * 8);
        }
        CP_COMMIT();
    }

    const uint32_t qoffBase = (uint32_t)((w * 16 + (lane & 15)) * 128 + ((lane >> 4) & 1) * 16);
    const uint32_t krowb = (uint32_t)((lane & 7) + ((lane >> 4) & 1) * 8);
    const uint32_t kbyteb = (uint32_t)(((lane >> 3) & 1) * 16);
    const uint32_t vrowb = (uint32_t)((lane & 7) + ((lane >> 3) & 1) * 8);
    const uint32_t vbyteb = (uint32_t)(((lane >> 4) & 1) * 16);

    uint32_t qah[4][4], qal[4][4];
    float oacc[8][4];
#pragma unroll
    for (int t = 0; t < 8; t++)
#pragma unroll
        for (int e = 0; e < 4; e++) oacc[t][e] = 0.f;
    float o[8][4];
    float m0v = -1e30f, m1v = -1e30f, l0 = 0.f, l1 = 0.f;

#pragma unroll 1
    for (int c = 0; c < 30; c++) {
        const int s  = (c < 16) ? 0 : (c < 24) ? 1 : (c < 28) ? 2 : 3;
        const int bas = (s == 0) ? 0 : (s == 1) ? 16 : (s == 2) ? 24 : 28;
        const int nch = (s == 0) ? 16 : (s == 1) ? 8 : (s == 2) ? 4 : 2;
        const int kc = c - bas;

        if (c == 29) CP_WAIT0(); else CP_WAIT1();
        __syncthreads();

        if (kc == 0) {
            uint32_t qb = sQb[s & 1];
#pragma unroll
            for (int k16 = 0; k16 < 4; k16++) {
                uint32_t off = qoffBase + k16 * 32;
                off ^= (off >> 3) & 0x70;
                LDSM4(qah[k16][0], qah[k16][1], qah[k16][2], qah[k16][3], qb + off);
                LDSM4(qal[k16][0], qal[k16][1], qal[k16][2], qal[k16][3], qb + 8192 + off);
            }
            m0v = -1e30f; m1v = -1e30f; l0 = 0.f; l1 = 0.f;
#pragma unroll
            for (int t = 0; t < 8; t++)
#pragma unroll
                for (int e = 0; e < 4; e++) o[t][e] = 0.f;
        }

        const uint32_t bs = kvb[c & 1];
        // ---- S = Q K^T ----
        float sc[8][4];
#pragma unroll
        for (int t = 0; t < 8; t++)
#pragma unroll
            for (int e = 0; e < 4; e++) sc[t][e] = 0.f;
#pragma unroll
        for (int k16 = 0; k16 < 4; k16++) {
            uint32_t kh[8][2], kl[8][2];
#pragma unroll
            for (int t4 = 0; t4 < 4; t4++) {
                uint32_t off = (t4 * 16 + krowb) * 128 + k16 * 32 + kbyteb;
                off ^= (off >> 3) & 0x70;
                LDSM4(kh[2*t4][0], kh[2*t4][1], kh[2*t4+1][0], kh[2*t4+1][1], bs + off);
                LDSM4(kl[2*t4][0], kl[2*t4][1], kl[2*t4+1][0], kl[2*t4+1][1], bs + 8192 + off);
            }
#pragma unroll
            for (int j = 0; j < 8; j++) {
                MMA16816(sc[j], qah[k16], kh[j]);
                MMA16816(sc[j], qal[k16], kh[j]);
                MMA16816(sc[j], qah[k16], kl[j]);
            }
        }

        // ---- online softmax ----
        float rmax0 = -1e30f, rmax1 = -1e30f;
#pragma unroll
        for (int t = 0; t < 8; t++) {
            sc[t][0] *= 0.125f; sc[t][1] *= 0.125f; sc[t][2] *= 0.125f; sc[t][3] *= 0.125f;
            rmax0 = fmaxf(rmax0, fmaxf(sc[t][0], sc[t][1]));
            rmax1 = fmaxf(rmax1, fmaxf(sc[t][2], sc[t][3]));
        }
        rmax0 = fmaxf(rmax0, __shfl_xor_sync(0xffffffffu, rmax0, 1));
        rmax0 = fmaxf(rmax0, __shfl_xor_sync(0xffffffffu, rmax0, 2));
        rmax1 = fmaxf(rmax1, __shfl_xor_sync(0xffffffffu, rmax1, 1));
        rmax1 = fmaxf(rmax1, __shfl_xor_sync(0xffffffffu, rmax1, 2));
        float mn0 = fmaxf(m0v, rmax0), mn1 = fmaxf(m1v, rmax1);
        float fac0 = __expf(m0v - mn0), fac1 = __expf(m1v - mn1);
        float rs0 = 0.f, rs1 = 0.f;
#pragma unroll
        for (int t = 0; t < 8; t++) {
            sc[t][0] = __expf(sc[t][0] - mn0); sc[t][1] = __expf(sc[t][1] - mn0);
            sc[t][2] = __expf(sc[t][2] - mn1); sc[t][3] = __expf(sc[t][3] - mn1);
            rs0 += sc[t][0] + sc[t][1];
            rs1 += sc[t][2] + sc[t][3];
        }
        rs0 += __shfl_xor_sync(0xffffffffu, rs0, 1);
        rs0 += __shfl_xor_sync(0xffffffffu, rs0, 2);
        rs1 += __shfl_xor_sync(0xffffffffu, rs1, 1);
        rs1 += __shfl_xor_sync(0xffffffffu, rs1, 2);
        l0 = l0 * fac0 + rs0; l1 = l1 * fac1 + rs1;
        m0v = mn0; m1v = mn1;
#pragma unroll
        for (int t = 0; t < 8; t++) {
            o[t][0] *= fac0; o[t][1] *= fac0; o[t][2] *= fac1; o[t][3] *= fac1;
        }

        // ---- O += P V ----
#pragma unroll
        for (int k16 = 0; k16 < 4; k16++) {
            uint32_t ph[4], pl[4];
            int t = 2 * k16;
            ph[0] = packsplit(sc[t][0],   sc[t][1],   pl[0]);
            ph[1] = packsplit(sc[t][2],   sc[t][3],   pl[1]);
            ph[2] = packsplit(sc[t+1][0], sc[t+1][1], pl[2]);
            ph[3] = packsplit(sc[t+1][2], sc[t+1][3], pl[3]);
            uint32_t vh[8][2], vl[8][2];
#pragma unroll
            for (int t4 = 0; t4 < 4; t4++) {
                uint32_t off = (k16 * 16 + vrowb) * 128 + t4 * 32 + vbyteb;
                off ^= (off >> 3) & 0x70;
                LDSM4T(vh[2*t4][0], vh[2*t4][1], vh[2*t4+1][0], vh[2*t4+1][1], bs + 16384 + off);
                LDSM4T(vl[2*t4][0], vl[2*t4][1], vl[2*t4+1][0], vl[2*t4+1][1], bs + 24576 + off);
            }
#pragma unroll
            for (int t8 = 0; t8 < 8; t8++) {
                MMA16816(o[t8], ph, vh[t8]);
                MMA16816(o[t8], pl, vh[t8]);
                MMA16816(o[t8], ph, vl[t8]);
            }
        }
        __syncthreads();

        // ---- prefetch chunk c+2 (+ next-scale Q at scale start) ----
        {
            bool doCommit = false;
            int cc = c + 2;
            if (cc < 30) {
                long long kr = kvRow(cc);
                uint32_t bs2 = kvb[c & 1];
#pragma unroll
                for (int j = 0; j < 4; j++) {
                    CP16(bs2         + dstOff[j], KVh + kr + j * 8);
                    CP16(bs2 + 8192  + dstOff[j], KVl + kr + j * 8);
                    CP16(bs2 + 16384 + dstOff[j], KVh + kr + 1024 + j * 8);
                    CP16(bs2 + 24576 + dstOff[j], KVl + kr + 1024 + j * 8);
                }
                doCommit = true;
            }
            if (kc == 0 && s < 3) {
                uint32_t qb2 = sQb[(s + 1) & 1];
                long long qsrc = qrowbase + (long long)(s + 1) * 1024;
#pragma unroll
                for (int j = 0; j < 4; j++) {
                    CP16(qb2        + dstOff[j], Qh4 + qsrc + j * 8);
                    CP16(qb2 + 8192 + dstOff[j], Ql4 + qsrc + j * 8);
                }
                doCommit = true;
            }
            if (doCommit) CP_COMMIT();
        }

        // ---- finalize scale ----
        if (kc == nch - 1) {
            float ws = w4[s];
            float inv0 = ws / l0, inv1 = ws / l1;
#pragma unroll
            for (int t = 0; t < 8; t++) {
                oacc[t][0] += o[t][0] * inv0;
                oacc[t][1] += o[t][1] * inv0;
                oacc[t][2] += o[t][2] * inv1;
                oacc[t][3] += o[t][3] * inv1;
            }
        }
    }

    // ---- write split bf16 ctx ----
    int g = lane >> 2;
    int qrow0 = q0 + w * 16 + g;
    long long base0 = ((long long)(b * Ll + qrow0)) * Dd + h * 64;
    long long base1 = base0 + 8LL * Dd;
#pragma unroll
    for (int t = 0; t < 8; t++) {
        int d0 = t * 8 + (lane & 3) * 2;
        uint32_t lo0, lo1;
        uint32_t hi0 = packsplit(oacc[t][0], oacc[t][1], lo0);
        uint32_t hi1 = packsplit(oacc[t][2], oacc[t][3], lo1);
        *(uint32_t*)(Oh + base0 + d0) = hi0;
        *(uint32_t*)(Ol + base0 + d0) = lo0;
        *(uint32_t*)(Oh + base1 + d0) = hi1;
        *(uint32_t*)(Ol + base1 + d0) = lo1;
    }
}

// ================= LayerNorm: out = LN(a + r), optional split bf16 =================
__global__ __launch_bounds__(256) void ln_kernel(
    const float* __restrict__ a, const float* __restrict__ rr,
    const float* __restrict__ gamma, const float* __restrict__ beta,
    float* __restrict__ out, __nv_bfloat16* __restrict__ oh, __nv_bfloat16* __restrict__ ol)
{
    __shared__ float red[8], red2[8];
    __shared__ float smu, sinv;
    int row = blockIdx.x, tid = threadIdx.x;
    long long base = (long long)row * Dd;
    float4 va = ((const float4*)(a + base))[tid];
    float4 vr = ((const float4*)(rr + base))[tid];
    float x0 = va.x+vr.x, x1 = va.y+vr.y, x2 = va.z+vr.z, x3 = va.w+vr.w;
    float s  = x0+x1+x2+x3;
    float s2 = x0*x0 + x1*x1 + x2*x2 + x3*x3;
#pragma unroll
    for (int off = 16; off >= 1; off >>= 1) {
        s  += __shfl_xor_sync(0xffffffffu, s,  off);
        s2 += __shfl_xor_sync(0xffffffffu, s2, off);
    }
    int w = tid >> 5, lane = tid & 31;
    if (lane == 0) { red[w] = s; red2[w] = s2; }
    __syncthreads();
    if (tid == 0) {
        float S = 0.f, S2 = 0.f;
        for (int i = 0; i < 8; i++) { S += red[i]; S2 += red2[i]; }
        float mu = S * (1.f/Dd);
        smu = mu;
        sinv = rsqrtf(S2 * (1.f/Dd) - mu*mu + 1e-5f);
    }
    __syncthreads();
    float mu = smu, inv = sinv;
    float4 gg = ((const float4*)gamma)[tid];
    float4 bb = ((const float4*)beta)[tid];
    float y0 = (x0-mu)*inv*gg.x + bb.x;
    float y1 = (x1-mu)*inv*gg.y + bb.y;
    float y2 = (x2-mu)*inv*gg.z + bb.z;
    float y3 = (x3-mu)*inv*gg.w + bb.w;
    float4 y; y.x=y0; y.y=y1; y.z=y2; y.w=y3;
    ((float4*)(out + base))[tid] = y;
    if (oh) {
        __nv_bfloat16 h0,l0,h1,l1,h2,l2,h3,l3;
        split2(y0,h0,l0); split2(y1,h1,l1); split2(y2,h2,l2); split2(y3,h3,l3);
        __nv_bfloat162 a01; a01.x=h0; a01.y=h1;
        __nv_bfloat162 a23; a23.x=h2; a23.y=h3;
        __nv_bfloat162 b01; b01.x=l0; b01.y=l1;
        __nv_bfloat162 b23; b23.x=l2; b23.y=l3;
        ((__nv_bfloat162*)(oh + base))[tid*2]   = a01;
        ((__nv_bfloat162*)(oh + base))[tid*2+1] = a23;
        ((__nv_bfloat162*)(ol + base))[tid*2]   = b01;
        ((__nv_bfloat162*)(ol + base))[tid*2+1] = b23;
    }
}

// ================= preprocessing kernels =================
__global__ void pad_split_kernel(const float* __restrict__ x)
{
    const long long total = (long long)Bb*(Ll+4)*Dd;
    for (long long i = blockIdx.x*256LL + threadIdx.x; i < total; i += (long long)gridDim.x*256LL) {
        int d = (int)(i % Dd);
        long long t = i / Dd;
        int p = (int)(t % (Ll+4));
        int b = (int)(t / (Ll+4));
        float v = 0.f;
        if (p >= 2 && p < Ll+2)
            v = x[((long long)b*Ll + (p-2))*Dd + d];
        __nv_bfloat16 h, l; split2(v, h, l);
        g_xph[i] = h; g_xpl[i] = l;
    }
}

__global__ void tdc_split(const float* __restrict__ W)
{
    const long long total = 3LL*Dd*Dd;
    for (long long idx = blockIdx.x*256LL + threadIdx.x; idx < total; idx += (long long)gridDim.x*256LL) {
        int tap = (int)(idx / (Dd*(long long)Dd));
        long long rem = idx % (Dd*(long long)Dd);
        int o = (int)(rem / Dd), i = (int)(rem % Dd);
        float v = W[((long long)o*Dd + i)*3 + tap];
        __nv_bfloat16 h, l; split2(v, h, l);
        g_wdcth[idx] = h; g_wdctl[idx] = l;
    }
}

__global__ void tdec_split(const float* __restrict__ W)
{
    const long long total = 6LL*Dd*Dd;
    for (long long idx = blockIdx.x*256LL + threadIdx.x; idx < total; idx += (long long)gridDim.x*256LL) {
        int st = (int)(idx / (Dd*(long long)Dd));
        int s = st >> 1, tap = st & 1;
        long long rem = idx % (Dd*(long long)Dd);
        int o = (int)(rem / Dd), i = (int)(rem % Dd);
        float v = W[(((long long)s*Dd + o)*Dd + i)*2 + tap];
        __nv_bfloat16 h, l; split2(v, h, l);
        g_wdecth[idx] = h; g_wdectl[idx] = l;
    }
}

// W[bz via inStride][K][N] -> out at bz*outSegStride + outOff + n*K + k (split bf16)
__global__ void transpose_split(const float* __restrict__ W,
                                __nv_bfloat16* __restrict__ oh, __nv_bfloat16* __restrict__ ol,
                                int K, int N, long long inStride,
                                long long outSegStride, long long outOff)
{
    __shared__ float t[32][33];
    int bx = blockIdx.x * 32;
    int by = blockIdx.y * 32;
    long long bz = blockIdx.z;
    const float* Wb = W + bz * inStride;
    int tx = threadIdx.x, ty = threadIdx.y;
    for (int i = ty; i < 32; i += 8)
        t[i][tx] = Wb[(long long)(by + i) * N + bx + tx];
    __syncthreads();
    long long ob = bz * outSegStride + outOff;
    for (int i = ty; i < 32; i += 8) {
        float v = t[tx][i];
        __nv_bfloat16 h, l; split2(v, h, l);
        long long oidx = ob + (long long)(bx + i) * K + by + tx;
        oh[oidx] = h; ol[oidx] = l;
    }
}

__global__ void agg_kernel(const float* __restrict__ logits, float* __restrict__ aux)
{
    float mx = -1e30f;
    for (int s = 0; s < Ss; s++) mx = fmaxf(mx, logits[s]);
    float e[Ss], sum = 0.f;
    for (int s = 0; s < Ss; s++) { e[s] = expf(logits[s] - mx); sum += e[s]; }
    float ent = 0.f;
    for (int s = 0; s < Ss; s++) {
        float w = e[s] / sum;
        g_w[s] = w;
        ent -= w * logf(w + 1e-9f);
    }
    if (aux) *aux = ent;
}

__global__ void fill0_kernel(float* p, long long n)
{
    for (long long i = blockIdx.x*256LL + threadIdx.x; i < n; i += (long long)gridDim.x*256LL)
        p[i] = 0.f;
}

// ================= launch =================
extern "C" void kernel_launch(void* const* d_in, const int* in_sizes, int n_in,
                              void* d_out, int out_size)
{
    const float* x     = (const float*)d_in[0];
    const float* W_dc  = (const float*)d_in[1];
    const float* b_dc  = (const float*)d_in[2];
    const float* W_dec = (const float*)d_in[3];
    const float* Wq    = (const float*)d_in[4];
    const float* Wk    = (const float*)d_in[5];
    const float* Wv    = (const float*)d_in[6];
    const float* Wo    = (const float*)d_in[7];
    const float* aggl  = (const float*)d_in[8];
    const float* g1    = (const float*)d_in[9];
    const float* be1   = (const float*)d_in[10];
    const float* g2    = (const float*)d_in[11];
    const float* be2   = (const float*)d_in[12];
    const float* W1    = (const float*)d_in[13];
    const float* b1    = (const float*)d_in[14];
    const float* W2    = (const float*)d_in[15];
    const float* b2    = (const float*)d_in[16];
    float* out = (float*)d_out;

    static int smem_set = 0;
    const int GEMM_SMEM = 2 * 65536;
    const int ATTN_SMEM = 32768 + 2 * 32768;   // 96KB -> 2 CTAs/SM
    if (!smem_set) {
        cudaFuncSetAttribute(gemmM, cudaFuncAttributeMaxDynamicSharedMemorySize, GEMM_SMEM);
        cudaFuncSetAttribute(attnF, cudaFuncAttributeMaxDynamicSharedMemorySize, ATTN_SMEM);
        smem_set = 1;
    }

#define SYM(v, s) cudaGetSymbolAddress((void**)&v, s)
    __nv_bfloat16 *xph,*xpl,*sah,*sal,*q4h,*q4l,*kvh,*kvl,*ctxh,*ctxl,*x1h,*x1l,*ffnh,*ffnl;
    __nv_bfloat16 *wdcth,*wdctl,*wdecth,*wdectl,*wqth,*wqtl,*wkvth,*wkvtl,*woth,*wotl,*w1th,*w1tl,*w2th,*w2tl;
    float *x1,*tmp,*gw;
    SYM(xph,g_xph); SYM(xpl,g_xpl); SYM(sah,g_sah); SYM(sal,g_sal);
    SYM(q4h,g_q4h); SYM(q4l,g_q4l); SYM(kvh,g_kvh); SYM(kvl,g_kvl);
    SYM(ctxh,g_ctxh); SYM(ctxl,g_ctxl); SYM(x1h,g_x1h); SYM(x1l,g_x1l); SYM(ffnh,g_ffnh); SYM(ffnl,g_ffnl);
    SYM(wdcth,g_wdcth); SYM(wdctl,g_wdctl); SYM(wdecth,g_wdecth); SYM(wdectl,g_wdectl);
    SYM(wqth,g_wqth); SYM(wqtl,g_wqtl); SYM(wkvth,g_wkvth); SYM(wkvtl,g_wkvtl);
    SYM(woth,g_woth); SYM(wotl,g_wotl);
    SYM(w1th,g_w1th); SYM(w1tl,g_w1tl); SYM(w2th,g_w2th); SYM(w2tl,g_w2tl);
    SYM(x1,g_x1); SYM(tmp,g_tmp); SYM(gw,g_w);
#undef SYM

    const int BLD = Bb*Ll*Dd;
    const int4 NOSEG = make_int4(0x7fffffff, 0x7fffffff, 0x7fffffff, 0);

    // ---- preprocessing ----
    tdc_split <<<1024, 256>>>(W_dc);
    tdec_split<<<2048, 256>>>(W_dec);
    {
        dim3 blk(32, 8);
        // Wq: flat [4*1024][1024]
        transpose_split<<<dim3(Dd/32, Dd/32, 4), blk>>>(Wq, wqth, wqtl, Dd, Dd, DDc, DDc, 0);
        // Wkv: [s][2048][1024] with Wk rows 0-1023, Wv rows 1024-2047
        transpose_split<<<dim3(Dd/32, Dd/32, 4), blk>>>(Wk, wkvth, wkvtl, Dd, Dd, DDc, 2*DDc, 0);
        transpose_split<<<dim3(Dd/32, Dd/32, 4), blk>>>(Wv, wkvth, wkvtl, Dd, Dd, 0,   2*DDc, DDc);
        transpose_split<<<dim3(Dd/32, Dd/32, 1), blk>>>(Wo, woth, wotl, Dd, Dd, DDc, DDc, 0);
        transpose_split<<<dim3(Ff/32, Dd/32, 1), blk>>>(W1, w1th, w1tl, Dd, Ff, (long long)Dd*Ff, (long long)Dd*Ff, 0);
        transpose_split<<<dim3(Dd/32, Ff/32, 1), blk>>>(W2, w2th, w2tl, Ff, Dd, (long long)Dd*Ff, (long long)Dd*Ff, 0);
    }
    pad_split_kernel<<<4096, 256>>>(x);
    if (out_size > BLD) {
        long long gap = (long long)out_size - BLD;
        fill0_kernel<<<256, 256>>>(out + BLD, gap);
        agg_kernel<<<1, 1>>>(aggl, out + out_size - 1);
    } else {
        agg_kernel<<<1, 1>>>(aggl, (float*)0);
    }

    auto gemm = [&](const __nv_bfloat16* Ah, const __nv_bfloat16* Al,
                    const __nv_bfloat16* Bh, const __nv_bfloat16* Bl,
                    float* Cf, __nv_bfloat16* Oh, __nv_bfloat16* Ol, const float* bias,
                    int M, int N, int K, int taps, long long tapStrideA,
                    int lseg, long long segStride, int rowStride, long long offA, int epi,
                    int4 segEnd, long long segUnit) {
        dim3 g(N/128, M/128);
        gemmM<<<g, 256, GEMM_SMEM>>>(Ah, Al, Bh, Bl, Cf, Oh, Ol, bias,
                                     N, K, taps, tapStrideA, lseg, segStride, rowStride, offA, epi,
                                     segEnd, segUnit);
    };

    // 1. dilated conv (k=3, dil=2) + bias + ReLU -> sa rows [0,4096)
    gemm(xph, xpl, wdcth, wdctl, 0, sah, sal, b_dc,
         Bb*Ll, Dd, Dd, 3, 2LL*Dd, Ll, (long long)(Ll+4)*Dd, Dd, 0, 1, NOSEG, 0);

    // 2. hierarchical decomposition (stride-2, k=2) into sa rows [4096,7680)
    {
        const long long inOff[3]  = {0, 4096, 6144};
        const long long outOff[3] = {4096, 6144, 7168};
        int Lin[3] = {1024, 512, 256};
        for (int s = 0; s < 3; s++)
            gemm(sah + inOff[s]*Dd, sal + inOff[s]*Dd,
                 wdecth + (long long)s*2*DDc, wdectl + (long long)s*2*DDc,
                 0, sah + outOff[s]*Dd, sal + outOff[s]*Dd, 0,
                 Bb*(Lin[s]/2), Dd, Dd, 2, (long long)Dd,
                 Lin[s]/2, (long long)Lin[s]*Dd, 2*Dd, 0, 0, NOSEG, 0);
    }

    // 3a. merged Q projection: q4 = xc @ [Wq0|Wq1|Wq2|Wq3]  (M=4096, N=4096)
    gemm(sah, sal, wqth, wqtl, 0, q4h, q4l, 0,
         Bb*Ll, 4*Dd, Dd, 1, 0, Bb*Ll, 0, Dd, 0, 0, NOSEG, 0);

    // 3b. merged K|V projection over all scales (segmented B): kv[7680][2048]
    gemm(sah, sal, wkvth, wkvtl, 0, kvh, kvl, 0,
         SAR, 2048, Dd, 1, 0, SAR, 0, Dd, 0, 0,
         make_int4(4096, 6144, 7168, 0), 2*DDc);

    // 3c. fused 4-scale attention -> split bf16 ctx
    {
        dim3 ag(Ll/64, Hh, Bb);
        attnF<<<ag, 128, ATTN_SMEM>>>(q4h, q4l, kvh, kvl, ctxh, ctxl, gw);
    }

    // 4. output projection Wo -> tmp fp32
    gemm(ctxh, ctxl, woth, wotl, tmp, 0, 0, 0, Bb*Ll, Dd, Dd, 1, 0, Bb*Ll, 0, Dd, 0, 0, NOSEG, 0);

    // 5. residual + LN1 (fp32 + split)
    ln_kernel<<<Bb*Ll, 256>>>(x, tmp, g1, be1, x1, x1h, x1l);

    // 6. FFN (GELU fused, split intermediate)
    gemm(x1h, x1l, w1th, w1tl, 0, ffnh, ffnl, b1, Bb*Ll, Ff, Dd, 1, 0, Bb*Ll, 0, Dd, 0, 2, NOSEG, 0);
    gemm(ffnh, ffnl, w2th, w2tl, tmp, 0, 0, b2, Bb*Ll, Dd, Ff, 1, 0, Bb*Ll, 0, Ff, 0, 0, NOSEG, 0);

    // 7. residual + LN2 -> out
    ln_kernel<<<Bb*Ll, 256>>>(x1, tmp, g2, be2, out, (__nv_bfloat16*)0, (__nv_bfloat16*)0);
}

// round 6
// speedup vs baseline: 3.5067x; 1.3876x over previous
#include <cuda_runtime.h>
#include <cuda_fp16.h>
#include <math.h>
#include <stdint.h>

#define Bb 4
#define Ll 1024
#define Dd 1024
#define Hh 16
#define Ff 4096
#define Ss 4
#define DDc (1024LL*1024LL)
#define SAR 7680   // total scale-activation rows: 4096+2048+1024+512

// ================= static scratch (no allocations) =================
__device__ __align__(256) __half g_xph[Bb*(Ll+4)*Dd], g_xpl[Bb*(Ll+4)*Dd];
__device__ __align__(256) __half g_sah[SAR*Dd],       g_sal[SAR*Dd];       // xc|s1|s2|s3
__device__ __align__(256) __half g_q4h[Bb*Ll*4*Dd],   g_q4l[Bb*Ll*4*Dd];   // [4096][4096]
__device__ __align__(256) __half g_kvh[SAR*2048];                          // [7680][2048] K|V (hi only)
__device__ __align__(256) __half g_ctxh[Bb*Ll*Dd],    g_ctxl[Bb*Ll*Dd];
__device__ __align__(256) __half g_x1h[Bb*Ll*Dd],     g_x1l[Bb*Ll*Dd];
__device__ __align__(256) __half g_ffnh[Bb*Ll*Ff],    g_ffnl[Bb*Ll*Ff];
__device__ __align__(256) __half g_wdcth[3*1024*1024];
__device__ __align__(256) __half g_wdecth[6*1024*1024];
__device__ __align__(256) __half g_wqth[4*1024*1024];
__device__ __align__(256) __half g_wkvth[4*2048*1024];
__device__ __align__(256) __half g_woth[1024*1024];
__device__ __align__(256) __half g_w1th[1024*4096];
__device__ __align__(256) __half g_w2th[4096*1024];
__device__ __align__(256) float g_x1[Bb*Ll*Dd];
__device__ __align__(256) float g_tmp[Bb*Ll*Dd];
__device__ float g_w[Ss];

// ================= PTX helpers (base features only) =================
#define CP16(dst, src)    asm volatile("cp.async.cg.shared.global [%0], [%1], 16;" :: "r"(dst), "l"(src) : "memory")
#define CP_COMMIT()       asm volatile("cp.async.commit_group;" ::: "memory")
#define CP_WAIT1()        asm volatile("cp.async.wait_group 1;" ::: "memory")
#define CP_WAIT0()        asm volatile("cp.async.wait_group 0;" ::: "memory")

#define LDSM4(r0,r1,r2,r3,addr) \
    asm volatile("ldmatrix.sync.aligned.m8n8.x4.shared.b16 {%0,%1,%2,%3}, [%4];" \
        : "=r"(r0),"=r"(r1),"=r"(r2),"=r"(r3) : "r"(addr))
#define LDSM4T(r0,r1,r2,r3,addr) \
    asm volatile("ldmatrix.sync.aligned.m8n8.x4.trans.shared.b16 {%0,%1,%2,%3}, [%4];" \
        : "=r"(r0),"=r"(r1),"=r"(r2),"=r"(r3) : "r"(addr))
#define LDSM2(r0,r1,addr) \
    asm volatile("ldmatrix.sync.aligned.m8n8.x2.shared.b16 {%0,%1}, [%2];" \
        : "=r"(r0),"=r"(r1) : "r"(addr))
#define MMA16816(d, a, b) \
    asm volatile("mma.sync.aligned.m16n8k16.row.col.f32.f16.f16.f32 " \
        "{%0,%1,%2,%3}, {%4,%5,%6,%7}, {%8,%9}, {%0,%1,%2,%3};" \
        : "+f"((d)[0]),"+f"((d)[1]),"+f"((d)[2]),"+f"((d)[3]) \
        : "r"((a)[0]),"r"((a)[1]),"r"((a)[2]),"r"((a)[3]), "r"((b)[0]),"r"((b)[1]))

__device__ __forceinline__ uint32_t smem_u32(const void* p) {
    uint32_t a;
    asm("{ .reg .u64 t; cvta.to.shared.u64 t, %1; cvt.u32.u64 %0, t; }" : "=r"(a) : "l"(p));
    return a;
}

__device__ __forceinline__ void split2(float x, __half& h, __half& l) {
    h = __float2half_rn(x);
    l = __float2half_rn(x - __half2float(h));
}

__device__ __forceinline__ uint32_t packsplit(float a, float b, uint32_t& lo) {
    __half ha = __float2half_rn(a), hb = __float2half_rn(b);
    __half la = __float2half_rn(a - __half2float(ha));
    __half lb = __float2half_rn(b - __half2float(hb));
    lo = ((uint32_t)__half_as_ushort(lb) << 16) | __half_as_ushort(la);
    return ((uint32_t)__half_as_ushort(hb) << 16) | __half_as_ushort(ha);
}

// ================= mma.sync 2-term fp16 split GEMM (seg-selectable B) =================
// C = A @ Bh with A = Ah + Al (fp16 split, exact); B rounded to fp16.
__global__ __launch_bounds__(256, 1) void gemmM(
    const __half* __restrict__ Ah, const __half* __restrict__ Al,
    const __half* __restrict__ Bh,
    float* __restrict__ Cf, __half* __restrict__ Oh, __half* __restrict__ Ol,
    const float* __restrict__ bias,
    int N, int K, int taps, long long tapStrideA,
    int lseg, long long segStride, int rowStride, long long offA, int epi,
    int4 segEnd, long long segUnit)
{
    extern __shared__ char smem[];
    uint32_t sb = smem_u32(smem);
    const int tid = threadIdx.x;
    const int wid = tid >> 5, lane = tid & 31;
    const int m0 = blockIdx.y * 128, n0 = blockIdx.x * 128;

    {
        int sidx = (m0 >= segEnd.x) + (m0 >= segEnd.y) + (m0 >= segEnd.z);
        Bh += (long long)sidx * segUnit;
    }

    const int r = tid >> 1, half_ = tid & 1;
    const long long mrow = m0 + r;
    const long long aoff0 = (mrow / lseg) * segStride + (mrow % lseg) * (long long)rowStride + offA + half_ * 32;
    const long long boff0 = (long long)(n0 + r) * K + half_ * 32;
    uint32_t dstOff[4];
#pragma unroll
    for (int j = 0; j < 4; j++) {
        uint32_t off = (uint32_t)(r * 128 + half_ * 64 + j * 16);
        dstOff[j] = off ^ ((off >> 3) & 0x70);
    }
    const uint32_t bufBase[2] = { sb, sb + 49152 };
    const int NCk = K >> 6;
    const int NC = NCk * taps;
    const long long tapStrideB = (long long)N * K;

    const int wm = wid & 1, wn = wid >> 1;
    const int arow = wm * 64 + (lane & 15);
    const uint32_t aRowOff = (uint32_t)(arow * 128);
    const uint32_t aXb = (uint32_t)((arow & 7) << 4);
    const uint32_t aHalf = (uint32_t)((lane >> 4) * 16);
    const uint32_t bRowOff = (uint32_t)((wn * 32 + (lane & 7)) * 128);
    const uint32_t bXb = (uint32_t)((lane & 7) << 4);
    const uint32_t bHalf = (uint32_t)(((lane >> 3) & 1) * 16);

    float acc[4][4][4];
#pragma unroll
    for (int i = 0; i < 4; i++)
#pragma unroll
        for (int j = 0; j < 4; j++)
#pragma unroll
            for (int e = 0; e < 4; e++) acc[i][j][e] = 0.f;

#pragma unroll 1
    for (int c = 0; c < 2 && c < NC; c++) {
        int tap = c / NCk, kc = c % NCk;
        long long ao = aoff0 + (long long)tap * tapStrideA + kc * 64;
        long long bo = boff0 + (long long)tap * tapStrideB + kc * 64;
        uint32_t bs = bufBase[c & 1];
#pragma unroll
        for (int j = 0; j < 4; j++) {
            CP16(bs +         dstOff[j], Ah + ao + j * 8);
            CP16(bs + 16384 + dstOff[j], Al + ao + j * 8);
            CP16(bs + 32768 + dstOff[j], Bh + bo + j * 8);
        }
        CP_COMMIT();
    }

#pragma unroll 1
    for (int c = 0; c < NC; c++) {
        const int buf = c & 1;
        if (c == NC - 1) CP_WAIT0(); else CP_WAIT1();
        __syncthreads();

        const uint32_t bs = bufBase[buf];
#pragma unroll
        for (int k16 = 0; k16 < 4; k16++) {
            const uint32_t aoff = aRowOff + ((k16 * 32 + aHalf) ^ aXb);
            const uint32_t boff = bRowOff + ((k16 * 32 + bHalf) ^ bXb);
            uint32_t ah[4][4], al_[4][4], bh[4][2];
#pragma unroll
            for (int i = 0; i < 4; i++) {
                LDSM4(ah[i][0], ah[i][1], ah[i][2], ah[i][3], bs + i * 2048 + aoff);
                LDSM4(al_[i][0], al_[i][1], al_[i][2], al_[i][3], bs + 16384 + i * 2048 + aoff);
            }
#pragma unroll
            for (int j = 0; j < 4; j++) {
                LDSM2(bh[j][0], bh[j][1], bs + 32768 + j * 1024 + boff);
            }
#pragma unroll
            for (int i = 0; i < 4; i++)
#pragma unroll
                for (int j = 0; j < 4; j++) {
                    MMA16816(acc[i][j], ah[i],  bh[j]);
                    MMA16816(acc[i][j], al_[i], bh[j]);
                }
        }
        __syncthreads();

        if (c + 2 < NC) {
            int cc = c + 2;
            int tap = cc / NCk, kc = cc % NCk;
            long long ao = aoff0 + (long long)tap * tapStrideA + kc * 64;
            long long bo = boff0 + (long long)tap * tapStrideB + kc * 64;
#pragma unroll
            for (int j = 0; j < 4; j++) {
                CP16(bs +         dstOff[j], Ah + ao + j * 8);
                CP16(bs + 16384 + dstOff[j], Al + ao + j * 8);
                CP16(bs + 32768 + dstOff[j], Bh + bo + j * 8);
            }
            CP_COMMIT();
        }
    }

#pragma unroll
    for (int i = 0; i < 4; i++)
#pragma unroll
        for (int j = 0; j < 4; j++)
#pragma unroll
            for (int p = 0; p < 2; p++) {
                int rr = m0 + wm * 64 + i * 16 + (lane >> 2) + p * 8;
                int cc = n0 + wn * 32 + j * 8 + (lane & 3) * 2;
                float v0 = acc[i][j][p * 2];
                float v1 = acc[i][j][p * 2 + 1];
                if (bias) { v0 += bias[cc]; v1 += bias[cc + 1]; }
                if (epi == 1) { v0 = fmaxf(v0, 0.f); v1 = fmaxf(v1, 0.f); }
                else if (epi == 2) {
                    v0 = 0.5f * v0 * (1.f + erff(v0 * 0.70710678118654752f));
                    v1 = 0.5f * v1 * (1.f + erff(v1 * 0.70710678118654752f));
                }
                long long idx = (long long)rr * N + cc;
                if (Cf) { float2 f; f.x = v0; f.y = v1; *(float2*)(Cf + idx) = f; }
                if (Oh) {
                    uint32_t lo;
                    uint32_t hi = packsplit(v0, v1, lo);
                    *(uint32_t*)(Oh + idx) = hi;
                    if (Ol) *(uint32_t*)(Ol + idx) = lo;
                }
            }
}

// ================= fused 4-scale tensor-core flash attention (2-term fp16) =================
__global__ __launch_bounds__(128, 2) void attnF(
    const __half* __restrict__ Qh4, const __half* __restrict__ Ql4,
    const __half* __restrict__ KVh,
    __half* __restrict__ Oh, __half* __restrict__ Ol,
    const float* __restrict__ gw)
{
    extern __shared__ char smem[];
    uint32_t sb = smem_u32(smem);
    const int tid = threadIdx.x;
    const int w = tid >> 5, lane = tid & 31;
    const int b = blockIdx.z, h = blockIdx.y;
    const int q0 = blockIdx.x * 64;

    float w4[4];
#pragma unroll
    for (int s = 0; s < 4; s++) w4[s] = gw[s];

    const int r = tid >> 1, half_ = tid & 1;
    uint32_t dstOff[4];
#pragma unroll
    for (int j = 0; j < 4; j++) {
        uint32_t off = (uint32_t)(r * 128 + half_ * 64 + j * 16);
        dstOff[j] = off ^ ((off >> 3) & 0x70);
    }
    // smem: Q bufs 2x16KB (hi 0 / lo 8192), KV bufs 2x16KB (Kh 0 / Vh 8192)
    const uint32_t sQb[2] = { sb, sb + 16384 };
    const uint32_t kvb[2] = { sb + 32768, sb + 49152 };

    const long long qrowbase = ((long long)(b * Ll + q0 + r)) * 4096 + h * 64 + half_ * 32;

    auto kvRow = [&](int cc) -> long long {
        int s2  = (cc < 16) ? 0 : (cc < 24) ? 1 : (cc < 28) ? 2 : 3;
        int bas = (s2 == 0) ? 0 : (s2 == 1) ? 16 : (s2 == 2) ? 24 : 28;
        int Ls2 = (s2 == 0) ? 1024 : (s2 == 1) ? 512 : (s2 == 2) ? 256 : 128;
        int ro2 = (s2 == 0) ? 0 : (s2 == 1) ? 4096 : (s2 == 2) ? 6144 : 7168;
        int kc2 = cc - bas;
        return ((long long)(ro2 + b * Ls2 + kc2 * 64 + r)) * 2048 + h * 64 + half_ * 32;
    };

    // prologue
    {
#pragma unroll
        for (int j = 0; j < 4; j++) {
            CP16(sQb[0]        + dstOff[j], Qh4 + qrowbase + j * 8);
            CP16(sQb[0] + 8192 + dstOff[j], Ql4 + qrowbase + j * 8);
        }
        long long kr = kvRow(0);
#pragma unroll
        for (int j = 0; j < 4; j++) {
            CP16(kvb[0]        + dstOff[j], KVh + kr + j * 8);
            CP16(kvb[0] + 8192 + dstOff[j], KVh + kr + 1024 + j * 8);
        }
        CP_COMMIT();
        kr = kvRow(1);
#pragma unroll
        for (int j = 0; j < 4; j++) {
            CP16(kvb[1]        + dstOff[j], KVh + kr + j * 8);
            CP16(kvb[1] + 8192 + dstOff[j], KVh + kr + 1024 + j * 8);
        }
        CP_COMMIT();
    }

    const uint32_t qoffBase = (uint32_t)((w * 16 + (lane & 15)) * 128 + ((lane >> 4) & 1) * 16);
    const uint32_t krowb = (uint32_t)((lane & 7) + ((lane >> 4) & 1) * 8);
    const uint32_t kbyteb = (uint32_t)(((lane >> 3) & 1) * 16);
    const uint32_t vrowb = (uint32_t)((lane & 7) + ((lane >> 3) & 1) * 8);
    const uint32_t vbyteb = (uint32_t)(((lane >> 4) & 1) * 16);

    uint32_t qah[4][4], qal[4][4];
    float oacc[8][4];
#pragma unroll
    for (int t = 0; t < 8; t++)
#pragma unroll
        for (int e = 0; e < 4; e++) oacc[t][e] = 0.f;
    float o[8][4];
    float m0v = -1e30f, m1v = -1e30f, l0 = 0.f, l1 = 0.f;

#pragma unroll 1
    for (int c = 0; c < 30; c++) {
        const int s  = (c < 16) ? 0 : (c < 24) ? 1 : (c < 28) ? 2 : 3;
        const int bas = (s == 0) ? 0 : (s == 1) ? 16 : (s == 2) ? 24 : 28;
        const int nch = (s == 0) ? 16 : (s == 1) ? 8 : (s == 2) ? 4 : 2;
        const int kc = c - bas;

        if (c == 29) CP_WAIT0(); else CP_WAIT1();
        __syncthreads();

        if (kc == 0) {
            uint32_t qb = sQb[s & 1];
#pragma unroll
            for (int k16 = 0; k16 < 4; k16++) {
                uint32_t off = qoffBase + k16 * 32;
                off ^= (off >> 3) & 0x70;
                LDSM4(qah[k16][0], qah[k16][1], qah[k16][2], qah[k16][3], qb + off);
                LDSM4(qal[k16][0], qal[k16][1], qal[k16][2], qal[k16][3], qb + 8192 + off);
            }
            m0v = -1e30f; m1v = -1e30f; l0 = 0.f; l1 = 0.f;
#pragma unroll
            for (int t = 0; t < 8; t++)
#pragma unroll
                for (int e = 0; e < 4; e++) o[t][e] = 0.f;
        }

        const uint32_t bs = kvb[c & 1];
        // ---- S = Q K^T ----
        float sc[8][4];
#pragma unroll
        for (int t = 0; t < 8; t++)
#pragma unroll
            for (int e = 0; e < 4; e++) sc[t][e] = 0.f;
#pragma unroll
        for (int k16 = 0; k16 < 4; k16++) {
            uint32_t kh[8][2];
#pragma unroll
            for (int t4 = 0; t4 < 4; t4++) {
                uint32_t off = (t4 * 16 + krowb) * 128 + k16 * 32 + kbyteb;
                off ^= (off >> 3) & 0x70;
                LDSM4(kh[2*t4][0], kh[2*t4][1], kh[2*t4+1][0], kh[2*t4+1][1], bs + off);
            }
#pragma unroll
            for (int j = 0; j < 8; j++) {
                MMA16816(sc[j], qah[k16], kh[j]);
                MMA16816(sc[j], qal[k16], kh[j]);
            }
        }

        // ---- online softmax ----
        float rmax0 = -1e30f, rmax1 = -1e30f;
#pragma unroll
        for (int t = 0; t < 8; t++) {
            sc[t][0] *= 0.125f; sc[t][1] *= 0.125f; sc[t][2] *= 0.125f; sc[t][3] *= 0.125f;
            rmax0 = fmaxf(rmax0, fmaxf(sc[t][0], sc[t][1]));
            rmax1 = fmaxf(rmax1, fmaxf(sc[t][2], sc[t][3]));
        }
        rmax0 = fmaxf(rmax0, __shfl_xor_sync(0xffffffffu, rmax0, 1));
        rmax0 = fmaxf(rmax0, __shfl_xor_sync(0xffffffffu, rmax0, 2));
        rmax1 = fmaxf(rmax1, __shfl_xor_sync(0xffffffffu, rmax1, 1));
        rmax1 = fmaxf(rmax1, __shfl_xor_sync(0xffffffffu, rmax1, 2));
        float mn0 = fmaxf(m0v, rmax0), mn1 = fmaxf(m1v, rmax1);
        float fac0 = __expf(m0v - mn0), fac1 = __expf(m1v - mn1);
        float rs0 = 0.f, rs1 = 0.f;
#pragma unroll
        for (int t = 0; t < 8; t++) {
            sc[t][0] = __expf(sc[t][0] - mn0); sc[t][1] = __expf(sc[t][1] - mn0);
            sc[t][2] = __expf(sc[t][2] - mn1); sc[t][3] = __expf(sc[t][3] - mn1);
            rs0 += sc[t][0] + sc[t][1];
            rs1 += sc[t][2] + sc[t][3];
        }
        rs0 += __shfl_xor_sync(0xffffffffu, rs0, 1);
        rs0 += __shfl_xor_sync(0xffffffffu, rs0, 2);
        rs1 += __shfl_xor_sync(0xffffffffu, rs1, 1);
        rs1 += __shfl_xor_sync(0xffffffffu, rs1, 2);
        l0 = l0 * fac0 + rs0; l1 = l1 * fac1 + rs1;
        m0v = mn0; m1v = mn1;
#pragma unroll
        for (int t = 0; t < 8; t++) {
            o[t][0] *= fac0; o[t][1] *= fac0; o[t][2] *= fac1; o[t][3] *= fac1;
        }

        // ---- O += P V ----
#pragma unroll
        for (int k16 = 0; k16 < 4; k16++) {
            uint32_t ph[4], pl[4];
            int t = 2 * k16;
            ph[0] = packsplit(sc[t][0],   sc[t][1],   pl[0]);
            ph[1] = packsplit(sc[t][2],   sc[t][3],   pl[1]);
            ph[2] = packsplit(sc[t+1][0], sc[t+1][1], pl[2]);
            ph[3] = packsplit(sc[t+1][2], sc[t+1][3], pl[3]);
            uint32_t vh[8][2];
#pragma unroll
            for (int t4 = 0; t4 < 4; t4++) {
                uint32_t off = (k16 * 16 + vrowb) * 128 + t4 * 32 + vbyteb;
                off ^= (off >> 3) & 0x70;
                LDSM4T(vh[2*t4][0], vh[2*t4][1], vh[2*t4+1][0], vh[2*t4+1][1], bs + 8192 + off);
            }
#pragma unroll
            for (int t8 = 0; t8 < 8; t8++) {
                MMA16816(o[t8], ph, vh[t8]);
                MMA16816(o[t8], pl, vh[t8]);
            }
        }
        __syncthreads();

        // ---- prefetch chunk c+2 (+ next-scale Q at scale start) ----
        {
            bool doCommit = false;
            int cc = c + 2;
            if (cc < 30) {
                long long kr = kvRow(cc);
                uint32_t bs2 = kvb[c & 1];
#pragma unroll
                for (int j = 0; j < 4; j++) {
                    CP16(bs2        + dstOff[j], KVh + kr + j * 8);
                    CP16(bs2 + 8192 + dstOff[j], KVh + kr + 1024 + j * 8);
                }
                doCommit = true;
            }
            if (kc == 0 && s < 3) {
                uint32_t qb2 = sQb[(s + 1) & 1];
                long long qsrc = qrowbase + (long long)(s + 1) * 1024;
#pragma unroll
                for (int j = 0; j < 4; j++) {
                    CP16(qb2        + dstOff[j], Qh4 + qsrc + j * 8);
                    CP16(qb2 + 8192 + dstOff[j], Ql4 + qsrc + j * 8);
                }
                doCommit = true;
            }
            if (doCommit) CP_COMMIT();
        }

        // ---- finalize scale ----
        if (kc == nch - 1) {
            float ws = w4[s];
            float inv0 = ws / l0, inv1 = ws / l1;
#pragma unroll
            for (int t = 0; t < 8; t++) {
                oacc[t][0] += o[t][0] * inv0;
                oacc[t][1] += o[t][1] * inv0;
                oacc[t][2] += o[t][2] * inv1;
                oacc[t][3] += o[t][3] * inv1;
            }
        }
    }

    // ---- write split fp16 ctx ----
    int g = lane >> 2;
    int qrow0 = q0 + w * 16 + g;
    long long base0 = ((long long)(b * Ll + qrow0)) * Dd + h * 64;
    long long base1 = base0 + 8LL * Dd;
#pragma unroll
    for (int t = 0; t < 8; t++) {
        int d0 = t * 8 + (lane & 3) * 2;
        uint32_t lo0, lo1;
        uint32_t hi0 = packsplit(oacc[t][0], oacc[t][1], lo0);
        uint32_t hi1 = packsplit(oacc[t][2], oacc[t][3], lo1);
        *(uint32_t*)(Oh + base0 + d0) = hi0;
        *(uint32_t*)(Ol + base0 + d0) = lo0;
        *(uint32_t*)(Oh + base1 + d0) = hi1;
        *(uint32_t*)(Ol + base1 + d0) = lo1;
    }
}

// ================= LayerNorm: out = LN(a + r), optional split fp16 =================
__global__ __launch_bounds__(256) void ln_kernel(
    const float* __restrict__ a, const float* __restrict__ rr,
    const float* __restrict__ gamma, const float* __restrict__ beta,
    float* __restrict__ out, __half* __restrict__ oh, __half* __restrict__ ol)
{
    __shared__ float red[8], red2[8];
    __shared__ float smu, sinv;
    int row = blockIdx.x, tid = threadIdx.x;
    long long base = (long long)row * Dd;
    float4 va = ((const float4*)(a + base))[tid];
    float4 vr = ((const float4*)(rr + base))[tid];
    float x0 = va.x+vr.x, x1 = va.y+vr.y, x2 = va.z+vr.z, x3 = va.w+vr.w;
    float s  = x0+x1+x2+x3;
    float s2 = x0*x0 + x1*x1 + x2*x2 + x3*x3;
#pragma unroll
    for (int off = 16; off >= 1; off >>= 1) {
        s  += __shfl_xor_sync(0xffffffffu, s,  off);
        s2 += __shfl_xor_sync(0xffffffffu, s2, off);
    }
    int w = tid >> 5, lane = tid & 31;
    if (lane == 0) { red[w] = s; red2[w] = s2; }
    __syncthreads();
    if (tid == 0) {
        float S = 0.f, S2 = 0.f;
        for (int i = 0; i < 8; i++) { S += red[i]; S2 += red2[i]; }
        float mu = S * (1.f/Dd);
        smu = mu;
        sinv = rsqrtf(S2 * (1.f/Dd) - mu*mu + 1e-5f);
    }
    __syncthreads();
    float mu = smu, inv = sinv;
    float4 gg = ((const float4*)gamma)[tid];
    float4 bb = ((const float4*)beta)[tid];
    float y0 = (x0-mu)*inv*gg.x + bb.x;
    float y1 = (x1-mu)*inv*gg.y + bb.y;
    float y2 = (x2-mu)*inv*gg.z + bb.z;
    float y3 = (x3-mu)*inv*gg.w + bb.w;
    float4 y; y.x=y0; y.y=y1; y.z=y2; y.w=y3;
    ((float4*)(out + base))[tid] = y;
    if (oh) {
        uint32_t lo01, lo23;
        uint32_t hi01 = packsplit(y0, y1, lo01);
        uint32_t hi23 = packsplit(y2, y3, lo23);
        ((uint32_t*)(oh + base))[tid*2]   = hi01;
        ((uint32_t*)(oh + base))[tid*2+1] = hi23;
        ((uint32_t*)(ol + base))[tid*2]   = lo01;
        ((uint32_t*)(ol + base))[tid*2+1] = lo23;
    }
}

// ================= preprocessing kernels =================
__global__ void pad_split_kernel(const float* __restrict__ x)
{
    const long long total = (long long)Bb*(Ll+4)*Dd;
    for (long long i = blockIdx.x*256LL + threadIdx.x; i < total; i += (long long)gridDim.x*256LL) {
        int d = (int)(i % Dd);
        long long t = i / Dd;
        int p = (int)(t % (Ll+4));
        int b = (int)(t / (Ll+4));
        float v = 0.f;
        if (p >= 2 && p < Ll+2)
            v = x[((long long)b*Ll + (p-2))*Dd + d];
        __half h, l; split2(v, h, l);
        g_xph[i] = h; g_xpl[i] = l;
    }
}

__global__ void tdc_split(const float* __restrict__ W)
{
    const long long total = 3LL*Dd*Dd;
    for (long long idx = blockIdx.x*256LL + threadIdx.x; idx < total; idx += (long long)gridDim.x*256LL) {
        int tap = (int)(idx / (Dd*(long long)Dd));
        long long rem = idx % (Dd*(long long)Dd);
        int o = (int)(rem / Dd), i = (int)(rem % Dd);
        g_wdcth[idx] = __float2half_rn(W[((long long)o*Dd + i)*3 + tap]);
    }
}

__global__ void tdec_split(const float* __restrict__ W)
{
    const long long total = 6LL*Dd*Dd;
    for (long long idx = blockIdx.x*256LL + threadIdx.x; idx < total; idx += (long long)gridDim.x*256LL) {
        int st = (int)(idx / (Dd*(long long)Dd));
        int s = st >> 1, tap = st & 1;
        long long rem = idx % (Dd*(long long)Dd);
        int o = (int)(rem / Dd), i = (int)(rem % Dd);
        g_wdecth[idx] = __float2half_rn(W[(((long long)s*Dd + o)*Dd + i)*2 + tap]);
    }
}

// W[bz via inStride][K][N] -> out (hi only) at bz*outSegStride + outOff + n*K + k
__global__ void transpose_split(const float* __restrict__ W,
                                __half* __restrict__ oh,
                                int K, int N, long long inStride,
                                long long outSegStride, long long outOff)
{
    __shared__ float t[32][33];
    int bx = blockIdx.x * 32;
    int by = blockIdx.y * 32;
    long long bz = blockIdx.z;
    const float* Wb = W + bz * inStride;
    int tx = threadIdx.x, ty = threadIdx.y;
    for (int i = ty; i < 32; i += 8)
        t[i][tx] = Wb[(long long)(by + i) * N + bx + tx];
    __syncthreads();
    long long ob = bz * outSegStride + outOff;
    for (int i = ty; i < 32; i += 8) {
        long long oidx = ob + (long long)(bx + i) * K + by + tx;
        oh[oidx] = __float2half_rn(t[tx][i]);
    }
}

__global__ void agg_kernel(const float* __restrict__ logits, float* __restrict__ aux)
{
    float mx = -1e30f;
    for (int s = 0; s < Ss; s++) mx = fmaxf(mx, logits[s]);
    float e[Ss], sum = 0.f;
    for (int s = 0; s < Ss; s++) { e[s] = expf(logits[s] - mx); sum += e[s]; }
    float ent = 0.f;
    for (int s = 0; s < Ss; s++) {
        float w = e[s] / sum;
        g_w[s] = w;
        ent -= w * logf(w + 1e-9f);
    }
    if (aux) *aux = ent;
}

__global__ void fill0_kernel(float* p, long long n)
{
    for (long long i = blockIdx.x*256LL + threadIdx.x; i < n; i += (long long)gridDim.x*256LL)
        p[i] = 0.f;
}

// ================= launch =================
extern "C" void kernel_launch(void* const* d_in, const int* in_sizes, int n_in,
                              void* d_out, int out_size)
{
    const float* x     = (const float*)d_in[0];
    const float* W_dc  = (const float*)d_in[1];
    const float* b_dc  = (const float*)d_in[2];
    const float* W_dec = (const float*)d_in[3];
    const float* Wq    = (const float*)d_in[4];
    const float* Wk    = (const float*)d_in[5];
    const float* Wv    = (const float*)d_in[6];
    const float* Wo    = (const float*)d_in[7];
    const float* aggl  = (const float*)d_in[8];
    const float* g1    = (const float*)d_in[9];
    const float* be1   = (const float*)d_in[10];
    const float* g2    = (const float*)d_in[11];
    const float* be2   = (const float*)d_in[12];
    const float* W1    = (const float*)d_in[13];
    const float* b1    = (const float*)d_in[14];
    const float* W2    = (const float*)d_in[15];
    const float* b2    = (const float*)d_in[16];
    float* out = (float*)d_out;

    static int smem_set = 0;
    const int GEMM_SMEM = 2 * 49152;   // 96KB
    const int ATTN_SMEM = 65536;       // 64KB -> 2 CTAs/SM
    if (!smem_set) {
        cudaFuncSetAttribute(gemmM, cudaFuncAttributeMaxDynamicSharedMemorySize, GEMM_SMEM);
        cudaFuncSetAttribute(attnF, cudaFuncAttributeMaxDynamicSharedMemorySize, ATTN_SMEM);
        smem_set = 1;
    }

#define SYM(v, s) cudaGetSymbolAddress((void**)&v, s)
    __half *xph,*xpl,*sah,*sal,*q4h,*q4l,*kvh,*ctxh,*ctxl,*x1h,*x1l,*ffnh,*ffnl;
    __half *wdcth,*wdecth,*wqth,*wkvth,*woth,*w1th,*w2th;
    float *x1,*tmp,*gw;
    SYM(xph,g_xph); SYM(xpl,g_xpl); SYM(sah,g_sah); SYM(sal,g_sal);
    SYM(q4h,g_q4h); SYM(q4l,g_q4l); SYM(kvh,g_kvh);
    SYM(ctxh,g_ctxh); SYM(ctxl,g_ctxl); SYM(x1h,g_x1h); SYM(x1l,g_x1l); SYM(ffnh,g_ffnh); SYM(ffnl,g_ffnl);
    SYM(wdcth,g_wdcth); SYM(wdecth,g_wdecth);
    SYM(wqth,g_wqth); SYM(wkvth,g_wkvth);
    SYM(woth,g_woth);
    SYM(w1th,g_w1th); SYM(w2th,g_w2th);
    SYM(x1,g_x1); SYM(tmp,g_tmp); SYM(gw,g_w);
#undef SYM

    const int BLD = Bb*Ll*Dd;
    const int4 NOSEG = make_int4(0x7fffffff, 0x7fffffff, 0x7fffffff, 0);

    // ---- preprocessing ----
    tdc_split <<<1024, 256>>>(W_dc);
    tdec_split<<<2048, 256>>>(W_dec);
    {
        dim3 blk(32, 8);
        transpose_split<<<dim3(Dd/32, Dd/32, 4), blk>>>(Wq, wqth, Dd, Dd, DDc, DDc, 0);
        transpose_split<<<dim3(Dd/32, Dd/32, 4), blk>>>(Wk, wkvth, Dd, Dd, DDc, 2*DDc, 0);
        transpose_split<<<dim3(Dd/32, Dd/32, 4), blk>>>(Wv, wkvth, Dd, Dd, 0,   2*DDc, DDc);
        transpose_split<<<dim3(Dd/32, Dd/32, 1), blk>>>(Wo, woth, Dd, Dd, DDc, DDc, 0);
        transpose_split<<<dim3(Ff/32, Dd/32, 1), blk>>>(W1, w1th, Dd, Ff, (long long)Dd*Ff, (long long)Dd*Ff, 0);
        transpose_split<<<dim3(Dd/32, Ff/32, 1), blk>>>(W2, w2th, Ff, Dd, (long long)Dd*Ff, (long long)Dd*Ff, 0);
    }
    pad_split_kernel<<<4096, 256>>>(x);
    if (out_size > BLD) {
        long long gap = (long long)out_size - BLD;
        fill0_kernel<<<256, 256>>>(out + BLD, gap);
        agg_kernel<<<1, 1>>>(aggl, out + out_size - 1);
    } else {
        agg_kernel<<<1, 1>>>(aggl, (float*)0);
    }

    auto gemm = [&](const __half* Ah, const __half* Al, const __half* Bh,
                    float* Cf, __half* Oh, __half* Ol, const float* bias,
                    int M, int N, int K, int taps, long long tapStrideA,
                    int lseg, long long segStride, int rowStride, long long offA, int epi,
                    int4 segEnd, long long segUnit) {
        dim3 g(N/128, M/128);
        gemmM<<<g, 256, GEMM_SMEM>>>(Ah, Al, Bh, Cf, Oh, Ol, bias,
                                     N, K, taps, tapStrideA, lseg, segStride, rowStride, offA, epi,
                                     segEnd, segUnit);
    };

    // 1. dilated conv (k=3, dil=2) + bias + ReLU -> sa rows [0,4096)
    gemm(xph, xpl, wdcth, 0, sah, sal, b_dc,
         Bb*Ll, Dd, Dd, 3, 2LL*Dd, Ll, (long long)(Ll+4)*Dd, Dd, 0, 1, NOSEG, 0);

    // 2. hierarchical decomposition (stride-2, k=2) into sa rows [4096,7680)
    {
        const long long inOff[3]  = {0, 4096, 6144};
        const long long outOff[3] = {4096, 6144, 7168};
        int Lin[3] = {1024, 512, 256};
        for (int s = 0; s < 3; s++)
            gemm(sah + inOff[s]*Dd, sal + inOff[s]*Dd,
                 wdecth + (long long)s*2*DDc,
                 0, sah + outOff[s]*Dd, sal + outOff[s]*Dd, 0,
                 Bb*(Lin[s]/2), Dd, Dd, 2, (long long)Dd,
                 Lin[s]/2, (long long)Lin[s]*Dd, 2*Dd, 0, 0, NOSEG, 0);
    }

    // 3a. merged Q projection: q4 = xc @ [Wq0|Wq1|Wq2|Wq3]  (hi+lo out)
    gemm(sah, sal, wqth, 0, q4h, q4l, 0,
         Bb*Ll, 4*Dd, Dd, 1, 0, Bb*Ll, 0, Dd, 0, 0, NOSEG, 0);

    // 3b. merged K|V projection over all scales (segmented B): kv[7680][2048], hi only
    gemm(sah, sal, wkvth, 0, kvh, (__half*)0, 0,
         SAR, 2048, Dd, 1, 0, SAR, 0, Dd, 0, 0,
         make_int4(4096, 6144, 7168, 0), 2*DDc);

    // 3c. fused 4-scale attention -> split fp16 ctx
    {
        dim3 ag(Ll/64, Hh, Bb);
        attnF<<<ag, 128, ATTN_SMEM>>>(q4h, q4l, kvh, ctxh, ctxl, gw);
    }

    // 4. output projection Wo -> tmp fp32
    gemm(ctxh, ctxl, woth, tmp, 0, 0, 0, Bb*Ll, Dd, Dd, 1, 0, Bb*Ll, 0, Dd, 0, 0, NOSEG, 0);

    // 5. residual + LN1 (fp32 + split)
    ln_kernel<<<Bb*Ll, 256>>>(x, tmp, g1, be1, x1, x1h, x1l);

    // 6. FFN (GELU fused, split intermediate)
    gemm(x1h, x1l, w1th, 0, ffnh, ffnl, b1, Bb*Ll, Ff, Dd, 1, 0, Bb*Ll, 0, Dd, 0, 2, NOSEG, 0);
    gemm(ffnh, ffnl, w2th, tmp, 0, 0, b2, Bb*Ll, Dd, Ff, 1, 0, Bb*Ll, 0, Ff, 0, 0, NOSEG, 0);

    // 7. residual + LN2 -> out
    ln_kernel<<<Bb*Ll, 256>>>(x1, tmp, g2, be2, out, (__half*)0, (__half*)0);
}

// round 7
// speedup vs baseline: 5.7558x; 1.6414x over previous
#include <cuda_runtime.h>
#include <cuda_fp16.h>
#include <math.h>
#include <stdint.h>

#define Bb 4
#define Ll 1024
#define Dd 1024
#define Hh 16
#define Ff 4096
#define Ss 4
#define DDc (1024LL*1024LL)
#define SAR 7680   // total scale-activation rows: 4096+2048+1024+512

// ================= static scratch (no allocations) =================
__device__ __align__(256) __half g_xph[Bb*(Ll+4)*Dd];
__device__ __align__(256) __half g_sah[SAR*Dd];                    // xc|s1|s2|s3
__device__ __align__(256) __half g_q4h[Bb*Ll*4*Dd];                // [4096][4096]
__device__ __align__(256) __half g_kvh[SAR*2048];                  // [7680][2048] K|V
__device__ __align__(256) __half g_ctxh[Bb*Ll*Dd];
__device__ __align__(256) __half g_x1h[Bb*Ll*Dd];
__device__ __align__(256) __half g_ffnh[Bb*Ll*Ff];
__device__ __align__(256) __half g_wdcth[3*1024*1024];
__device__ __align__(256) __half g_wdecth[6*1024*1024];
__device__ __align__(256) __half g_wqth[4*1024*1024];
__device__ __align__(256) __half g_wkvth[4*2048*1024];
__device__ __align__(256) __half g_woth[1024*1024];
__device__ __align__(256) __half g_w1th[1024*4096];
__device__ __align__(256) __half g_w2th[4096*1024];
__device__ __align__(256) float g_x1[Bb*Ll*Dd];
__device__ __align__(256) float g_tmp[Bb*Ll*Dd];
__device__ float g_w[Ss];

// ================= PTX helpers (base features only) =================
#define CP16(dst, src)    asm volatile("cp.async.cg.shared.global [%0], [%1], 16;" :: "r"(dst), "l"(src) : "memory")
#define CP_COMMIT()       asm volatile("cp.async.commit_group;" ::: "memory")
#define CP_WAIT1()        asm volatile("cp.async.wait_group 1;" ::: "memory")
#define CP_WAIT0()        asm volatile("cp.async.wait_group 0;" ::: "memory")

#define LDSM4(r0,r1,r2,r3,addr) \
    asm volatile("ldmatrix.sync.aligned.m8n8.x4.shared.b16 {%0,%1,%2,%3}, [%4];" \
        : "=r"(r0),"=r"(r1),"=r"(r2),"=r"(r3) : "r"(addr))
#define LDSM4T(r0,r1,r2,r3,addr) \
    asm volatile("ldmatrix.sync.aligned.m8n8.x4.trans.shared.b16 {%0,%1,%2,%3}, [%4];" \
        : "=r"(r0),"=r"(r1),"=r"(r2),"=r"(r3) : "r"(addr))
#define LDSM2(r0,r1,addr) \
    asm volatile("ldmatrix.sync.aligned.m8n8.x2.shared.b16 {%0,%1}, [%2];" \
        : "=r"(r0),"=r"(r1) : "r"(addr))
#define MMA16816(d, a, b) \
    asm volatile("mma.sync.aligned.m16n8k16.row.col.f32.f16.f16.f32 " \
        "{%0,%1,%2,%3}, {%4,%5,%6,%7}, {%8,%9}, {%0,%1,%2,%3};" \
        : "+f"((d)[0]),"+f"((d)[1]),"+f"((d)[2]),"+f"((d)[3]) \
        : "r"((a)[0]),"r"((a)[1]),"r"((a)[2]),"r"((a)[3]), "r"((b)[0]),"r"((b)[1]))

__device__ __forceinline__ uint32_t smem_u32(const void* p) {
    uint32_t a;
    asm("{ .reg .u64 t; cvta.to.shared.u64 t, %1; cvt.u32.u64 %0, t; }" : "=r"(a) : "l"(p));
    return a;
}

__device__ __forceinline__ uint32_t pack2h(float a, float b) {
    __half2 h2 = __floats2half2_rn(a, b);
    return *(uint32_t*)&h2;
}

__device__ __forceinline__ uint32_t packsplit(float a, float b, uint32_t& lo) {
    __half ha = __float2half_rn(a), hb = __float2half_rn(b);
    __half la = __float2half_rn(a - __half2float(ha));
    __half lb = __float2half_rn(b - __half2float(hb));
    lo = ((uint32_t)__half_as_ushort(lb) << 16) | __half_as_ushort(la);
    return ((uint32_t)__half_as_ushort(hb) << 16) | __half_as_ushort(ha);
}

// ================= mma.sync pure-fp16 GEMM (seg-selectable B) =================
__global__ __launch_bounds__(256, 2) void gemmM(
    const __half* __restrict__ Ah, const __half* __restrict__ Bh,
    float* __restrict__ Cf, __half* __restrict__ Oh,
    const float* __restrict__ bias,
    int N, int K, int taps, long long tapStrideA,
    int lseg, long long segStride, int rowStride, long long offA, int epi,
    int4 segEnd, long long segUnit)
{
    extern __shared__ char smem[];
    uint32_t sb = smem_u32(smem);
    const int tid = threadIdx.x;
    const int wid = tid >> 5, lane = tid & 31;
    const int m0 = blockIdx.y * 128, n0 = blockIdx.x * 128;

    {
        int sidx = (m0 >= segEnd.x) + (m0 >= segEnd.y) + (m0 >= segEnd.z);
        Bh += (long long)sidx * segUnit;
    }

    const int r = tid >> 1, half_ = tid & 1;
    const long long mrow = m0 + r;
    const long long aoff0 = (mrow / lseg) * segStride + (mrow % lseg) * (long long)rowStride + offA + half_ * 32;
    const long long boff0 = (long long)(n0 + r) * K + half_ * 32;
    uint32_t dstOff[4];
#pragma unroll
    for (int j = 0; j < 4; j++) {
        uint32_t off = (uint32_t)(r * 128 + half_ * 64 + j * 16);
        dstOff[j] = off ^ ((off >> 3) & 0x70);
    }
    const uint32_t bufBase[2] = { sb, sb + 32768 };
    const int NCk = K >> 6;
    const int NC = NCk * taps;
    const long long tapStrideB = (long long)N * K;

    const int wm = wid & 1, wn = wid >> 1;
    const int arow = wm * 64 + (lane & 15);
    const uint32_t aRowOff = (uint32_t)(arow * 128);
    const uint32_t aXb = (uint32_t)((arow & 7) << 4);
    const uint32_t aHalf = (uint32_t)((lane >> 4) * 16);
    const uint32_t bRowOff = (uint32_t)((wn * 32 + (lane & 7)) * 128);
    const uint32_t bXb = (uint32_t)((lane & 7) << 4);
    const uint32_t bHalf = (uint32_t)(((lane >> 3) & 1) * 16);

    float acc[4][4][4];
#pragma unroll
    for (int i = 0; i < 4; i++)
#pragma unroll
        for (int j = 0; j < 4; j++)
#pragma unroll
            for (int e = 0; e < 4; e++) acc[i][j][e] = 0.f;

#pragma unroll 1
    for (int c = 0; c < 2 && c < NC; c++) {
        int tap = c / NCk, kc = c % NCk;
        long long ao = aoff0 + (long long)tap * tapStrideA + kc * 64;
        long long bo = boff0 + (long long)tap * tapStrideB + kc * 64;
        uint32_t bs = bufBase[c & 1];
#pragma unroll
        for (int j = 0; j < 4; j++) {
            CP16(bs +         dstOff[j], Ah + ao + j * 8);
            CP16(bs + 16384 + dstOff[j], Bh + bo + j * 8);
        }
        CP_COMMIT();
    }

#pragma unroll 1
    for (int c = 0; c < NC; c++) {
        const int buf = c & 1;
        if (c == NC - 1) CP_WAIT0(); else CP_WAIT1();
        __syncthreads();

        const uint32_t bs = bufBase[buf];
#pragma unroll
        for (int k16 = 0; k16 < 4; k16++) {
            const uint32_t aoff = aRowOff + ((k16 * 32 + aHalf) ^ aXb);
            const uint32_t boff = bRowOff + ((k16 * 32 + bHalf) ^ bXb);
            uint32_t ah[4][4], bh[4][2];
#pragma unroll
            for (int i = 0; i < 4; i++) {
                LDSM4(ah[i][0], ah[i][1], ah[i][2], ah[i][3], bs + i * 2048 + aoff);
            }
#pragma unroll
            for (int j = 0; j < 4; j++) {
                LDSM2(bh[j][0], bh[j][1], bs + 16384 + j * 1024 + boff);
            }
#pragma unroll
            for (int i = 0; i < 4; i++)
#pragma unroll
                for (int j = 0; j < 4; j++) {
                    MMA16816(acc[i][j], ah[i], bh[j]);
                }
        }
        __syncthreads();

        if (c + 2 < NC) {
            int cc = c + 2;
            int tap = cc / NCk, kc = cc % NCk;
            long long ao = aoff0 + (long long)tap * tapStrideA + kc * 64;
            long long bo = boff0 + (long long)tap * tapStrideB + kc * 64;
#pragma unroll
            for (int j = 0; j < 4; j++) {
                CP16(bs +         dstOff[j], Ah + ao + j * 8);
                CP16(bs + 16384 + dstOff[j], Bh + bo + j * 8);
            }
            CP_COMMIT();
        }
    }

#pragma unroll
    for (int i = 0; i < 4; i++)
#pragma unroll
        for (int j = 0; j < 4; j++)
#pragma unroll
            for (int p = 0; p < 2; p++) {
                int rr = m0 + wm * 64 + i * 16 + (lane >> 2) + p * 8;
                int cc = n0 + wn * 32 + j * 8 + (lane & 3) * 2;
                float v0 = acc[i][j][p * 2];
                float v1 = acc[i][j][p * 2 + 1];
                if (bias) { v0 += bias[cc]; v1 += bias[cc + 1]; }
                if (epi == 1) { v0 = fmaxf(v0, 0.f); v1 = fmaxf(v1, 0.f); }
                else if (epi == 2) {
                    v0 = 0.5f * v0 * (1.f + erff(v0 * 0.70710678118654752f));
                    v1 = 0.5f * v1 * (1.f + erff(v1 * 0.70710678118654752f));
                }
                long long idx = (long long)rr * N + cc;
                if (Cf) { float2 f; f.x = v0; f.y = v1; *(float2*)(Cf + idx) = f; }
                if (Oh) *(uint32_t*)(Oh + idx) = pack2h(v0, v1);
            }
}

// ================= fused 4-scale tensor-core flash attention (fp16; P split) =================
__global__ __launch_bounds__(128, 2) void attnF(
    const __half* __restrict__ Qh4, const __half* __restrict__ KVh,
    __half* __restrict__ Oh, const float* __restrict__ gw)
{
    extern __shared__ char smem[];
    uint32_t sb = smem_u32(smem);
    const int tid = threadIdx.x;
    const int w = tid >> 5, lane = tid & 31;
    const int b = blockIdx.z, h = blockIdx.y;
    const int q0 = blockIdx.x * 64;

    float w4[4];
#pragma unroll
    for (int s = 0; s < 4; s++) w4[s] = gw[s];

    const int r = tid >> 1, half_ = tid & 1;
    uint32_t dstOff[4];
#pragma unroll
    for (int j = 0; j < 4; j++) {
        uint32_t off = (uint32_t)(r * 128 + half_ * 64 + j * 16);
        dstOff[j] = off ^ ((off >> 3) & 0x70);
    }
    // smem: Q bufs 2x8KB, KV bufs 2x16KB (Kh 0 / Vh 8192)
    const uint32_t sQb[2] = { sb, sb + 8192 };
    const uint32_t kvb[2] = { sb + 16384, sb + 32768 };

    const long long qrowbase = ((long long)(b * Ll + q0 + r)) * 4096 + h * 64 + half_ * 32;

    auto kvRow = [&](int cc) -> long long {
        int s2  = (cc < 16) ? 0 : (cc < 24) ? 1 : (cc < 28) ? 2 : 3;
        int bas = (s2 == 0) ? 0 : (s2 == 1) ? 16 : (s2 == 2) ? 24 : 28;
        int Ls2 = (s2 == 0) ? 1024 : (s2 == 1) ? 512 : (s2 == 2) ? 256 : 128;
        int ro2 = (s2 == 0) ? 0 : (s2 == 1) ? 4096 : (s2 == 2) ? 6144 : 7168;
        int kc2 = cc - bas;
        return ((long long)(ro2 + b * Ls2 + kc2 * 64 + r)) * 2048 + h * 64 + half_ * 32;
    };

    // prologue
    {
#pragma unroll
        for (int j = 0; j < 4; j++)
            CP16(sQb[0] + dstOff[j], Qh4 + qrowbase + j * 8);
        long long kr = kvRow(0);
#pragma unroll
        for (int j = 0; j < 4; j++) {
            CP16(kvb[0]        + dstOff[j], KVh + kr + j * 8);
            CP16(kvb[0] + 8192 + dstOff[j], KVh + kr + 1024 + j * 8);
        }
        CP_COMMIT();
        kr = kvRow(1);
#pragma unroll
        for (int j = 0; j < 4; j++) {
            CP16(kvb[1]        + dstOff[j], KVh + kr + j * 8);
            CP16(kvb[1] + 8192 + dstOff[j], KVh + kr + 1024 + j * 8);
        }
        CP_COMMIT();
    }

    const uint32_t qoffBase = (uint32_t)((w * 16 + (lane & 15)) * 128 + ((lane >> 4) & 1) * 16);
    const uint32_t krowb = (uint32_t)((lane & 7) + ((lane >> 4) & 1) * 8);
    const uint32_t kbyteb = (uint32_t)(((lane >> 3) & 1) * 16);
    const uint32_t vrowb = (uint32_t)((lane & 7) + ((lane >> 3) & 1) * 8);
    const uint32_t vbyteb = (uint32_t)(((lane >> 4) & 1) * 16);

    uint32_t qah[4][4];
    float oacc[8][4];
#pragma unroll
    for (int t = 0; t < 8; t++)
#pragma unroll
        for (int e = 0; e < 4; e++) oacc[t][e] = 0.f;
    float o[8][4];
    float m0v = -1e30f, m1v = -1e30f, l0 = 0.f, l1 = 0.f;

#pragma unroll 1
    for (int c = 0; c < 30; c++) {
        const int s  = (c < 16) ? 0 : (c < 24) ? 1 : (c < 28) ? 2 : 3;
        const int bas = (s == 0) ? 0 : (s == 1) ? 16 : (s == 2) ? 24 : 28;
        const int nch = (s == 0) ? 16 : (s == 1) ? 8 : (s == 2) ? 4 : 2;
        const int kc = c - bas;

        if (c == 29) CP_WAIT0(); else CP_WAIT1();
        __syncthreads();

        if (kc == 0) {
            uint32_t qb = sQb[s & 1];
#pragma unroll
            for (int k16 = 0; k16 < 4; k16++) {
                uint32_t off = qoffBase + k16 * 32;
                off ^= (off >> 3) & 0x70;
                LDSM4(qah[k16][0], qah[k16][1], qah[k16][2], qah[k16][3], qb + off);
            }
            m0v = -1e30f; m1v = -1e30f; l0 = 0.f; l1 = 0.f;
#pragma unroll
            for (int t = 0; t < 8; t++)
#pragma unroll
                for (int e = 0; e < 4; e++) o[t][e] = 0.f;
        }

        const uint32_t bs = kvb[c & 1];
        // ---- S = Q K^T ----
        float sc[8][4];
#pragma unroll
        for (int t = 0; t < 8; t++)
#pragma unroll
            for (int e = 0; e < 4; e++) sc[t][e] = 0.f;
#pragma unroll
        for (int k16 = 0; k16 < 4; k16++) {
            uint32_t kh[8][2];
#pragma unroll
            for (int t4 = 0; t4 < 4; t4++) {
                uint32_t off = (t4 * 16 + krowb) * 128 + k16 * 32 + kbyteb;
                off ^= (off >> 3) & 0x70;
                LDSM4(kh[2*t4][0], kh[2*t4][1], kh[2*t4+1][0], kh[2*t4+1][1], bs + off);
            }
#pragma unroll
            for (int j = 0; j < 8; j++)
                MMA16816(sc[j], qah[k16], kh[j]);
        }

        // ---- online softmax ----
        float rmax0 = -1e30f, rmax1 = -1e30f;
#pragma unroll
        for (int t = 0; t < 8; t++) {
            sc[t][0] *= 0.125f; sc[t][1] *= 0.125f; sc[t][2] *= 0.125f; sc[t][3] *= 0.125f;
            rmax0 = fmaxf(rmax0, fmaxf(sc[t][0], sc[t][1]));
            rmax1 = fmaxf(rmax1, fmaxf(sc[t][2], sc[t][3]));
        }
        rmax0 = fmaxf(rmax0, __shfl_xor_sync(0xffffffffu, rmax0, 1));
        rmax0 = fmaxf(rmax0, __shfl_xor_sync(0xffffffffu, rmax0, 2));
        rmax1 = fmaxf(rmax1, __shfl_xor_sync(0xffffffffu, rmax1, 1));
        rmax1 = fmaxf(rmax1, __shfl_xor_sync(0xffffffffu, rmax1, 2));
        float mn0 = fmaxf(m0v, rmax0), mn1 = fmaxf(m1v, rmax1);
        float fac0 = __expf(m0v - mn0), fac1 = __expf(m1v - mn1);
        float rs0 = 0.f, rs1 = 0.f;
#pragma unroll
        for (int t = 0; t < 8; t++) {
            sc[t][0] = __expf(sc[t][0] - mn0); sc[t][1] = __expf(sc[t][1] - mn0);
            sc[t][2] = __expf(sc[t][2] - mn1); sc[t][3] = __expf(sc[t][3] - mn1);
            rs0 += sc[t][0] + sc[t][1];
            rs1 += sc[t][2] + sc[t][3];
        }
        rs0 += __shfl_xor_sync(0xffffffffu, rs0, 1);
        rs0 += __shfl_xor_sync(0xffffffffu, rs0, 2);
        rs1 += __shfl_xor_sync(0xffffffffu, rs1, 1);
        rs1 += __shfl_xor_sync(0xffffffffu, rs1, 2);
        l0 = l0 * fac0 + rs0; l1 = l1 * fac1 + rs1;
        m0v = mn0; m1v = mn1;
#pragma unroll
        for (int t = 0; t < 8; t++) {
            o[t][0] *= fac0; o[t][1] *= fac0; o[t][2] *= fac1; o[t][3] *= fac1;
        }

        // ---- O += P V (P split hi+lo) ----
#pragma unroll
        for (int k16 = 0; k16 < 4; k16++) {
            uint32_t ph[4], pl[4];
            int t = 2 * k16;
            ph[0] = packsplit(sc[t][0],   sc[t][1],   pl[0]);
            ph[1] = packsplit(sc[t][2],   sc[t][3],   pl[1]);
            ph[2] = packsplit(sc[t+1][0], sc[t+1][1], pl[2]);
            ph[3] = packsplit(sc[t+1][2], sc[t+1][3], pl[3]);
            uint32_t vh[8][2];
#pragma unroll
            for (int t4 = 0; t4 < 4; t4++) {
                uint32_t off = (k16 * 16 + vrowb) * 128 + t4 * 32 + vbyteb;
                off ^= (off >> 3) & 0x70;
                LDSM4T(vh[2*t4][0], vh[2*t4][1], vh[2*t4+1][0], vh[2*t4+1][1], bs + 8192 + off);
            }
#pragma unroll
            for (int t8 = 0; t8 < 8; t8++) {
                MMA16816(o[t8], ph, vh[t8]);
                MMA16816(o[t8], pl, vh[t8]);
            }
        }
        __syncthreads();

        // ---- prefetch chunk c+2 (+ next-scale Q at scale start) ----
        {
            bool doCommit = false;
            int cc = c + 2;
            if (cc < 30) {
                long long kr = kvRow(cc);
                uint32_t bs2 = kvb[c & 1];
#pragma unroll
                for (int j = 0; j < 4; j++) {
                    CP16(bs2        + dstOff[j], KVh + kr + j * 8);
                    CP16(bs2 + 8192 + dstOff[j], KVh + kr + 1024 + j * 8);
                }
                doCommit = true;
            }
            if (kc == 0 && s < 3) {
                uint32_t qb2 = sQb[(s + 1) & 1];
                long long qsrc = qrowbase + (long long)(s + 1) * 1024;
#pragma unroll
                for (int j = 0; j < 4; j++)
                    CP16(qb2 + dstOff[j], Qh4 + qsrc + j * 8);
                doCommit = true;
            }
            if (doCommit) CP_COMMIT();
        }

        // ---- finalize scale ----
        if (kc == nch - 1) {
            float ws = w4[s];
            float inv0 = ws / l0, inv1 = ws / l1;
#pragma unroll
            for (int t = 0; t < 8; t++) {
                oacc[t][0] += o[t][0] * inv0;
                oacc[t][1] += o[t][1] * inv0;
                oacc[t][2] += o[t][2] * inv1;
                oacc[t][3] += o[t][3] * inv1;
            }
        }
    }

    // ---- write fp16 ctx ----
    int g = lane >> 2;
    int qrow0 = q0 + w * 16 + g;
    long long base0 = ((long long)(b * Ll + qrow0)) * Dd + h * 64;
    long long base1 = base0 + 8LL * Dd;
#pragma unroll
    for (int t = 0; t < 8; t++) {
        int d0 = t * 8 + (lane & 3) * 2;
        *(uint32_t*)(Oh + base0 + d0) = pack2h(oacc[t][0], oacc[t][1]);
        *(uint32_t*)(Oh + base1 + d0) = pack2h(oacc[t][2], oacc[t][3]);
    }
}

// ================= LayerNorm: out = LN(a + r), optional fp16 =================
__global__ __launch_bounds__(256) void ln_kernel(
    const float* __restrict__ a, const float* __restrict__ rr,
    const float* __restrict__ gamma, const float* __restrict__ beta,
    float* __restrict__ out, __half* __restrict__ oh)
{
    __shared__ float red[8], red2[8];
    __shared__ float smu, sinv;
    int row = blockIdx.x, tid = threadIdx.x;
    long long base = (long long)row * Dd;
    float4 va = ((const float4*)(a + base))[tid];
    float4 vr = ((const float4*)(rr + base))[tid];
    float x0 = va.x+vr.x, x1 = va.y+vr.y, x2 = va.z+vr.z, x3 = va.w+vr.w;
    float s  = x0+x1+x2+x3;
    float s2 = x0*x0 + x1*x1 + x2*x2 + x3*x3;
#pragma unroll
    for (int off = 16; off >= 1; off >>= 1) {
        s  += __shfl_xor_sync(0xffffffffu, s,  off);
        s2 += __shfl_xor_sync(0xffffffffu, s2, off);
    }
    int w = tid >> 5, lane = tid & 31;
    if (lane == 0) { red[w] = s; red2[w] = s2; }
    __syncthreads();
    if (tid == 0) {
        float S = 0.f, S2 = 0.f;
        for (int i = 0; i < 8; i++) { S += red[i]; S2 += red2[i]; }
        float mu = S * (1.f/Dd);
        smu = mu;
        sinv = rsqrtf(S2 * (1.f/Dd) - mu*mu + 1e-5f);
    }
    __syncthreads();
    float mu = smu, inv = sinv;
    float4 gg = ((const float4*)gamma)[tid];
    float4 bb = ((const float4*)beta)[tid];
    float y0 = (x0-mu)*inv*gg.x + bb.x;
    float y1 = (x1-mu)*inv*gg.y + bb.y;
    float y2 = (x2-mu)*inv*gg.z + bb.z;
    float y3 = (x3-mu)*inv*gg.w + bb.w;
    float4 y; y.x=y0; y.y=y1; y.z=y2; y.w=y3;
    ((float4*)(out + base))[tid] = y;
    if (oh) {
        ((uint32_t*)(oh + base))[tid*2]   = pack2h(y0, y1);
        ((uint32_t*)(oh + base))[tid*2+1] = pack2h(y2, y3);
    }
}

// ================= preprocessing kernels =================
__global__ void pad_split_kernel(const float* __restrict__ x)
{
    const long long total = (long long)Bb*(Ll+4)*Dd;
    for (long long i = blockIdx.x*256LL + threadIdx.x; i < total; i += (long long)gridDim.x*256LL) {
        int d = (int)(i % Dd);
        long long t = i / Dd;
        int p = (int)(t % (Ll+4));
        int b = (int)(t / (Ll+4));
        float v = 0.f;
        if (p >= 2 && p < Ll+2)
            v = x[((long long)b*Ll + (p-2))*Dd + d];
        g_xph[i] = __float2half_rn(v);
    }
}

__global__ void tdc_split(const float* __restrict__ W)
{
    const long long total = 3LL*Dd*Dd;
    for (long long idx = blockIdx.x*256LL + threadIdx.x; idx < total; idx += (long long)gridDim.x*256LL) {
        int tap = (int)(idx / (Dd*(long long)Dd));
        long long rem = idx % (Dd*(long long)Dd);
        int o = (int)(rem / Dd), i = (int)(rem % Dd);
        g_wdcth[idx] = __float2half_rn(W[((long long)o*Dd + i)*3 + tap]);
    }
}

__global__ void tdec_split(const float* __restrict__ W)
{
    const long long total = 6LL*Dd*Dd;
    for (long long idx = blockIdx.x*256LL + threadIdx.x; idx < total; idx += (long long)gridDim.x*256LL) {
        int st = (int)(idx / (Dd*(long long)Dd));
        int s = st >> 1, tap = st & 1;
        long long rem = idx % (Dd*(long long)Dd);
        int o = (int)(rem / Dd), i = (int)(rem % Dd);
        g_wdecth[idx] = __float2half_rn(W[(((long long)s*Dd + o)*Dd + i)*2 + tap]);
    }
}

// W[bz via inStride][K][N] -> out at bz*outSegStride + outOff + n*K + k
__global__ void transpose_split(const float* __restrict__ W,
                                __half* __restrict__ oh,
                                int K, int N, long long inStride,
                                long long outSegStride, long long outOff)
{
    __shared__ float t[32][33];
    int bx = blockIdx.x * 32;
    int by = blockIdx.y * 32;
    long long bz = blockIdx.z;
    const float* Wb = W + bz * inStride;
    int tx = threadIdx.x, ty = threadIdx.y;
    for (int i = ty; i < 32; i += 8)
        t[i][tx] = Wb[(long long)(by + i) * N + bx + tx];
    __syncthreads();
    long long ob = bz * outSegStride + outOff;
    for (int i = ty; i < 32; i += 8) {
        long long oidx = ob + (long long)(bx + i) * K + by + tx;
        oh[oidx] = __float2half_rn(t[tx][i]);
    }
}

__global__ void agg_kernel(const float* __restrict__ logits, float* __restrict__ aux)
{
    float mx = -1e30f;
    for (int s = 0; s < Ss; s++) mx = fmaxf(mx, logits[s]);
    float e[Ss], sum = 0.f;
    for (int s = 0; s < Ss; s++) { e[s] = expf(logits[s] - mx); sum += e[s]; }
    float ent = 0.f;
    for (int s = 0; s < Ss; s++) {
        float w = e[s] / sum;
        g_w[s] = w;
        ent -= w * logf(w + 1e-9f);
    }
    if (aux) *aux = ent;
}

__global__ void fill0_kernel(float* p, long long n)
{
    for (long long i = blockIdx.x*256LL + threadIdx.x; i < n; i += (long long)gridDim.x*256LL)
        p[i] = 0.f;
}

// ================= launch =================
extern "C" void kernel_launch(void* const* d_in, const int* in_sizes, int n_in,
                              void* d_out, int out_size)
{
    const float* x     = (const float*)d_in[0];
    const float* W_dc  = (const float*)d_in[1];
    const float* b_dc  = (const float*)d_in[2];
    const float* W_dec = (const float*)d_in[3];
    const float* Wq    = (const float*)d_in[4];
    const float* Wk    = (const float*)d_in[5];
    const float* Wv    = (const float*)d_in[6];
    const float* Wo    = (const float*)d_in[7];
    const float* aggl  = (const float*)d_in[8];
    const float* g1    = (const float*)d_in[9];
    const float* be1   = (const float*)d_in[10];
    const float* g2    = (const float*)d_in[11];
    const float* be2   = (const float*)d_in[12];
    const float* W1    = (const float*)d_in[13];
    const float* b1    = (const float*)d_in[14];
    const float* W2    = (const float*)d_in[15];
    const float* b2    = (const float*)d_in[16];
    float* out = (float*)d_out;

    static int smem_set = 0;
    const int GEMM_SMEM = 2 * 32768;   // 64KB -> 2 CTAs/SM
    const int ATTN_SMEM = 49152;       // 48KB -> 2 CTAs/SM
    if (!smem_set) {
        cudaFuncSetAttribute(gemmM, cudaFuncAttributeMaxDynamicSharedMemorySize, GEMM_SMEM);
        cudaFuncSetAttribute(attnF, cudaFuncAttributeMaxDynamicSharedMemorySize, ATTN_SMEM);
        smem_set = 1;
    }

#define SYM(v, s) cudaGetSymbolAddress((void**)&v, s)
    __half *xph,*sah,*q4h,*kvh,*ctxh,*x1h,*ffnh;
    __half *wdcth,*wdecth,*wqth,*wkvth,*woth,*w1th,*w2th;
    float *x1,*tmp,*gw;
    SYM(xph,g_xph); SYM(sah,g_sah);
    SYM(q4h,g_q4h); SYM(kvh,g_kvh);
    SYM(ctxh,g_ctxh); SYM(x1h,g_x1h); SYM(ffnh,g_ffnh);
    SYM(wdcth,g_wdcth); SYM(wdecth,g_wdecth);
    SYM(wqth,g_wqth); SYM(wkvth,g_wkvth);
    SYM(woth,g_woth);
    SYM(w1th,g_w1th); SYM(w2th,g_w2th);
    SYM(x1,g_x1); SYM(tmp,g_tmp); SYM(gw,g_w);
#undef SYM

    const int BLD = Bb*Ll*Dd;
    const int4 NOSEG = make_int4(0x7fffffff, 0x7fffffff, 0x7fffffff, 0);

    // ---- preprocessing ----
    tdc_split <<<1024, 256>>>(W_dc);
    tdec_split<<<2048, 256>>>(W_dec);
    {
        dim3 blk(32, 8);
        transpose_split<<<dim3(Dd/32, Dd/32, 4), blk>>>(Wq, wqth, Dd, Dd, DDc, DDc, 0);
        transpose_split<<<dim3(Dd/32, Dd/32, 4), blk>>>(Wk, wkvth, Dd, Dd, DDc, 2*DDc, 0);
        transpose_split<<<dim3(Dd/32, Dd/32, 4), blk>>>(Wv, wkvth, Dd, Dd, 0,   2*DDc, DDc);
        transpose_split<<<dim3(Dd/32, Dd/32, 1), blk>>>(Wo, woth, Dd, Dd, DDc, DDc, 0);
        transpose_split<<<dim3(Ff/32, Dd/32, 1), blk>>>(W1, w1th, Dd, Ff, (long long)Dd*Ff, (long long)Dd*Ff, 0);
        transpose_split<<<dim3(Dd/32, Ff/32, 1), blk>>>(W2, w2th, Ff, Dd, (long long)Dd*Ff, (long long)Dd*Ff, 0);
    }
    pad_split_kernel<<<4096, 256>>>(x);
    if (out_size > BLD) {
        long long gap = (long long)out_size - BLD;
        fill0_kernel<<<256, 256>>>(out + BLD, gap);
        agg_kernel<<<1, 1>>>(aggl, out + out_size - 1);
    } else {
        agg_kernel<<<1, 1>>>(aggl, (float*)0);
    }

    auto gemm = [&](const __half* Ah, const __half* Bh,
                    float* Cf, __half* Oh, const float* bias,
                    int M, int N, int K, int taps, long long tapStrideA,
                    int lseg, long long segStride, int rowStride, long long offA, int epi,
                    int4 segEnd, long long segUnit) {
        dim3 g(N/128, M/128);
        gemmM<<<g, 256, GEMM_SMEM>>>(Ah, Bh, Cf, Oh, bias,
                                     N, K, taps, tapStrideA, lseg, segStride, rowStride, offA, epi,
                                     segEnd, segUnit);
    };

    // 1. dilated conv (k=3, dil=2) + bias + ReLU -> sa rows [0,4096)
    gemm(xph, wdcth, 0, sah, b_dc,
         Bb*Ll, Dd, Dd, 3, 2LL*Dd, Ll, (long long)(Ll+4)*Dd, Dd, 0, 1, NOSEG, 0);

    // 2. hierarchical decomposition (stride-2, k=2) into sa rows [4096,7680)
    {
        const long long inOff[3]  = {0, 4096, 6144};
        const long long outOff[3] = {4096, 6144, 7168};
        int Lin[3] = {1024, 512, 256};
        for (int s = 0; s < 3; s++)
            gemm(sah + inOff[s]*Dd,
                 wdecth + (long long)s*2*DDc,
                 0, sah + outOff[s]*Dd, 0,
                 Bb*(Lin[s]/2), Dd, Dd, 2, (long long)Dd,
                 Lin[s]/2, (long long)Lin[s]*Dd, 2*Dd, 0, 0, NOSEG, 0);
    }

    // 3a. merged Q projection: q4 = xc @ [Wq0|Wq1|Wq2|Wq3]
    gemm(sah, wqth, 0, q4h, 0,
         Bb*Ll, 4*Dd, Dd, 1, 0, Bb*Ll, 0, Dd, 0, 0, NOSEG, 0);

    // 3b. merged K|V projection over all scales (segmented B): kv[7680][2048]
    gemm(sah, wkvth, 0, kvh, 0,
         SAR, 2048, Dd, 1, 0, SAR, 0, Dd, 0, 0,
         make_int4(4096, 6144, 7168, 0), 2*DDc);

    // 3c. fused 4-scale attention -> fp16 ctx
    {
        dim3 ag(Ll/64, Hh, Bb);
        attnF<<<ag, 128, ATTN_SMEM>>>(q4h, kvh, ctxh, gw);
    }

    // 4. output projection Wo -> tmp fp32
    gemm(ctxh, woth, tmp, 0, 0, Bb*Ll, Dd, Dd, 1, 0, Bb*Ll, 0, Dd, 0, 0, NOSEG, 0);

    // 5. residual + LN1 (fp32 + fp16)
    ln_kernel<<<Bb*Ll, 256>>>(x, tmp, g1, be1, x1, x1h);

    // 6. FFN (GELU fused, fp16 intermediate)
    gemm(x1h, w1th, 0, ffnh, b1, Bb*Ll, Ff, Dd, 1, 0, Bb*Ll, 0, Dd, 0, 2, NOSEG, 0);
    gemm(ffnh, w2th, tmp, 0, b2, Bb*Ll, Dd, Ff, 1, 0, Bb*Ll, 0, Ff, 0, 0, NOSEG, 0);

    // 7. residual + LN2 -> out
    ln_kernel<<<Bb*Ll, 256>>>(x1, tmp, g2, be2, out, (__half*)0);
}

// round 8
// speedup vs baseline: 5.8581x; 1.0178x over previous
#include <cuda_runtime.h>
#include <cuda_fp16.h>
#include <math.h>
#include <stdint.h>

#define Bb 4
#define Ll 1024
#define Dd 1024
#define Hh 16
#define Ff 4096
#define Ss 4
#define DDc (1024LL*1024LL)
#define SAR 7680   // total scale-activation rows: 4096+2048+1024+512

// ================= static scratch (no allocations) =================
__device__ __align__(256) __half g_xph[Bb*(Ll+4)*Dd];
__device__ __align__(256) __half g_sah[SAR*Dd];                    // xc|s1|s2|s3
__device__ __align__(256) __half g_q4h[Bb*Ll*4*Dd];                // [4096][4096]
__device__ __align__(256) __half g_kvh[SAR*2048];                  // [7680][2048] K|V
__device__ __align__(256) __half g_ctxh[Bb*Ll*Dd];
__device__ __align__(256) __half g_x1h[Bb*Ll*Dd];
__device__ __align__(256) __half g_ffnh[Bb*Ll*Ff];
__device__ __align__(256) __half g_wdcth[3*1024*1024];             // [tap][N][K]
__device__ __align__(256) __half g_wdecth[6*1024*1024];            // [s*2+tap][N][K]
__device__ __align__(256) __half g_wq16[4*1024*1024];              // fp16 copies, natural [K][N]
__device__ __align__(256) __half g_wk16[4*1024*1024];
__device__ __align__(256) __half g_wv16[1024*1024];
__device__ __align__(256) __half g_wo16[1024*1024];
__device__ __align__(256) __half g_w116[1024*4096];
__device__ __align__(256) __half g_w216[4096*1024];
__device__ __align__(256) float g_x1[Bb*Ll*Dd];
__device__ __align__(256) float g_tmp[Bb*Ll*Dd];
__device__ float g_w[Ss];

// ================= PTX helpers (base features only) =================
#define CP16(dst, src)    asm volatile("cp.async.cg.shared.global [%0], [%1], 16;" :: "r"(dst), "l"(src) : "memory")
#define CP_COMMIT()       asm volatile("cp.async.commit_group;" ::: "memory")
#define CP_WAIT1()        asm volatile("cp.async.wait_group 1;" ::: "memory")
#define CP_WAIT0()        asm volatile("cp.async.wait_group 0;" ::: "memory")

#define LDSM4(r0,r1,r2,r3,addr) \
    asm volatile("ldmatrix.sync.aligned.m8n8.x4.shared.b16 {%0,%1,%2,%3}, [%4];" \
        : "=r"(r0),"=r"(r1),"=r"(r2),"=r"(r3) : "r"(addr))
#define LDSM4T(r0,r1,r2,r3,addr) \
    asm volatile("ldmatrix.sync.aligned.m8n8.x4.trans.shared.b16 {%0,%1,%2,%3}, [%4];" \
        : "=r"(r0),"=r"(r1),"=r"(r2),"=r"(r3) : "r"(addr))
#define LDSM2(r0,r1,addr) \
    asm volatile("ldmatrix.sync.aligned.m8n8.x2.shared.b16 {%0,%1}, [%2];" \
        : "=r"(r0),"=r"(r1) : "r"(addr))
#define MMA16816(d, a, b) \
    asm volatile("mma.sync.aligned.m16n8k16.row.col.f32.f16.f16.f32 " \
        "{%0,%1,%2,%3}, {%4,%5,%6,%7}, {%8,%9}, {%0,%1,%2,%3};" \
        : "+f"((d)[0]),"+f"((d)[1]),"+f"((d)[2]),"+f"((d)[3]) \
        : "r"((a)[0]),"r"((a)[1]),"r"((a)[2]),"r"((a)[3]), "r"((b)[0]),"r"((b)[1]))

__device__ __forceinline__ uint32_t smem_u32(const void* p) {
    uint32_t a;
    asm("{ .reg .u64 t; cvta.to.shared.u64 t, %1; cvt.u32.u64 %0, t; }" : "=r"(a) : "l"(p));
    return a;
}

__device__ __forceinline__ uint32_t pack2h(float a, float b) {
    __half2 h2 = __floats2half2_rn(a, b);
    return *(uint32_t*)&h2;
}

__device__ __forceinline__ uint32_t packsplit(float a, float b, uint32_t& lo) {
    __half ha = __float2half_rn(a), hb = __float2half_rn(b);
    __half la = __float2half_rn(a - __half2float(ha));
    __half lb = __float2half_rn(b - __half2float(hb));
    lo = ((uint32_t)__half_as_ushort(lb) << 16) | __half_as_ushort(la);
    return ((uint32_t)__half_as_ushort(hb) << 16) | __half_as_ushort(ha);
}

// ================= mma.sync fp16 GEMM: 3-stage pipeline, optional B-trans =================
// BT=0: B pre-laid-out [tap][N][K] fp16 (conv weights). BT=1: B natural [K][N] fp16 (taps==1).
template<int BT>
__device__ __forceinline__ void gemm_body(
    const __half* __restrict__ Ah, const __half* __restrict__ Bh, const __half* __restrict__ B2,
    float* __restrict__ Cf, __half* __restrict__ Oh, const float* __restrict__ bias,
    int N, int K, int NB, int nSplit, int nSegShift,
    int taps, long long tapStrideA,
    int lseg, long long segStride, int rowStride, long long offA, int epi,
    int4 segEnd, long long segUnit)
{
    extern __shared__ char smem[];
    uint32_t sb = smem_u32(smem);
    const int tid = threadIdx.x;
    const int wid = tid >> 5, lane = tid & 31;
    const int m0 = blockIdx.y * 128, n0 = blockIdx.x * 128;

    // ---- B source select ----
    const __half* Bsel;
    int ncol = n0;
    if (BT) {
        if (n0 >= nSplit) { Bsel = B2; ncol = n0 - nSplit; }
        else {
            int nseg = n0 >> nSegShift;
            int mseg = (m0 >= segEnd.x) + (m0 >= segEnd.y) + (m0 >= segEnd.z);
            Bsel = Bh + (long long)(nseg + mseg) * segUnit;
            ncol = n0 & ((1 << nSegShift) - 1);
        }
    } else {
        int mseg = (m0 >= segEnd.x) + (m0 >= segEnd.y) + (m0 >= segEnd.z);
        Bsel = Bh + (long long)mseg * segUnit;
    }

    // ---- cp.async mappings ----
    const int r = tid >> 1, half_ = tid & 1;
    const long long mrow = m0 + r;
    const long long aoff0 = (mrow / lseg) * segStride + (mrow % lseg) * (long long)rowStride + offA + half_ * 32;
    uint32_t dstOffA[4];
#pragma unroll
    for (int j = 0; j < 4; j++) {
        uint32_t off = (uint32_t)(r * 128 + half_ * 64 + j * 16);
        dstOffA[j] = off ^ ((off >> 3) & 0x70);
    }
    // trans-B: 64 k-rows x 256B, split into two 8KB n-half sub-buffers
    const int brow = tid >> 2, bq = tid & 3;
    uint32_t bDst[4];
    long long boff0 = 0;
    if (BT) {
#pragma unroll
        for (int j = 0; j < 4; j++) {
            int bp = bq * 64 + j * 16;
            uint32_t raw = (uint32_t)(brow * 128 + (bp & 127));
            bDst[j] = (uint32_t)((bp >> 7) * 8192) + (raw ^ ((raw >> 3) & 0x70));
        }
        boff0 = (long long)brow * NB + ncol + bq * 32;
    } else {
        boff0 = (long long)(n0 + r) * K + half_ * 32;
    }

    const uint32_t bufBase[3] = { sb, sb + 32768, sb + 65536 };
    const int NCk = K >> 6;
    const int NC = NCk * taps;
    const long long tapStrideB = (long long)N * K;

    auto issue = [&](int c) {
        uint32_t bs = bufBase[c % 3];
        int tap = c / NCk, kc = c - tap * NCk;
        long long ao = aoff0 + (long long)tap * tapStrideA + kc * 64;
#pragma unroll
        for (int j = 0; j < 4; j++) CP16(bs + dstOffA[j], Ah + ao + j * 8);
        if (BT) {
            long long bo = boff0 + (long long)c * 64 * NB;
#pragma unroll
            for (int j = 0; j < 4; j++) CP16(bs + 16384 + bDst[j], Bsel + bo + j * 8);
        } else {
            long long bo = boff0 + (long long)tap * tapStrideB + kc * 64;
#pragma unroll
            for (int j = 0; j < 4; j++) CP16(bs + 16384 + dstOffA[j], Bsel + bo + j * 8);
        }
        CP_COMMIT();
    };

    // ---- mma fragment addressing ----
    const int wm = wid & 1, wn = wid >> 1;
    const int arow = wm * 64 + (lane & 15);
    const uint32_t aRowOff = (uint32_t)(arow * 128);
    const uint32_t aXb = (uint32_t)((arow & 7) << 4);
    const uint32_t aHalf = (uint32_t)((lane >> 4) * 16);
    // non-trans B addressing
    const uint32_t bRowOff = (uint32_t)((wn * 32 + (lane & 7)) * 128);
    const uint32_t bXb = (uint32_t)((lane & 7) << 4);
    const uint32_t bHalf = (uint32_t)(((lane >> 3) & 1) * 16);
    // trans B addressing (attnF V pattern)
    const uint32_t vrowb = (uint32_t)((lane & 7) + ((lane >> 3) & 1) * 8);
    const uint32_t vbyteb = (uint32_t)(((lane >> 4) & 1) * 16);
    const uint32_t warpNb = (uint32_t)((wn & 1) * 64);
    const uint32_t subSel = (uint32_t)((wn >> 1) * 8192);

    float acc[4][4][4];
#pragma unroll
    for (int i = 0; i < 4; i++)
#pragma unroll
        for (int j = 0; j < 4; j++)
#pragma unroll
            for (int e = 0; e < 4; e++) acc[i][j][e] = 0.f;

    issue(0); issue(1);

#pragma unroll 1
    for (int c = 0; c < NC; c++) {
        if (c == NC - 1) CP_WAIT0(); else CP_WAIT1();
        __syncthreads();
        if (c + 2 < NC) issue(c + 2);

        const uint32_t bs = bufBase[c % 3];
#pragma unroll
        for (int k16 = 0; k16 < 4; k16++) {
            const uint32_t aoff = aRowOff + ((k16 * 32 + aHalf) ^ aXb);
            uint32_t ah[4][4], bh[4][2];
#pragma unroll
            for (int i = 0; i < 4; i++)
                LDSM4(ah[i][0], ah[i][1], ah[i][2], ah[i][3], bs + i * 2048 + aoff);
            if (BT) {
                uint32_t subB = bs + 16384 + subSel;
#pragma unroll
                for (int t2 = 0; t2 < 2; t2++) {
                    uint32_t off = (k16 * 16 + vrowb) * 128 + warpNb + t2 * 32 + vbyteb;
                    off ^= (off >> 3) & 0x70;
                    LDSM4T(bh[2*t2][0], bh[2*t2][1], bh[2*t2+1][0], bh[2*t2+1][1], subB + off);
                }
            } else {
                const uint32_t boff = bRowOff + ((k16 * 32 + bHalf) ^ bXb);
#pragma unroll
                for (int j = 0; j < 4; j++)
                    LDSM2(bh[j][0], bh[j][1], bs + 16384 + j * 1024 + boff);
            }
#pragma unroll
            for (int i = 0; i < 4; i++)
#pragma unroll
                for (int j = 0; j < 4; j++)
                    MMA16816(acc[i][j], ah[i], bh[j]);
        }
    }

    // ---- epilogue ----
#pragma unroll
    for (int i = 0; i < 4; i++)
#pragma unroll
        for (int j = 0; j < 4; j++)
#pragma unroll
            for (int p = 0; p < 2; p++) {
                int rr = m0 + wm * 64 + i * 16 + (lane >> 2) + p * 8;
                int cc = n0 + wn * 32 + j * 8 + (lane & 3) * 2;
                float v0 = acc[i][j][p * 2];
                float v1 = acc[i][j][p * 2 + 1];
                if (bias) { v0 += bias[cc]; v1 += bias[cc + 1]; }
                if (epi == 1) { v0 = fmaxf(v0, 0.f); v1 = fmaxf(v1, 0.f); }
                else if (epi == 2) {
                    v0 = 0.5f * v0 * (1.f + erff(v0 * 0.70710678118654752f));
                    v1 = 0.5f * v1 * (1.f + erff(v1 * 0.70710678118654752f));
                }
                long long idx = (long long)rr * N + cc;
                if (Cf) { float2 f; f.x = v0; f.y = v1; *(float2*)(Cf + idx) = f; }
                if (Oh) *(uint32_t*)(Oh + idx) = pack2h(v0, v1);
            }
}

__global__ __launch_bounds__(256, 2) void gemmM0(
    const __half* __restrict__ Ah, const __half* __restrict__ Bh, const __half* __restrict__ B2,
    float* __restrict__ Cf, __half* __restrict__ Oh, const float* __restrict__ bias,
    int N, int K, int NB, int nSplit, int nSegShift,
    int taps, long long tapStrideA, int lseg, long long segStride, int rowStride,
    long long offA, int epi, int4 segEnd, long long segUnit)
{
    gemm_body<0>(Ah, Bh, B2, Cf, Oh, bias, N, K, NB, nSplit, nSegShift,
                 taps, tapStrideA, lseg, segStride, rowStride, offA, epi, segEnd, segUnit);
}

__global__ __launch_bounds__(256, 2) void gemmM1(
    const __half* __restrict__ Ah, const __half* __restrict__ Bh, const __half* __restrict__ B2,
    float* __restrict__ Cf, __half* __restrict__ Oh, const float* __restrict__ bias,
    int N, int K, int NB, int nSplit, int nSegShift,
    int taps, long long tapStrideA, int lseg, long long segStride, int rowStride,
    long long offA, int epi, int4 segEnd, long long segUnit)
{
    gemm_body<1>(Ah, Bh, B2, Cf, Oh, bias, N, K, NB, nSplit, nSegShift,
                 taps, tapStrideA, lseg, segStride, rowStride, offA, epi, segEnd, segUnit);
}

// ================= fused 4-scale flash attention (fp16; P split; 3-stage KV) =================
__global__ __launch_bounds__(128, 2) void attnF(
    const __half* __restrict__ Qh4, const __half* __restrict__ KVh,
    __half* __restrict__ Oh, const float* __restrict__ gw)
{
    extern __shared__ char smem[];
    uint32_t sb = smem_u32(smem);
    const int tid = threadIdx.x;
    const int w = tid >> 5, lane = tid & 31;
    const int b = blockIdx.z, h = blockIdx.y;
    const int q0 = blockIdx.x * 64;

    float w4[4];
#pragma unroll
    for (int s = 0; s < 4; s++) w4[s] = gw[s];

    const int r = tid >> 1, half_ = tid & 1;
    uint32_t dstOff[4];
#pragma unroll
    for (int j = 0; j < 4; j++) {
        uint32_t off = (uint32_t)(r * 128 + half_ * 64 + j * 16);
        dstOff[j] = off ^ ((off >> 3) & 0x70);
    }
    // smem: Q bufs 2x8KB, KV bufs 3x16KB (Kh 0 / Vh 8192)
    const uint32_t sQb[2] = { sb, sb + 8192 };
    const uint32_t kvb[3] = { sb + 16384, sb + 32768, sb + 49152 };

    const long long qrowbase = ((long long)(b * Ll + q0 + r)) * 4096 + h * 64 + half_ * 32;

    auto kvRow = [&](int cc) -> long long {
        int s2  = (cc < 16) ? 0 : (cc < 24) ? 1 : (cc < 28) ? 2 : 3;
        int bas = (s2 == 0) ? 0 : (s2 == 1) ? 16 : (s2 == 2) ? 24 : 28;
        int Ls2 = (s2 == 0) ? 1024 : (s2 == 1) ? 512 : (s2 == 2) ? 256 : 128;
        int ro2 = (s2 == 0) ? 0 : (s2 == 1) ? 4096 : (s2 == 2) ? 6144 : 7168;
        int kc2 = cc - bas;
        return ((long long)(ro2 + b * Ls2 + kc2 * 64 + r)) * 2048 + h * 64 + half_ * 32;
    };

    // prologue: (Q0 + kv0), (kv1)
    {
#pragma unroll
        for (int j = 0; j < 4; j++)
            CP16(sQb[0] + dstOff[j], Qh4 + qrowbase + j * 8);
        long long kr = kvRow(0);
#pragma unroll
        for (int j = 0; j < 4; j++) {
            CP16(kvb[0]        + dstOff[j], KVh + kr + j * 8);
            CP16(kvb[0] + 8192 + dstOff[j], KVh + kr + 1024 + j * 8);
        }
        CP_COMMIT();
        kr = kvRow(1);
#pragma unroll
        for (int j = 0; j < 4; j++) {
            CP16(kvb[1]        + dstOff[j], KVh + kr + j * 8);
            CP16(kvb[1] + 8192 + dstOff[j], KVh + kr + 1024 + j * 8);
        }
        CP_COMMIT();
    }

    const uint32_t qoffBase = (uint32_t)((w * 16 + (lane & 15)) * 128 + ((lane >> 4) & 1) * 16);
    const uint32_t krowb = (uint32_t)((lane & 7) + ((lane >> 4) & 1) * 8);
    const uint32_t kbyteb = (uint32_t)(((lane >> 3) & 1) * 16);
    const uint32_t vrowb = (uint32_t)((lane & 7) + ((lane >> 3) & 1) * 8);
    const uint32_t vbyteb = (uint32_t)(((lane >> 4) & 1) * 16);

    uint32_t qah[4][4];
    float oacc[8][4];
#pragma unroll
    for (int t = 0; t < 8; t++)
#pragma unroll
        for (int e = 0; e < 4; e++) oacc[t][e] = 0.f;
    float o[8][4];
    float m0v = -1e30f, m1v = -1e30f, l0 = 0.f, l1 = 0.f;

#pragma unroll 1
    for (int c = 0; c < 30; c++) {
        const int s  = (c < 16) ? 0 : (c < 24) ? 1 : (c < 28) ? 2 : 3;
        const int bas = (s == 0) ? 0 : (s == 1) ? 16 : (s == 2) ? 24 : 28;
        const int nch = (s == 0) ? 16 : (s == 1) ? 8 : (s == 2) ? 4 : 2;
        const int kc = c - bas;

        if (c == 29) CP_WAIT0(); else CP_WAIT1();
        __syncthreads();

        // prefetch kv c+2 and (at scale start) next-scale Q
        {
            bool doCommit = false;
            int cc = c + 2;
            if (cc < 30) {
                long long kr = kvRow(cc);
                uint32_t bs2 = kvb[cc % 3];
#pragma unroll
                for (int j = 0; j < 4; j++) {
                    CP16(bs2        + dstOff[j], KVh + kr + j * 8);
                    CP16(bs2 + 8192 + dstOff[j], KVh + kr + 1024 + j * 8);
                }
                doCommit = true;
            }
            if (kc == 0 && s < 3) {
                uint32_t qb2 = sQb[(s + 1) & 1];
                long long qsrc = qrowbase + (long long)(s + 1) * 1024;
#pragma unroll
                for (int j = 0; j < 4; j++)
                    CP16(qb2 + dstOff[j], Qh4 + qsrc + j * 8);
                doCommit = true;
            }
            if (doCommit) CP_COMMIT();
        }

        if (kc == 0) {
            uint32_t qb = sQb[s & 1];
#pragma unroll
            for (int k16 = 0; k16 < 4; k16++) {
                uint32_t off = qoffBase + k16 * 32;
                off ^= (off >> 3) & 0x70;
                LDSM4(qah[k16][0], qah[k16][1], qah[k16][2], qah[k16][3], qb + off);
            }
            m0v = -1e30f; m1v = -1e30f; l0 = 0.f; l1 = 0.f;
#pragma unroll
            for (int t = 0; t < 8; t++)
#pragma unroll
                for (int e = 0; e < 4; e++) o[t][e] = 0.f;
        }

        const uint32_t bs = kvb[c % 3];
        // ---- S = Q K^T ----
        float sc[8][4];
#pragma unroll
        for (int t = 0; t < 8; t++)
#pragma unroll
            for (int e = 0; e < 4; e++) sc[t][e] = 0.f;
#pragma unroll
        for (int k16 = 0; k16 < 4; k16++) {
            uint32_t kh[8][2];
#pragma unroll
            for (int t4 = 0; t4 < 4; t4++) {
                uint32_t off = (t4 * 16 + krowb) * 128 + k16 * 32 + kbyteb;
                off ^= (off >> 3) & 0x70;
                LDSM4(kh[2*t4][0], kh[2*t4][1], kh[2*t4+1][0], kh[2*t4+1][1], bs + off);
            }
#pragma unroll
            for (int j = 0; j < 8; j++)
                MMA16816(sc[j], qah[k16], kh[j]);
        }

        // ---- online softmax ----
        float rmax0 = -1e30f, rmax1 = -1e30f;
#pragma unroll
        for (int t = 0; t < 8; t++) {
            sc[t][0] *= 0.125f; sc[t][1] *= 0.125f; sc[t][2] *= 0.125f; sc[t][3] *= 0.125f;
            rmax0 = fmaxf(rmax0, fmaxf(sc[t][0], sc[t][1]));
            rmax1 = fmaxf(rmax1, fmaxf(sc[t][2], sc[t][3]));
        }
        rmax0 = fmaxf(rmax0, __shfl_xor_sync(0xffffffffu, rmax0, 1));
        rmax0 = fmaxf(rmax0, __shfl_xor_sync(0xffffffffu, rmax0, 2));
        rmax1 = fmaxf(rmax1, __shfl_xor_sync(0xffffffffu, rmax1, 1));
        rmax1 = fmaxf(rmax1, __shfl_xor_sync(0xffffffffu, rmax1, 2));
        float mn0 = fmaxf(m0v, rmax0), mn1 = fmaxf(m1v, rmax1);
        float fac0 = __expf(m0v - mn0), fac1 = __expf(m1v - mn1);
        float rs0 = 0.f, rs1 = 0.f;
#pragma unroll
        for (int t = 0; t < 8; t++) {
            sc[t][0] = __expf(sc[t][0] - mn0); sc[t][1] = __expf(sc[t][1] - mn0);
            sc[t][2] = __expf(sc[t][2] - mn1); sc[t][3] = __expf(sc[t][3] - mn1);
            rs0 += sc[t][0] + sc[t][1];
            rs1 += sc[t][2] + sc[t][3];
        }
        rs0 += __shfl_xor_sync(0xffffffffu, rs0, 1);
        rs0 += __shfl_xor_sync(0xffffffffu, rs0, 2);
        rs1 += __shfl_xor_sync(0xffffffffu, rs1, 1);
        rs1 += __shfl_xor_sync(0xffffffffu, rs1, 2);
        l0 = l0 * fac0 + rs0; l1 = l1 * fac1 + rs1;
        m0v = mn0; m1v = mn1;
#pragma unroll
        for (int t = 0; t < 8; t++) {
            o[t][0] *= fac0; o[t][1] *= fac0; o[t][2] *= fac1; o[t][3] *= fac1;
        }

        // ---- O += P V (P split hi+lo) ----
#pragma unroll
        for (int k16 = 0; k16 < 4; k16++) {
            uint32_t ph[4], pl[4];
            int t = 2 * k16;
            ph[0] = packsplit(sc[t][0],   sc[t][1],   pl[0]);
            ph[1] = packsplit(sc[t][2],   sc[t][3],   pl[1]);
            ph[2] = packsplit(sc[t+1][0], sc[t+1][1], pl[2]);
            ph[3] = packsplit(sc[t+1][2], sc[t+1][3], pl[3]);
            uint32_t vh[8][2];
#pragma unroll
            for (int t4 = 0; t4 < 4; t4++) {
                uint32_t off = (k16 * 16 + vrowb) * 128 + t4 * 32 + vbyteb;
                off ^= (off >> 3) & 0x70;
                LDSM4T(vh[2*t4][0], vh[2*t4][1], vh[2*t4+1][0], vh[2*t4+1][1], bs + 8192 + off);
            }
#pragma unroll
            for (int t8 = 0; t8 < 8; t8++) {
                MMA16816(o[t8], ph, vh[t8]);
                MMA16816(o[t8], pl, vh[t8]);
            }
        }

        // ---- finalize scale ----
        if (kc == nch - 1) {
            float ws = w4[s];
            float inv0 = ws / l0, inv1 = ws / l1;
#pragma unroll
            for (int t = 0; t < 8; t++) {
                oacc[t][0] += o[t][0] * inv0;
                oacc[t][1] += o[t][1] * inv0;
                oacc[t][2] += o[t][2] * inv1;
                oacc[t][3] += o[t][3] * inv1;
            }
        }
    }

    // ---- write fp16 ctx ----
    int g = lane >> 2;
    int qrow0 = q0 + w * 16 + g;
    long long base0 = ((long long)(b * Ll + qrow0)) * Dd + h * 64;
    long long base1 = base0 + 8LL * Dd;
#pragma unroll
    for (int t = 0; t < 8; t++) {
        int d0 = t * 8 + (lane & 3) * 2;
        *(uint32_t*)(Oh + base0 + d0) = pack2h(oacc[t][0], oacc[t][1]);
        *(uint32_t*)(Oh + base1 + d0) = pack2h(oacc[t][2], oacc[t][3]);
    }
}

// ================= LayerNorm: out = LN(a + r), optional fp16 =================
__global__ __launch_bounds__(256) void ln_kernel(
    const float* __restrict__ a, const float* __restrict__ rr,
    const float* __restrict__ gamma, const float* __restrict__ beta,
    float* __restrict__ out, __half* __restrict__ oh)
{
    __shared__ float red[8], red2[8];
    __shared__ float smu, sinv;
    int row = blockIdx.x, tid = threadIdx.x;
    long long base = (long long)row * Dd;
    float4 va = ((const float4*)(a + base))[tid];
    float4 vr = ((const float4*)(rr + base))[tid];
    float x0 = va.x+vr.x, x1 = va.y+vr.y, x2 = va.z+vr.z, x3 = va.w+vr.w;
    float s  = x0+x1+x2+x3;
    float s2 = x0*x0 + x1*x1 + x2*x2 + x3*x3;
#pragma unroll
    for (int off = 16; off >= 1; off >>= 1) {
        s  += __shfl_xor_sync(0xffffffffu, s,  off);
        s2 += __shfl_xor_sync(0xffffffffu, s2, off);
    }
    int w = tid >> 5, lane = tid & 31;
    if (lane == 0) { red[w] = s; red2[w] = s2; }
    __syncthreads();
    if (tid == 0) {
        float S = 0.f, S2 = 0.f;
        for (int i = 0; i < 8; i++) { S += red[i]; S2 += red2[i]; }
        float mu = S * (1.f/Dd);
        smu = mu;
        sinv = rsqrtf(S2 * (1.f/Dd) - mu*mu + 1e-5f);
    }
    __syncthreads();
    float mu = smu, inv = sinv;
    float4 gg = ((const float4*)gamma)[tid];
    float4 bb = ((const float4*)beta)[tid];
    float y0 = (x0-mu)*inv*gg.x + bb.x;
    float y1 = (x1-mu)*inv*gg.y + bb.y;
    float y2 = (x2-mu)*inv*gg.z + bb.z;
    float y3 = (x3-mu)*inv*gg.w + bb.w;
    float4 y; y.x=y0; y.y=y1; y.z=y2; y.w=y3;
    ((float4*)(out + base))[tid] = y;
    if (oh) {
        ((uint32_t*)(oh + base))[tid*2]   = pack2h(y0, y1);
        ((uint32_t*)(oh + base))[tid*2+1] = pack2h(y2, y3);
    }
}

// ================= preprocessing kernels =================
__global__ void pad_split_kernel(const float* __restrict__ x)
{
    const long long total = (long long)Bb*(Ll+4)*Dd;
    for (long long i = blockIdx.x*256LL + threadIdx.x; i < total; i += (long long)gridDim.x*256LL) {
        int d = (int)(i % Dd);
        long long t = i / Dd;
        int p = (int)(t % (Ll+4));
        int b = (int)(t / (Ll+4));
        float v = 0.f;
        if (p >= 2 && p < Ll+2)
            v = x[((long long)b*Ll + (p-2))*Dd + d];
        g_xph[i] = __float2half_rn(v);
    }
}

__global__ void tdc_split(const float* __restrict__ W)
{
    const long long total = 3LL*Dd*Dd;
    for (long long idx = blockIdx.x*256LL + threadIdx.x; idx < total; idx += (long long)gridDim.x*256LL) {
        int tap = (int)(idx / (Dd*(long long)Dd));
        long long rem = idx % (Dd*(long long)Dd);
        int o = (int)(rem / Dd), i = (int)(rem % Dd);
        g_wdcth[idx] = __float2half_rn(W[((long long)o*Dd + i)*3 + tap]);
    }
}

__global__ void tdec_split(const float* __restrict__ W)
{
    const long long total = 6LL*Dd*Dd;
    for (long long idx = blockIdx.x*256LL + threadIdx.x; idx < total; idx += (long long)gridDim.x*256LL) {
        int st = (int)(idx / (Dd*(long long)Dd));
        int s = st >> 1, tap = st & 1;
        long long rem = idx % (Dd*(long long)Dd);
        int o = (int)(rem / Dd), i = (int)(rem % Dd);
        g_wdecth[idx] = __float2half_rn(W[(((long long)s*Dd + o)*Dd + i)*2 + tap]);
    }
}

// one-shot fp32->fp16 convert over 6 jobs (flat, vectorized)
struct CvtJobs {
    const float4* src[6];
    uint2* dst[6];
    long long n4[6];
};
__global__ void cvt16(CvtJobs J, long long tot4)
{
    for (long long i = blockIdx.x*256LL + threadIdx.x; i < tot4; i += (long long)gridDim.x*256LL) {
        long long rr = i; int j = 0;
#pragma unroll
        for (int t = 0; t < 5; t++) if (rr >= J.n4[j]) { rr -= J.n4[j]; j++; }
        float4 v = J.src[j][rr];
        __half2 a = __floats2half2_rn(v.x, v.y), b = __floats2half2_rn(v.z, v.w);
        uint2 oo; oo.x = *(uint32_t*)&a; oo.y = *(uint32_t*)&b;
        J.dst[j][rr] = oo;
    }
}

__global__ void agg_kernel(const float* __restrict__ logits, float* __restrict__ aux)
{
    float mx = -1e30f;
    for (int s = 0; s < Ss; s++) mx = fmaxf(mx, logits[s]);
    float e[Ss], sum = 0.f;
    for (int s = 0; s < Ss; s++) { e[s] = expf(logits[s] - mx); sum += e[s]; }
    float ent = 0.f;
    for (int s = 0; s < Ss; s++) {
        float w = e[s] / sum;
        g_w[s] = w;
        ent -= w * logf(w + 1e-9f);
    }
    if (aux) *aux = ent;
}

__global__ void fill0_kernel(float* p, long long n)
{
    for (long long i = blockIdx.x*256LL + threadIdx.x; i < n; i += (long long)gridDim.x*256LL)
        p[i] = 0.f;
}

// ================= launch =================
extern "C" void kernel_launch(void* const* d_in, const int* in_sizes, int n_in,
                              void* d_out, int out_size)
{
    const float* x     = (const float*)d_in[0];
    const float* W_dc  = (const float*)d_in[1];
    const float* b_dc  = (const float*)d_in[2];
    const float* W_dec = (const float*)d_in[3];
    const float* Wq    = (const float*)d_in[4];
    const float* Wk    = (const float*)d_in[5];
    const float* Wv    = (const float*)d_in[6];
    const float* Wo    = (const float*)d_in[7];
    const float* aggl  = (const float*)d_in[8];
    const float* g1    = (const float*)d_in[9];
    const float* be1   = (const float*)d_in[10];
    const float* g2    = (const float*)d_in[11];
    const float* be2   = (const float*)d_in[12];
    const float* W1    = (const float*)d_in[13];
    const float* b1    = (const float*)d_in[14];
    const float* W2    = (const float*)d_in[15];
    const float* b2    = (const float*)d_in[16];
    float* out = (float*)d_out;

    static int smem_set = 0;
    const int GEMM_SMEM = 3 * 32768;   // 96KB, 2 CTAs/SM
    const int ATTN_SMEM = 4 * 16384;   // 64KB, 2 CTAs/SM
    if (!smem_set) {
        cudaFuncSetAttribute(gemmM0, cudaFuncAttributeMaxDynamicSharedMemorySize, GEMM_SMEM);
        cudaFuncSetAttribute(gemmM1, cudaFuncAttributeMaxDynamicSharedMemorySize, GEMM_SMEM);
        cudaFuncSetAttribute(attnF,  cudaFuncAttributeMaxDynamicSharedMemorySize, ATTN_SMEM);
        smem_set = 1;
    }

#define SYM(v, s) cudaGetSymbolAddress((void**)&v, s)
    __half *xph,*sah,*q4h,*kvh,*ctxh,*x1h,*ffnh;
    __half *wdcth,*wdecth,*wq16,*wk16,*wv16,*wo16,*w116,*w216;
    float *x1,*tmp,*gw;
    SYM(xph,g_xph); SYM(sah,g_sah);
    SYM(q4h,g_q4h); SYM(kvh,g_kvh);
    SYM(ctxh,g_ctxh); SYM(x1h,g_x1h); SYM(ffnh,g_ffnh);
    SYM(wdcth,g_wdcth); SYM(wdecth,g_wdecth);
    SYM(wq16,g_wq16); SYM(wk16,g_wk16); SYM(wv16,g_wv16); SYM(wo16,g_wo16);
    SYM(w116,g_w116); SYM(w216,g_w216);
    SYM(x1,g_x1); SYM(tmp,g_tmp); SYM(gw,g_w);
#undef SYM

    const int BLD = Bb*Ll*Dd;
    const int4 NOSEG = make_int4(0x7fffffff, 0x7fffffff, 0x7fffffff, 0);
    const int NOSPLIT = 1 << 30;

    // ---- preprocessing ----
    tdc_split <<<1024, 256>>>(W_dc);
    tdec_split<<<2048, 256>>>(W_dec);
    {
        CvtJobs J;
        J.src[0] = (const float4*)Wq; J.dst[0] = (uint2*)wq16; J.n4[0] = 4*DDc/4;
        J.src[1] = (const float4*)Wk; J.dst[1] = (uint2*)wk16; J.n4[1] = 4*DDc/4;
        J.src[2] = (const float4*)Wv; J.dst[2] = (uint2*)wv16; J.n4[2] = DDc/4;
        J.src[3] = (const float4*)Wo; J.dst[3] = (uint2*)wo16; J.n4[3] = DDc/4;
        J.src[4] = (const float4*)W1; J.dst[4] = (uint2*)w116; J.n4[4] = (long long)Dd*Ff/4;
        J.src[5] = (const float4*)W2; J.dst[5] = (uint2*)w216; J.n4[5] = (long long)Dd*Ff/4;
        long long tot4 = J.n4[0]+J.n4[1]+J.n4[2]+J.n4[3]+J.n4[4]+J.n4[5];
        cvt16<<<2048, 256>>>(J, tot4);
    }
    pad_split_kernel<<<4096, 256>>>(x);
    if (out_size > BLD) {
        long long gap = (long long)out_size - BLD;
        fill0_kernel<<<256, 256>>>(out + BLD, gap);
        agg_kernel<<<1, 1>>>(aggl, out + out_size - 1);
    } else {
        agg_kernel<<<1, 1>>>(aggl, (float*)0);
    }

    // ---- conv GEMMs (pre-transposed weights, BT=0) ----
    // 1. dilated conv (k=3, dil=2) + bias + ReLU -> sa rows [0,4096)
    gemmM0<<<dim3(Dd/128, (Bb*Ll)/128), 256, GEMM_SMEM>>>(
        xph, wdcth, (const __half*)0, 0, sah, b_dc,
        Dd, Dd, 0, NOSPLIT, 30,
        3, 2LL*Dd, Ll, (long long)(Ll+4)*Dd, Dd, 0, 1, NOSEG, 0);

    // 2. hierarchical decomposition (stride-2, k=2) into sa rows [4096,7680)
    {
        const long long inOff[3]  = {0, 4096, 6144};
        const long long outOff[3] = {4096, 6144, 7168};
        int Lin[3] = {1024, 512, 256};
        for (int s = 0; s < 3; s++) {
            int M = Bb*(Lin[s]/2);
            gemmM0<<<dim3(Dd/128, M/128), 256, GEMM_SMEM>>>(
                sah + inOff[s]*Dd, wdecth + (long long)s*2*DDc, (const __half*)0,
                0, sah + outOff[s]*Dd, 0,
                Dd, Dd, 0, NOSPLIT, 30,
                2, (long long)Dd, Lin[s]/2, (long long)Lin[s]*Dd, 2*Dd, 0, 0, NOSEG, 0);
        }
    }

    // ---- projection / FFN GEMMs (natural-layout fp16 weights, BT=1) ----
    // 3a. merged Q projection: q4 = xc @ [Wq0|Wq1|Wq2|Wq3] (n-seg select)
    gemmM1<<<dim3(4*Dd/128, (Bb*Ll)/128), 256, GEMM_SMEM>>>(
        sah, wq16, (const __half*)0, 0, q4h, 0,
        4*Dd, Dd, Dd, NOSPLIT, 10,
        1, 0, Bb*Ll, 0, Dd, 0, 0, NOSEG, DDc);

    // 3b. merged K|V projection: m-seg for Wk, n-split to shared Wv
    gemmM1<<<dim3(2048/128, SAR/128), 256, GEMM_SMEM>>>(
        sah, wk16, wv16, 0, kvh, 0,
        2048, Dd, Dd, 1024, 30,
        1, 0, SAR, 0, Dd, 0, 0,
        make_int4(4096, 6144, 7168, 0), DDc);

    // 3c. fused 4-scale attention -> fp16 ctx
    {
        dim3 ag(Ll/64, Hh, Bb);
        attnF<<<ag, 128, ATTN_SMEM>>>(q4h, kvh, ctxh, gw);
    }

    // 4. output projection Wo -> tmp fp32
    gemmM1<<<dim3(Dd/128, (Bb*Ll)/128), 256, GEMM_SMEM>>>(
        ctxh, wo16, (const __half*)0, tmp, 0, 0,
        Dd, Dd, Dd, NOSPLIT, 30,
        1, 0, Bb*Ll, 0, Dd, 0, 0, NOSEG, 0);

    // 5. residual + LN1 (fp32 + fp16)
    ln_kernel<<<Bb*Ll, 256>>>(x, tmp, g1, be1, x1, x1h);

    // 6. FFN (GELU fused, fp16 intermediate)
    gemmM1<<<dim3(Ff/128, (Bb*Ll)/128), 256, GEMM_SMEM>>>(
        x1h, w116, (const __half*)0, 0, ffnh, b1,
        Ff, Dd, Ff, NOSPLIT, 30,
        1, 0, Bb*Ll, 0, Dd, 0, 2, NOSEG, 0);
    gemmM1<<<dim3(Dd/128, (Bb*Ll)/128), 256, GEMM_SMEM>>>(
        ffnh, w216, (const __half*)0, tmp, 0, b2,
        Dd, Ff, Dd, NOSPLIT, 30,
        1, 0, Bb*Ll, 0, Ff, 0, 0, NOSEG, 0);

    // 7. residual + LN2 -> out
    ln_kernel<<<Bb*Ll, 256>>>(x1, tmp, g2, be2, out, (__half*)0);
}

// round 9
// speedup vs baseline: 6.1343x; 1.0472x over previous
#include <cuda_runtime.h>
#include <cuda_fp16.h>
#include <math.h>
#include <stdint.h>

#define Bb 4
#define Ll 1024
#define Dd 1024
#define Hh 16
#define Ff 4096
#define Ss 4
#define DDc (1024LL*1024LL)
#define SAR 7680   // total scale-activation rows: 4096+2048+1024+512

// ================= static scratch (no allocations) =================
__device__ __align__(256) __half g_xph[Bb*(Ll+4)*Dd];
__device__ __align__(256) __half g_sah[SAR*Dd];                    // xc|s1|s2|s3
__device__ __align__(256) __half g_q4h[Bb*Ll*4*Dd];                // [4096][4096]
__device__ __align__(256) __half g_kvh[SAR*2048];                  // [7680][2048] K|V
__device__ __align__(256) __half g_ctxh[Bb*Ll*Dd];
__device__ __align__(256) __half g_x1h[Bb*Ll*Dd];
__device__ __align__(256) __half g_ffnh[Bb*Ll*Ff];
__device__ __align__(256) __half g_wdcth[3*1024*1024];             // [tap][N][K]
__device__ __align__(256) __half g_wdecth[6*1024*1024];            // [s*2+tap][N][K]
__device__ __align__(256) __half g_wq16[4*1024*1024];              // fp16 copies, natural [K][N]
__device__ __align__(256) __half g_wk16[4*1024*1024];
__device__ __align__(256) __half g_wv16[1024*1024];
__device__ __align__(256) __half g_wo16[1024*1024];
__device__ __align__(256) __half g_w116[1024*4096];
__device__ __align__(256) __half g_w216[4096*1024];
__device__ __align__(256) float g_x1[Bb*Ll*Dd];
__device__ __align__(256) float g_tmp[Bb*Ll*Dd];
__device__ __align__(256) float g_dec[4*2048*1024];                // split-K partials (32MB)
__device__ float g_w[Ss];

// ================= PTX helpers (base features only) =================
#define CP16(dst, src)    asm volatile("cp.async.cg.shared.global [%0], [%1], 16;" :: "r"(dst), "l"(src) : "memory")
#define CP_COMMIT()       asm volatile("cp.async.commit_group;" ::: "memory")
#define CP_WAIT1()        asm volatile("cp.async.wait_group 1;" ::: "memory")
#define CP_WAIT0()        asm volatile("cp.async.wait_group 0;" ::: "memory")

#define LDSM4(r0,r1,r2,r3,addr) \
    asm volatile("ldmatrix.sync.aligned.m8n8.x4.shared.b16 {%0,%1,%2,%3}, [%4];" \
        : "=r"(r0),"=r"(r1),"=r"(r2),"=r"(r3) : "r"(addr))
#define LDSM4T(r0,r1,r2,r3,addr) \
    asm volatile("ldmatrix.sync.aligned.m8n8.x4.trans.shared.b16 {%0,%1,%2,%3}, [%4];" \
        : "=r"(r0),"=r"(r1),"=r"(r2),"=r"(r3) : "r"(addr))
#define LDSM2(r0,r1,addr) \
    asm volatile("ldmatrix.sync.aligned.m8n8.x2.shared.b16 {%0,%1}, [%2];" \
        : "=r"(r0),"=r"(r1) : "r"(addr))
#define MMA16816(d, a, b) \
    asm volatile("mma.sync.aligned.m16n8k16.row.col.f32.f16.f16.f32 " \
        "{%0,%1,%2,%3}, {%4,%5,%6,%7}, {%8,%9}, {%0,%1,%2,%3};" \
        : "+f"((d)[0]),"+f"((d)[1]),"+f"((d)[2]),"+f"((d)[3]) \
        : "r"((a)[0]),"r"((a)[1]),"r"((a)[2]),"r"((a)[3]), "r"((b)[0]),"r"((b)[1]))

__device__ __forceinline__ uint32_t smem_u32(const void* p) {
    uint32_t a;
    asm("{ .reg .u64 t; cvta.to.shared.u64 t, %1; cvt.u32.u64 %0, t; }" : "=r"(a) : "l"(p));
    return a;
}

__device__ __forceinline__ uint32_t pack2h(float a, float b) {
    __half2 h2 = __floats2half2_rn(a, b);
    return *(uint32_t*)&h2;
}

__device__ __forceinline__ uint32_t packsplit(float a, float b, uint32_t& lo) {
    __half ha = __float2half_rn(a), hb = __float2half_rn(b);
    __half la = __float2half_rn(a - __half2float(ha));
    __half lb = __float2half_rn(b - __half2float(hb));
    lo = ((uint32_t)__half_as_ushort(lb) << 16) | __half_as_ushort(la);
    return ((uint32_t)__half_as_ushort(hb) << 16) | __half_as_ushort(ha);
}

// ================= mma.sync fp16 GEMM: 3-stage, optional B-trans, optional split-K =================
// BT=0: B pre-laid-out [tap][N][K] fp16. BT=1: B natural [K][N] fp16 (taps==1).
// Split-K: blockIdx.z picks a K-chunk range; fp32 partials stored at Cf + z*zCfStride.
template<int BT>
__device__ __forceinline__ void gemm_body(
    const __half* __restrict__ Ah, const __half* __restrict__ Bh, const __half* __restrict__ B2,
    float* __restrict__ Cf, __half* __restrict__ Oh, const float* __restrict__ bias,
    int N, int K, int NB, int nSplit, int nSegShift,
    int taps, long long tapStrideA,
    int lseg, long long segStride, int rowStride, long long offA, int epi,
    int4 segEnd, long long segUnit, long long zCfStride)
{
    extern __shared__ char smem[];
    uint32_t sb = smem_u32(smem);
    const int tid = threadIdx.x;
    const int wid = tid >> 5, lane = tid & 31;
    const int m0 = blockIdx.y * 128, n0 = blockIdx.x * 128;

    // ---- B source select ----
    const __half* Bsel;
    int ncol = n0;
    if (BT) {
        if (n0 >= nSplit) { Bsel = B2; ncol = n0 - nSplit; }
        else {
            int nseg = n0 >> nSegShift;
            int mseg = (m0 >= segEnd.x) + (m0 >= segEnd.y) + (m0 >= segEnd.z);
            Bsel = Bh + (long long)(nseg + mseg) * segUnit;
            ncol = n0 & ((1 << nSegShift) - 1);
        }
    } else {
        int mseg = (m0 >= segEnd.x) + (m0 >= segEnd.y) + (m0 >= segEnd.z);
        Bsel = Bh + (long long)mseg * segUnit;
    }

    // ---- cp.async mappings ----
    const int r = tid >> 1, half_ = tid & 1;
    const long long mrow = m0 + r;
    const long long aoff0 = (mrow / lseg) * segStride + (mrow % lseg) * (long long)rowStride + offA + half_ * 32;
    uint32_t dstOffA[4];
#pragma unroll
    for (int j = 0; j < 4; j++) {
        uint32_t off = (uint32_t)(r * 128 + half_ * 64 + j * 16);
        dstOffA[j] = off ^ ((off >> 3) & 0x70);
    }
    const int brow = tid >> 2, bq = tid & 3;
    uint32_t bDst[4];
    long long boff0 = 0;
    if (BT) {
#pragma unroll
        for (int j = 0; j < 4; j++) {
            int bp = bq * 64 + j * 16;
            uint32_t raw = (uint32_t)(brow * 128 + (bp & 127));
            bDst[j] = (uint32_t)((bp >> 7) * 8192) + (raw ^ ((raw >> 3) & 0x70));
        }
        boff0 = (long long)brow * NB + ncol + bq * 32;
    } else {
        boff0 = (long long)(n0 + r) * K + half_ * 32;
    }

    const uint32_t bufBase[3] = { sb, sb + 32768, sb + 65536 };
    const int NCk = K >> 6;
    const int NCtot = NCk * taps;
    const int NCz = NCtot / (int)gridDim.z;
    const int c0 = (int)blockIdx.z * NCz;
    const int cEnd = c0 + NCz;
    const long long tapStrideB = (long long)N * K;

    auto issue = [&](int c) {
        uint32_t bs = bufBase[c % 3];
        int tap = c / NCk, kc = c - tap * NCk;
        long long ao = aoff0 + (long long)tap * tapStrideA + kc * 64;
#pragma unroll
        for (int j = 0; j < 4; j++) CP16(bs + dstOffA[j], Ah + ao + j * 8);
        if (BT) {
            long long bo = boff0 + (long long)c * 64 * NB;
#pragma unroll
            for (int j = 0; j < 4; j++) CP16(bs + 16384 + bDst[j], Bsel + bo + j * 8);
        } else {
            long long bo = boff0 + (long long)tap * tapStrideB + kc * 64;
#pragma unroll
            for (int j = 0; j < 4; j++) CP16(bs + 16384 + dstOffA[j], Bsel + bo + j * 8);
        }
        CP_COMMIT();
    };

    // ---- mma fragment addressing ----
    const int wm = wid & 1, wn = wid >> 1;
    const int arow = wm * 64 + (lane & 15);
    const uint32_t aRowOff = (uint32_t)(arow * 128);
    const uint32_t aXb = (uint32_t)((arow & 7) << 4);
    const uint32_t aHalf = (uint32_t)((lane >> 4) * 16);
    const uint32_t bRowOff = (uint32_t)((wn * 32 + (lane & 7)) * 128);
    const uint32_t bXb = (uint32_t)((lane & 7) << 4);
    const uint32_t bHalf = (uint32_t)(((lane >> 3) & 1) * 16);
    const uint32_t vrowb = (uint32_t)((lane & 7) + ((lane >> 3) & 1) * 8);
    const uint32_t vbyteb = (uint32_t)(((lane >> 4) & 1) * 16);
    const uint32_t warpNb = (uint32_t)((wn & 1) * 64);
    const uint32_t subSel = (uint32_t)((wn >> 1) * 8192);

    float acc[4][4][4];
#pragma unroll
    for (int i = 0; i < 4; i++)
#pragma unroll
        for (int j = 0; j < 4; j++)
#pragma unroll
            for (int e = 0; e < 4; e++) acc[i][j][e] = 0.f;

    issue(c0); issue(c0 + 1);

#pragma unroll 1
    for (int c = c0; c < cEnd; c++) {
        if (c == cEnd - 1) CP_WAIT0(); else CP_WAIT1();
        __syncthreads();
        if (c + 2 < cEnd) issue(c + 2);

        const uint32_t bs = bufBase[c % 3];
#pragma unroll
        for (int k16 = 0; k16 < 4; k16++) {
            const uint32_t aoff = aRowOff + ((k16 * 32 + aHalf) ^ aXb);
            uint32_t ah[4][4], bh[4][2];
#pragma unroll
            for (int i = 0; i < 4; i++)
                LDSM4(ah[i][0], ah[i][1], ah[i][2], ah[i][3], bs + i * 2048 + aoff);
            if (BT) {
                uint32_t subB = bs + 16384 + subSel;
#pragma unroll
                for (int t2 = 0; t2 < 2; t2++) {
                    uint32_t off = (k16 * 16 + vrowb) * 128 + warpNb + t2 * 32 + vbyteb;
                    off ^= (off >> 3) & 0x70;
                    LDSM4T(bh[2*t2][0], bh[2*t2][1], bh[2*t2+1][0], bh[2*t2+1][1], subB + off);
                }
            } else {
                const uint32_t boff = bRowOff + ((k16 * 32 + bHalf) ^ bXb);
#pragma unroll
                for (int j = 0; j < 4; j++)
                    LDSM2(bh[j][0], bh[j][1], bs + 16384 + j * 1024 + boff);
            }
#pragma unroll
            for (int i = 0; i < 4; i++)
#pragma unroll
                for (int j = 0; j < 4; j++)
                    MMA16816(acc[i][j], ah[i], bh[j]);
        }
    }

    // ---- epilogue ----
    if (Cf) Cf += (long long)blockIdx.z * zCfStride;
#pragma unroll
    for (int i = 0; i < 4; i++)
#pragma unroll
        for (int j = 0; j < 4; j++)
#pragma unroll
            for (int p = 0; p < 2; p++) {
                int rr = m0 + wm * 64 + i * 16 + (lane >> 2) + p * 8;
                int cc = n0 + wn * 32 + j * 8 + (lane & 3) * 2;
                float v0 = acc[i][j][p * 2];
                float v1 = acc[i][j][p * 2 + 1];
                if (bias) { v0 += bias[cc]; v1 += bias[cc + 1]; }
                if (epi == 1) { v0 = fmaxf(v0, 0.f); v1 = fmaxf(v1, 0.f); }
                else if (epi == 2) {
                    v0 = 0.5f * v0 * (1.f + erff(v0 * 0.70710678118654752f));
                    v1 = 0.5f * v1 * (1.f + erff(v1 * 0.70710678118654752f));
                }
                long long idx = (long long)rr * N + cc;
                if (Cf) { float2 f; f.x = v0; f.y = v1; *(float2*)(Cf + idx) = f; }
                if (Oh) *(uint32_t*)(Oh + idx) = pack2h(v0, v1);
            }
}

__global__ __launch_bounds__(256, 2) void gemmM0(
    const __half* __restrict__ Ah, const __half* __restrict__ Bh, const __half* __restrict__ B2,
    float* __restrict__ Cf, __half* __restrict__ Oh, const float* __restrict__ bias,
    int N, int K, int NB, int nSplit, int nSegShift,
    int taps, long long tapStrideA, int lseg, long long segStride, int rowStride,
    long long offA, int epi, int4 segEnd, long long segUnit, long long zCfStride)
{
    gemm_body<0>(Ah, Bh, B2, Cf, Oh, bias, N, K, NB, nSplit, nSegShift,
                 taps, tapStrideA, lseg, segStride, rowStride, offA, epi, segEnd, segUnit, zCfStride);
}

__global__ __launch_bounds__(256, 2) void gemmM1(
    const __half* __restrict__ Ah, const __half* __restrict__ Bh, const __half* __restrict__ B2,
    float* __restrict__ Cf, __half* __restrict__ Oh, const float* __restrict__ bias,
    int N, int K, int NB, int nSplit, int nSegShift,
    int taps, long long tapStrideA, int lseg, long long segStride, int rowStride,
    long long offA, int epi, int4 segEnd, long long segUnit, long long zCfStride)
{
    gemm_body<1>(Ah, Bh, B2, Cf, Oh, bias, N, K, NB, nSplit, nSegShift,
                 taps, tapStrideA, lseg, segStride, rowStride, offA, epi, segEnd, segUnit, zCfStride);
}

// sum 4 split-K fp32 partials -> fp16 (fixed order, deterministic)
__global__ void cvt_dec(const float* __restrict__ scr, long long zStride,
                        __half* __restrict__ dst, long long n)
{
    for (long long i = blockIdx.x*256LL + threadIdx.x; i * 2 < n; i += (long long)gridDim.x*256LL) {
        long long e = i * 2;
        float2 a = *(const float2*)(scr + e);
        float2 b = *(const float2*)(scr + e + zStride);
        float2 c = *(const float2*)(scr + e + 2*zStride);
        float2 d = *(const float2*)(scr + e + 3*zStride);
        float v0 = ((a.x + b.x) + (c.x + d.x));
        float v1 = ((a.y + b.y) + (c.y + d.y));
        *(uint32_t*)(dst + e) = pack2h(v0, v1);
    }
}

// ================= fused 4-scale flash attention (fp16; P split; 3-stage KV) =================
__global__ __launch_bounds__(128, 2) void attnF(
    const __half* __restrict__ Qh4, const __half* __restrict__ KVh,
    __half* __restrict__ Oh, const float* __restrict__ gw)
{
    extern __shared__ char smem[];
    uint32_t sb = smem_u32(smem);
    const int tid = threadIdx.x;
    const int w = tid >> 5, lane = tid & 31;
    const int b = blockIdx.z, h = blockIdx.y;
    const int q0 = blockIdx.x * 64;

    float w4[4];
#pragma unroll
    for (int s = 0; s < 4; s++) w4[s] = gw[s];

    const int r = tid >> 1, half_ = tid & 1;
    uint32_t dstOff[4];
#pragma unroll
    for (int j = 0; j < 4; j++) {
        uint32_t off = (uint32_t)(r * 128 + half_ * 64 + j * 16);
        dstOff[j] = off ^ ((off >> 3) & 0x70);
    }
    const uint32_t sQb[2] = { sb, sb + 8192 };
    const uint32_t kvb[3] = { sb + 16384, sb + 32768, sb + 49152 };

    const long long qrowbase = ((long long)(b * Ll + q0 + r)) * 4096 + h * 64 + half_ * 32;

    auto kvRow = [&](int cc) -> long long {
        int s2  = (cc < 16) ? 0 : (cc < 24) ? 1 : (cc < 28) ? 2 : 3;
        int bas = (s2 == 0) ? 0 : (s2 == 1) ? 16 : (s2 == 2) ? 24 : 28;
        int Ls2 = (s2 == 0) ? 1024 : (s2 == 1) ? 512 : (s2 == 2) ? 256 : 128;
        int ro2 = (s2 == 0) ? 0 : (s2 == 1) ? 4096 : (s2 == 2) ? 6144 : 7168;
        int kc2 = cc - bas;
        return ((long long)(ro2 + b * Ls2 + kc2 * 64 + r)) * 2048 + h * 64 + half_ * 32;
    };

    {
#pragma unroll
        for (int j = 0; j < 4; j++)
            CP16(sQb[0] + dstOff[j], Qh4 + qrowbase + j * 8);
        long long kr = kvRow(0);
#pragma unroll
        for (int j = 0; j < 4; j++) {
            CP16(kvb[0]        + dstOff[j], KVh + kr + j * 8);
            CP16(kvb[0] + 8192 + dstOff[j], KVh + kr + 1024 + j * 8);
        }
        CP_COMMIT();
        kr = kvRow(1);
#pragma unroll
        for (int j = 0; j < 4; j++) {
            CP16(kvb[1]        + dstOff[j], KVh + kr + j * 8);
            CP16(kvb[1] + 8192 + dstOff[j], KVh + kr + 1024 + j * 8);
        }
        CP_COMMIT();
    }

    const uint32_t qoffBase = (uint32_t)((w * 16 + (lane & 15)) * 128 + ((lane >> 4) & 1) * 16);
    const uint32_t krowb = (uint32_t)((lane & 7) + ((lane >> 4) & 1) * 8);
    const uint32_t kbyteb = (uint32_t)(((lane >> 3) & 1) * 16);
    const uint32_t vrowb = (uint32_t)((lane & 7) + ((lane >> 3) & 1) * 8);
    const uint32_t vbyteb = (uint32_t)(((lane >> 4) & 1) * 16);

    uint32_t qah[4][4];
    float oacc[8][4];
#pragma unroll
    for (int t = 0; t < 8; t++)
#pragma unroll
        for (int e = 0; e < 4; e++) oacc[t][e] = 0.f;
    float o[8][4];
    float m0v = -1e30f, m1v = -1e30f, l0 = 0.f, l1 = 0.f;

#pragma unroll 1
    for (int c = 0; c < 30; c++) {
        const int s  = (c < 16) ? 0 : (c < 24) ? 1 : (c < 28) ? 2 : 3;
        const int bas = (s == 0) ? 0 : (s == 1) ? 16 : (s == 2) ? 24 : 28;
        const int nch = (s == 0) ? 16 : (s == 1) ? 8 : (s == 2) ? 4 : 2;
        const int kc = c - bas;

        if (c == 29) CP_WAIT0(); else CP_WAIT1();
        __syncthreads();

        {
            bool doCommit = false;
            int cc = c + 2;
            if (cc < 30) {
                long long kr = kvRow(cc);
                uint32_t bs2 = kvb[cc % 3];
#pragma unroll
                for (int j = 0; j < 4; j++) {
                    CP16(bs2        + dstOff[j], KVh + kr + j * 8);
                    CP16(bs2 + 8192 + dstOff[j], KVh + kr + 1024 + j * 8);
                }
                doCommit = true;
            }
            if (kc == 0 && s < 3) {
                uint32_t qb2 = sQb[(s + 1) & 1];
                long long qsrc = qrowbase + (long long)(s + 1) * 1024;
#pragma unroll
                for (int j = 0; j < 4; j++)
                    CP16(qb2 + dstOff[j], Qh4 + qsrc + j * 8);
                doCommit = true;
            }
            if (doCommit) CP_COMMIT();
        }

        if (kc == 0) {
            uint32_t qb = sQb[s & 1];
#pragma unroll
            for (int k16 = 0; k16 < 4; k16++) {
                uint32_t off = qoffBase + k16 * 32;
                off ^= (off >> 3) & 0x70;
                LDSM4(qah[k16][0], qah[k16][1], qah[k16][2], qah[k16][3], qb + off);
            }
            m0v = -1e30f; m1v = -1e30f; l0 = 0.f; l1 = 0.f;
#pragma unroll
            for (int t = 0; t < 8; t++)
#pragma unroll
                for (int e = 0; e < 4; e++) o[t][e] = 0.f;
        }

        const uint32_t bs = kvb[c % 3];
        float sc[8][4];
#pragma unroll
        for (int t = 0; t < 8; t++)
#pragma unroll
            for (int e = 0; e < 4; e++) sc[t][e] = 0.f;
#pragma unroll
        for (int k16 = 0; k16 < 4; k16++) {
            uint32_t kh[8][2];
#pragma unroll
            for (int t4 = 0; t4 < 4; t4++) {
                uint32_t off = (t4 * 16 + krowb) * 128 + k16 * 32 + kbyteb;
                off ^= (off >> 3) & 0x70;
                LDSM4(kh[2*t4][0], kh[2*t4][1], kh[2*t4+1][0], kh[2*t4+1][1], bs + off);
            }
#pragma unroll
            for (int j = 0; j < 8; j++)
                MMA16816(sc[j], qah[k16], kh[j]);
        }

        float rmax0 = -1e30f, rmax1 = -1e30f;
#pragma unroll
        for (int t = 0; t < 8; t++) {
            sc[t][0] *= 0.125f; sc[t][1] *= 0.125f; sc[t][2] *= 0.125f; sc[t][3] *= 0.125f;
            rmax0 = fmaxf(rmax0, fmaxf(sc[t][0], sc[t][1]));
            rmax1 = fmaxf(rmax1, fmaxf(sc[t][2], sc[t][3]));
        }
        rmax0 = fmaxf(rmax0, __shfl_xor_sync(0xffffffffu, rmax0, 1));
        rmax0 = fmaxf(rmax0, __shfl_xor_sync(0xffffffffu, rmax0, 2));
        rmax1 = fmaxf(rmax1, __shfl_xor_sync(0xffffffffu, rmax1, 1));
        rmax1 = fmaxf(rmax1, __shfl_xor_sync(0xffffffffu, rmax1, 2));
        float mn0 = fmaxf(m0v, rmax0), mn1 = fmaxf(m1v, rmax1);
        float fac0 = __expf(m0v - mn0), fac1 = __expf(m1v - mn1);
        float rs0 = 0.f, rs1 = 0.f;
#pragma unroll
        for (int t = 0; t < 8; t++) {
            sc[t][0] = __expf(sc[t][0] - mn0); sc[t][1] = __expf(sc[t][1] - mn0);
            sc[t][2] = __expf(sc[t][2] - mn1); sc[t][3] = __expf(sc[t][3] - mn1);
            rs0 += sc[t][0] + sc[t][1];
            rs1 += sc[t][2] + sc[t][3];
        }
        rs0 += __shfl_xor_sync(0xffffffffu, rs0, 1);
        rs0 += __shfl_xor_sync(0xffffffffu, rs0, 2);
        rs1 += __shfl_xor_sync(0xffffffffu, rs1, 1);
        rs1 += __shfl_xor_sync(0xffffffffu, rs1, 2);
        l0 = l0 * fac0 + rs0; l1 = l1 * fac1 + rs1;
        m0v = mn0; m1v = mn1;
#pragma unroll
        for (int t = 0; t < 8; t++) {
            o[t][0] *= fac0; o[t][1] *= fac0; o[t][2] *= fac1; o[t][3] *= fac1;
        }

#pragma unroll
        for (int k16 = 0; k16 < 4; k16++) {
            uint32_t ph[4], pl[4];
            int t = 2 * k16;
            ph[0] = packsplit(sc[t][0],   sc[t][1],   pl[0]);
            ph[1] = packsplit(sc[t][2],   sc[t][3],   pl[1]);
            ph[2] = packsplit(sc[t+1][0], sc[t+1][1], pl[2]);
            ph[3] = packsplit(sc[t+1][2], sc[t+1][3], pl[3]);
            uint32_t vh[8][2];
#pragma unroll
            for (int t4 = 0; t4 < 4; t4++) {
                uint32_t off = (k16 * 16 + vrowb) * 128 + t4 * 32 + vbyteb;
                off ^= (off >> 3) & 0x70;
                LDSM4T(vh[2*t4][0], vh[2*t4][1], vh[2*t4+1][0], vh[2*t4+1][1], bs + 8192 + off);
            }
#pragma unroll
            for (int t8 = 0; t8 < 8; t8++) {
                MMA16816(o[t8], ph, vh[t8]);
                MMA16816(o[t8], pl, vh[t8]);
            }
        }

        if (kc == nch - 1) {
            float ws = w4[s];
            float inv0 = ws / l0, inv1 = ws / l1;
#pragma unroll
            for (int t = 0; t < 8; t++) {
                oacc[t][0] += o[t][0] * inv0;
                oacc[t][1] += o[t][1] * inv0;
                oacc[t][2] += o[t][2] * inv1;
                oacc[t][3] += o[t][3] * inv1;
            }
        }
    }

    int g = lane >> 2;
    int qrow0 = q0 + w * 16 + g;
    long long base0 = ((long long)(b * Ll + qrow0)) * Dd + h * 64;
    long long base1 = base0 + 8LL * Dd;
#pragma unroll
    for (int t = 0; t < 8; t++) {
        int d0 = t * 8 + (lane & 3) * 2;
        *(uint32_t*)(Oh + base0 + d0) = pack2h(oacc[t][0], oacc[t][1]);
        *(uint32_t*)(Oh + base1 + d0) = pack2h(oacc[t][2], oacc[t][3]);
    }
}

// ================= LayerNorm: out = LN(a + r), optional fp16 =================
__global__ __launch_bounds__(256) void ln_kernel(
    const float* __restrict__ a, const float* __restrict__ rr,
    const float* __restrict__ gamma, const float* __restrict__ beta,
    float* __restrict__ out, __half* __restrict__ oh)
{
    __shared__ float red[8], red2[8];
    __shared__ float smu, sinv;
    int row = blockIdx.x, tid = threadIdx.x;
    long long base = (long long)row * Dd;
    float4 va = ((const float4*)(a + base))[tid];
    float4 vr = ((const float4*)(rr + base))[tid];
    float x0 = va.x+vr.x, x1 = va.y+vr.y, x2 = va.z+vr.z, x3 = va.w+vr.w;
    float s  = x0+x1+x2+x3;
    float s2 = x0*x0 + x1*x1 + x2*x2 + x3*x3;
#pragma unroll
    for (int off = 16; off >= 1; off >>= 1) {
        s  += __shfl_xor_sync(0xffffffffu, s,  off);
        s2 += __shfl_xor_sync(0xffffffffu, s2, off);
    }
    int w = tid >> 5, lane = tid & 31;
    if (lane == 0) { red[w] = s; red2[w] = s2; }
    __syncthreads();
    if (tid == 0) {
        float S = 0.f, S2 = 0.f;
        for (int i = 0; i < 8; i++) { S += red[i]; S2 += red2[i]; }
        float mu = S * (1.f/Dd);
        smu = mu;
        sinv = rsqrtf(S2 * (1.f/Dd) - mu*mu + 1e-5f);
    }
    __syncthreads();
    float mu = smu, inv = sinv;
    float4 gg = ((const float4*)gamma)[tid];
    float4 bb = ((const float4*)beta)[tid];
    float y0 = (x0-mu)*inv*gg.x + bb.x;
    float y1 = (x1-mu)*inv*gg.y + bb.y;
    float y2 = (x2-mu)*inv*gg.z + bb.z;
    float y3 = (x3-mu)*inv*gg.w + bb.w;
    float4 y; y.x=y0; y.y=y1; y.z=y2; y.w=y3;
    ((float4*)(out + base))[tid] = y;
    if (oh) {
        ((uint32_t*)(oh + base))[tid*2]   = pack2h(y0, y1);
        ((uint32_t*)(oh + base))[tid*2+1] = pack2h(y2, y3);
    }
}

// ================= preprocessing kernels =================
__global__ void pad_split_kernel(const float* __restrict__ x)
{
    const long long total = (long long)Bb*(Ll+4)*Dd;
    for (long long i = blockIdx.x*256LL + threadIdx.x; i < total; i += (long long)gridDim.x*256LL) {
        int d = (int)(i & (Dd-1));
        long long t = i >> 10;
        int p = (int)(t % (Ll+4));
        int b = (int)(t / (Ll+4));
        float v = 0.f;
        if (p >= 2 && p < Ll+2)
            v = x[((long long)b*Ll + (p-2))*Dd + d];
        g_xph[i] = __float2half_rn(v);
    }
}

__global__ void tdc_split(const float* __restrict__ W)
{
    const long long total = 3LL*Dd*Dd;
    for (long long idx = blockIdx.x*256LL + threadIdx.x; idx < total; idx += (long long)gridDim.x*256LL) {
        int tap = (int)(idx / (Dd*(long long)Dd));
        long long rem = idx - (long long)tap * (Dd*(long long)Dd);
        int o = (int)(rem >> 10), i = (int)(rem & (Dd-1));
        g_wdcth[idx] = __float2half_rn(W[((long long)o*Dd + i)*3 + tap]);
    }
}

__global__ void tdec_split(const float* __restrict__ W)
{
    const long long total = 6LL*Dd*Dd;
    for (long long idx = blockIdx.x*256LL + threadIdx.x; idx < total; idx += (long long)gridDim.x*256LL) {
        int st = (int)(idx / (Dd*(long long)Dd));
        int s = st >> 1, tap = st & 1;
        long long rem = idx - (long long)st * (Dd*(long long)Dd);
        int o = (int)(rem >> 10), i = (int)(rem & (Dd-1));
        g_wdecth[idx] = __float2half_rn(W[(((long long)s*Dd + o)*Dd + i)*2 + tap]);
    }
}

struct CvtJobs {
    const float4* src[6];
    uint2* dst[6];
    long long n4[6];
};
__global__ void cvt16(CvtJobs J, long long tot4)
{
    for (long long i = blockIdx.x*256LL + threadIdx.x; i < tot4; i += (long long)gridDim.x*256LL) {
        long long rr = i; int j = 0;
#pragma unroll
        for (int t = 0; t < 5; t++) if (rr >= J.n4[j]) { rr -= J.n4[j]; j++; }
        float4 v = J.src[j][rr];
        __half2 a = __floats2half2_rn(v.x, v.y), b = __floats2half2_rn(v.z, v.w);
        uint2 oo; oo.x = *(uint32_t*)&a; oo.y = *(uint32_t*)&b;
        J.dst[j][rr] = oo;
    }
}

__global__ void agg_kernel(const float* __restrict__ logits, float* __restrict__ aux)
{
    float mx = -1e30f;
    for (int s = 0; s < Ss; s++) mx = fmaxf(mx, logits[s]);
    float e[Ss], sum = 0.f;
    for (int s = 0; s < Ss; s++) { e[s] = expf(logits[s] - mx); sum += e[s]; }
    float ent = 0.f;
    for (int s = 0; s < Ss; s++) {
        float w = e[s] / sum;
        g_w[s] = w;
        ent -= w * logf(w + 1e-9f);
    }
    if (aux) *aux = ent;
}

__global__ void fill0_kernel(float* p, long long n)
{
    for (long long i = blockIdx.x*256LL + threadIdx.x; i < n; i += (long long)gridDim.x*256LL)
        p[i] = 0.f;
}

// ================= launch =================
extern "C" void kernel_launch(void* const* d_in, const int* in_sizes, int n_in,
                              void* d_out, int out_size)
{
    const float* x     = (const float*)d_in[0];
    const float* W_dc  = (const float*)d_in[1];
    const float* b_dc  = (const float*)d_in[2];
    const float* W_dec = (const float*)d_in[3];
    const float* Wq    = (const float*)d_in[4];
    const float* Wk    = (const float*)d_in[5];
    const float* Wv    = (const float*)d_in[6];
    const float* Wo    = (const float*)d_in[7];
    const float* aggl  = (const float*)d_in[8];
    const float* g1    = (const float*)d_in[9];
    const float* be1   = (const float*)d_in[10];
    const float* g2    = (const float*)d_in[11];
    const float* be2   = (const float*)d_in[12];
    const float* W1    = (const float*)d_in[13];
    const float* b1    = (const float*)d_in[14];
    const float* W2    = (const float*)d_in[15];
    const float* b2    = (const float*)d_in[16];
    float* out = (float*)d_out;

    static int smem_set = 0;
    const int GEMM_SMEM = 3 * 32768;   // 96KB, 2 CTAs/SM
    const int ATTN_SMEM = 4 * 16384;   // 64KB, 2 CTAs/SM
    if (!smem_set) {
        cudaFuncSetAttribute(gemmM0, cudaFuncAttributeMaxDynamicSharedMemorySize, GEMM_SMEM);
        cudaFuncSetAttribute(gemmM1, cudaFuncAttributeMaxDynamicSharedMemorySize, GEMM_SMEM);
        cudaFuncSetAttribute(attnF,  cudaFuncAttributeMaxDynamicSharedMemorySize, ATTN_SMEM);
        smem_set = 1;
    }

#define SYM(v, s) cudaGetSymbolAddress((void**)&v, s)
    __half *xph,*sah,*q4h,*kvh,*ctxh,*x1h,*ffnh;
    __half *wdcth,*wdecth,*wq16,*wk16,*wv16,*wo16,*w116,*w216;
    float *x1,*tmp,*dec,*gw;
    SYM(xph,g_xph); SYM(sah,g_sah);
    SYM(q4h,g_q4h); SYM(kvh,g_kvh);
    SYM(ctxh,g_ctxh); SYM(x1h,g_x1h); SYM(ffnh,g_ffnh);
    SYM(wdcth,g_wdcth); SYM(wdecth,g_wdecth);
    SYM(wq16,g_wq16); SYM(wk16,g_wk16); SYM(wv16,g_wv16); SYM(wo16,g_wo16);
    SYM(w116,g_w116); SYM(w216,g_w216);
    SYM(x1,g_x1); SYM(tmp,g_tmp); SYM(dec,g_dec); SYM(gw,g_w);
#undef SYM

    const int BLD = Bb*Ll*Dd;
    const int4 NOSEG = make_int4(0x7fffffff, 0x7fffffff, 0x7fffffff, 0);
    const int NOSPLIT = 1 << 30;

    // ---- preprocessing ----
    tdc_split <<<1024, 256>>>(W_dc);
    tdec_split<<<2048, 256>>>(W_dec);
    {
        CvtJobs J;
        J.src[0] = (const float4*)Wq; J.dst[0] = (uint2*)wq16; J.n4[0] = 4*DDc/4;
        J.src[1] = (const float4*)Wk; J.dst[1] = (uint2*)wk16; J.n4[1] = 4*DDc/4;
        J.src[2] = (const float4*)Wv; J.dst[2] = (uint2*)wv16; J.n4[2] = DDc/4;
        J.src[3] = (const float4*)Wo; J.dst[3] = (uint2*)wo16; J.n4[3] = DDc/4;
        J.src[4] = (const float4*)W1; J.dst[4] = (uint2*)w116; J.n4[4] = (long long)Dd*Ff/4;
        J.src[5] = (const float4*)W2; J.dst[5] = (uint2*)w216; J.n4[5] = (long long)Dd*Ff/4;
        long long tot4 = J.n4[0]+J.n4[1]+J.n4[2]+J.n4[3]+J.n4[4]+J.n4[5];
        cvt16<<<2048, 256>>>(J, tot4);
    }
    pad_split_kernel<<<4096, 256>>>(x);
    if (out_size > BLD) {
        long long gap = (long long)out_size - BLD;
        fill0_kernel<<<256, 256>>>(out + BLD, gap);
        agg_kernel<<<1, 1>>>(aggl, out + out_size - 1);
    } else {
        agg_kernel<<<1, 1>>>(aggl, (float*)0);
    }

    // ---- conv GEMM (BT=0, z=1) ----
    gemmM0<<<dim3(Dd/128, (Bb*Ll)/128), 256, GEMM_SMEM>>>(
        xph, wdcth, (const __half*)0, 0, sah, b_dc,
        Dd, Dd, 0, NOSPLIT, 30,
        3, 2LL*Dd, Ll, (long long)(Ll+4)*Dd, Dd, 0, 1, NOSEG, 0, 0);

    // ---- hierarchical decomposition: split-K x4 + deterministic reduce ----
    {
        const long long inOff[3]  = {0, 4096, 6144};
        const long long outOff[3] = {4096, 6144, 7168};
        int Lin[3] = {1024, 512, 256};
        for (int s = 0; s < 3; s++) {
            int M = Bb*(Lin[s]/2);
            long long cnt = (long long)M * Dd;
            gemmM0<<<dim3(Dd/128, M/128, 4), 256, GEMM_SMEM>>>(
                sah + inOff[s]*Dd, wdecth + (long long)s*2*DDc, (const __half*)0,
                dec, 0, 0,
                Dd, Dd, 0, NOSPLIT, 30,
                2, (long long)Dd, Lin[s]/2, (long long)Lin[s]*Dd, 2*Dd, 0, 0, NOSEG, 0, cnt);
            cvt_dec<<<1024, 256>>>(dec, cnt, sah + outOff[s]*Dd, cnt);
        }
    }

    // ---- projection / FFN GEMMs (BT=1) ----
    gemmM1<<<dim3(4*Dd/128, (Bb*Ll)/128), 256, GEMM_SMEM>>>(
        sah, wq16, (const __half*)0, 0, q4h, 0,
        4*Dd, Dd, Dd, NOSPLIT, 10,
        1, 0, Bb*Ll, 0, Dd, 0, 0, NOSEG, DDc, 0);

    gemmM1<<<dim3(2048/128, SAR/128), 256, GEMM_SMEM>>>(
        sah, wk16, wv16, 0, kvh, 0,
        2048, Dd, Dd, 1024, 30,
        1, 0, SAR, 0, Dd, 0, 0,
        make_int4(4096, 6144, 7168, 0), DDc, 0);

    {
        dim3 ag(Ll/64, Hh, Bb);
        attnF<<<ag, 128, ATTN_SMEM>>>(q4h, kvh, ctxh, gw);
    }

    gemmM1<<<dim3(Dd/128, (Bb*Ll)/128), 256, GEMM_SMEM>>>(
        ctxh, wo16, (const __half*)0, tmp, 0, 0,
        Dd, Dd, Dd, NOSPLIT, 30,
        1, 0, Bb*Ll, 0, Dd, 0, 0, NOSEG, 0, 0);

    ln_kernel<<<Bb*Ll, 256>>>(x, tmp, g1, be1, x1, x1h);

    gemmM1<<<dim3(Ff/128, (Bb*Ll)/128), 256, GEMM_SMEM>>>(
        x1h, w116, (const __half*)0, 0, ffnh, b1,
        Ff, Dd, Ff, NOSPLIT, 30,
        1, 0, Bb*Ll, 0, Dd, 0, 2, NOSEG, 0, 0);
    gemmM1<<<dim3(Dd/128, (Bb*Ll)/128), 256, GEMM_SMEM>>>(
        ffnh, w216, (const __half*)0, tmp, 0, b2,
        Dd, Ff, Dd, NOSPLIT, 30,
        1, 0, Bb*Ll, 0, Ff, 0, 0, NOSEG, 0, 0);

    ln_kernel<<<Bb*Ll, 256>>>(x1, tmp, g2, be2, out, (__half*)0);
}

// round 11
// speedup vs baseline: 6.3393x; 1.0334x over previous
#include <cuda_runtime.h>
#include <cuda_fp16.h>
#include <math.h>
#include <stdint.h>

#define Bb 4
#define Ll 1024
#define Dd 1024
#define Hh 16
#define Ff 4096
#define Ss 4
#define DDc (1024LL*1024LL)
#define SAR 7680   // total scale-activation rows: 4096+2048+1024+512

// ================= static scratch (no allocations) =================
__device__ __align__(256) __half g_xph[Bb*(Ll+4)*Dd];
__device__ __align__(256) __half g_sah[SAR*Dd];                    // xc|s1|s2|s3
__device__ __align__(256) __half g_q4h[Bb*Ll*4*Dd];                // [4096][4096]
__device__ __align__(256) __half g_kvh[SAR*2048];                  // [7680][2048] K|V
__device__ __align__(256) __half g_ctxh[Bb*Ll*Dd];
__device__ __align__(256) __half g_x1h[Bb*Ll*Dd];
__device__ __align__(256) __half g_ffnh[Bb*Ll*Ff];
__device__ __align__(256) __half g_wdcth[3*1024*1024];             // [tap][N][K]
__device__ __align__(256) __half g_wdecth[6*1024*1024];            // [s*2+tap][N][K]
__device__ __align__(256) __half g_wq16[4*1024*1024];              // fp16 copies, natural [K][N]
__device__ __align__(256) __half g_wk16[4*1024*1024];
__device__ __align__(256) __half g_wv16[1024*1024];
__device__ __align__(256) __half g_wo16[1024*1024];
__device__ __align__(256) __half g_w116[1024*4096];
__device__ __align__(256) __half g_w216[4096*1024];
__device__ __align__(256) float g_x1[Bb*Ll*Dd];
__device__ __align__(256) float g_tmp[Bb*Ll*Dd];
__device__ __align__(256) float g_dec[4*2048*1024];                // split-K partials (32MB)
__device__ float g_w[Ss];

// ================= PTX helpers (base features only) =================
#define CP16(dst, src)    asm volatile("cp.async.cg.shared.global [%0], [%1], 16;" :: "r"(dst), "l"(src) : "memory")
#define CP_COMMIT()       asm volatile("cp.async.commit_group;" ::: "memory")
#define CP_WAIT1()        asm volatile("cp.async.wait_group 1;" ::: "memory")
#define CP_WAIT0()        asm volatile("cp.async.wait_group 0;" ::: "memory")

#define LDSM4(r0,r1,r2,r3,addr) \
    asm volatile("ldmatrix.sync.aligned.m8n8.x4.shared.b16 {%0,%1,%2,%3}, [%4];" \
        : "=r"(r0),"=r"(r1),"=r"(r2),"=r"(r3) : "r"(addr))
#define LDSM4T(r0,r1,r2,r3,addr) \
    asm volatile("ldmatrix.sync.aligned.m8n8.x4.trans.shared.b16 {%0,%1,%2,%3}, [%4];" \
        : "=r"(r0),"=r"(r1),"=r"(r2),"=r"(r3) : "r"(addr))
#define LDSM2(r0,r1,addr) \
    asm volatile("ldmatrix.sync.aligned.m8n8.x2.shared.b16 {%0,%1}, [%2];" \
        : "=r"(r0),"=r"(r1) : "r"(addr))
#define MMA16816(d, a, b) \
    asm volatile("mma.sync.aligned.m16n8k16.row.col.f32.f16.f16.f32 " \
        "{%0,%1,%2,%3}, {%4,%5,%6,%7}, {%8,%9}, {%0,%1,%2,%3};" \
        : "+f"((d)[0]),"+f"((d)[1]),"+f"((d)[2]),"+f"((d)[3]) \
        : "r"((a)[0]),"r"((a)[1]),"r"((a)[2]),"r"((a)[3]), "r"((b)[0]),"r"((b)[1]))

__device__ __forceinline__ uint32_t smem_u32(const void* p) {
    uint32_t a;
    asm("{ .reg .u64 t; cvta.to.shared.u64 t, %1; cvt.u32.u64 %0, t; }" : "=r"(a) : "l"(p));
    return a;
}

__device__ __forceinline__ uint32_t pack2h(float a, float b) {
    __half2 h2 = __floats2half2_rn(a, b);
    return *(uint32_t*)&h2;
}

// ================= mma.sync fp16 GEMM: 3-stage, optional B-trans, optional split-K =================
template<int BT>
__device__ __forceinline__ void gemm_body(
    const __half* __restrict__ Ah, const __half* __restrict__ Bh, const __half* __restrict__ B2,
    float* __restrict__ Cf, __half* __restrict__ Oh, const float* __restrict__ bias,
    int N, int K, int NB, int nSplit, int nSegShift,
    int taps, long long tapStrideA,
    int lseg, long long segStride, int rowStride, long long offA, int epi,
    int4 segEnd, long long segUnit, long long zCfStride)
{
    extern __shared__ char smem[];
    uint32_t sb = smem_u32(smem);
    const int tid = threadIdx.x;
    const int wid = tid >> 5, lane = tid & 31;
    const int m0 = blockIdx.y * 128, n0 = blockIdx.x * 128;

    const __half* Bsel;
    int ncol = n0;
    if (BT) {
        if (n0 >= nSplit) { Bsel = B2; ncol = n0 - nSplit; }
        else {
            int nseg = n0 >> nSegShift;
            int mseg = (m0 >= segEnd.x) + (m0 >= segEnd.y) + (m0 >= segEnd.z);
            Bsel = Bh + (long long)(nseg + mseg) * segUnit;
            ncol = n0 & ((1 << nSegShift) - 1);
        }
    } else {
        int mseg = (m0 >= segEnd.x) + (m0 >= segEnd.y) + (m0 >= segEnd.z);
        Bsel = Bh + (long long)mseg * segUnit;
    }

    const int r = tid >> 1, half_ = tid & 1;
    const long long mrow = m0 + r;
    const long long aoff0 = (mrow / lseg) * segStride + (mrow % lseg) * (long long)rowStride + offA + half_ * 32;
    uint32_t dstOffA[4];
#pragma unroll
    for (int j = 0; j < 4; j++) {
        uint32_t off = (uint32_t)(r * 128 + half_ * 64 + j * 16);
        dstOffA[j] = off ^ ((off >> 3) & 0x70);
    }
    const int brow = tid >> 2, bq = tid & 3;
    uint32_t bDst[4];
    long long boff0 = 0;
    if (BT) {
#pragma unroll
        for (int j = 0; j < 4; j++) {
            int bp = bq * 64 + j * 16;
            uint32_t raw = (uint32_t)(brow * 128 + (bp & 127));
            bDst[j] = (uint32_t)((bp >> 7) * 8192) + (raw ^ ((raw >> 3) & 0x70));
        }
        boff0 = (long long)brow * NB + ncol + bq * 32;
    } else {
        boff0 = (long long)(n0 + r) * K + half_ * 32;
    }

    const uint32_t bufBase[3] = { sb, sb + 32768, sb + 65536 };
    const int NCk = K >> 6;
    const int NCtot = NCk * taps;
    const int NCz = NCtot / (int)gridDim.z;
    const int c0 = (int)blockIdx.z * NCz;
    const int cEnd = c0 + NCz;
    const long long tapStrideB = (long long)N * K;

    auto issue = [&](int c) {
        uint32_t bs = bufBase[c % 3];
        int tap = c / NCk, kc = c - tap * NCk;
        long long ao = aoff0 + (long long)tap * tapStrideA + kc * 64;
#pragma unroll
        for (int j = 0; j < 4; j++) CP16(bs + dstOffA[j], Ah + ao + j * 8);
        if (BT) {
            long long bo = boff0 + (long long)c * 64 * NB;
#pragma unroll
            for (int j = 0; j < 4; j++) CP16(bs + 16384 + bDst[j], Bsel + bo + j * 8);
        } else {
            long long bo = boff0 + (long long)tap * tapStrideB + kc * 64;
#pragma unroll
            for (int j = 0; j < 4; j++) CP16(bs + 16384 + dstOffA[j], Bsel + bo + j * 8);
        }
        CP_COMMIT();
    };

    const int wm = wid & 1, wn = wid >> 1;
    const int arow = wm * 64 + (lane & 15);
    const uint32_t aRowOff = (uint32_t)(arow * 128);
    const uint32_t aXb = (uint32_t)((arow & 7) << 4);
    const uint32_t aHalf = (uint32_t)((lane >> 4) * 16);
    const uint32_t bRowOff = (uint32_t)((wn * 32 + (lane & 7)) * 128);
    const uint32_t bXb = (uint32_t)((lane & 7) << 4);
    const uint32_t bHalf = (uint32_t)(((lane >> 3) & 1) * 16);
    const uint32_t vrowb = (uint32_t)((lane & 7) + ((lane >> 3) & 1) * 8);
    const uint32_t vbyteb = (uint32_t)(((lane >> 4) & 1) * 16);
    const uint32_t warpNb = (uint32_t)((wn & 1) * 64);
    const uint32_t subSel = (uint32_t)((wn >> 1) * 8192);

    float acc[4][4][4];
#pragma unroll
    for (int i = 0; i < 4; i++)
#pragma unroll
        for (int j = 0; j < 4; j++)
#pragma unroll
            for (int e = 0; e < 4; e++) acc[i][j][e] = 0.f;

    issue(c0); issue(c0 + 1);

#pragma unroll 1
    for (int c = c0; c < cEnd; c++) {
        if (c == cEnd - 1) CP_WAIT0(); else CP_WAIT1();
        __syncthreads();
        if (c + 2 < cEnd) issue(c + 2);

        const uint32_t bs = bufBase[c % 3];
#pragma unroll
        for (int k16 = 0; k16 < 4; k16++) {
            const uint32_t aoff = aRowOff + ((k16 * 32 + aHalf) ^ aXb);
            uint32_t ah[4][4], bh[4][2];
#pragma unroll
            for (int i = 0; i < 4; i++)
                LDSM4(ah[i][0], ah[i][1], ah[i][2], ah[i][3], bs + i * 2048 + aoff);
            if (BT) {
                uint32_t subB = bs + 16384 + subSel;
#pragma unroll
                for (int t2 = 0; t2 < 2; t2++) {
                    uint32_t off = (k16 * 16 + vrowb) * 128 + warpNb + t2 * 32 + vbyteb;
                    off ^= (off >> 3) & 0x70;
                    LDSM4T(bh[2*t2][0], bh[2*t2][1], bh[2*t2+1][0], bh[2*t2+1][1], subB + off);
                }
            } else {
                const uint32_t boff = bRowOff + ((k16 * 32 + bHalf) ^ bXb);
#pragma unroll
                for (int j = 0; j < 4; j++)
                    LDSM2(bh[j][0], bh[j][1], bs + 16384 + j * 1024 + boff);
            }
#pragma unroll
            for (int i = 0; i < 4; i++)
#pragma unroll
                for (int j = 0; j < 4; j++)
                    MMA16816(acc[i][j], ah[i], bh[j]);
        }
    }

    if (Cf) Cf += (long long)blockIdx.z * zCfStride;
#pragma unroll
    for (int i = 0; i < 4; i++)
#pragma unroll
        for (int j = 0; j < 4; j++)
#pragma unroll
            for (int p = 0; p < 2; p++) {
                int rr = m0 + wm * 64 + i * 16 + (lane >> 2) + p * 8;
                int cc = n0 + wn * 32 + j * 8 + (lane & 3) * 2;
                float v0 = acc[i][j][p * 2];
                float v1 = acc[i][j][p * 2 + 1];
                if (bias) { v0 += bias[cc]; v1 += bias[cc + 1]; }
                if (epi == 1) { v0 = fmaxf(v0, 0.f); v1 = fmaxf(v1, 0.f); }
                else if (epi == 2) {
                    v0 = 0.5f * v0 * (1.f + erff(v0 * 0.70710678118654752f));
                    v1 = 0.5f * v1 * (1.f + erff(v1 * 0.70710678118654752f));
                }
                long long idx = (long long)rr * N + cc;
                if (Cf) { float2 f; f.x = v0; f.y = v1; *(float2*)(Cf + idx) = f; }
                if (Oh) *(uint32_t*)(Oh + idx) = pack2h(v0, v1);
            }
}

__global__ __launch_bounds__(256, 2) void gemmM0(
    const __half* __restrict__ Ah, const __half* __restrict__ Bh, const __half* __restrict__ B2,
    float* __restrict__ Cf, __half* __restrict__ Oh, const float* __restrict__ bias,
    int N, int K, int NB, int nSplit, int nSegShift,
    int taps, long long tapStrideA, int lseg, long long segStride, int rowStride,
    long long offA, int epi, int4 segEnd, long long segUnit, long long zCfStride)
{
    gemm_body<0>(Ah, Bh, B2, Cf, Oh, bias, N, K, NB, nSplit, nSegShift,
                 taps, tapStrideA, lseg, segStride, rowStride, offA, epi, segEnd, segUnit, zCfStride);
}

__global__ __launch_bounds__(256, 2) void gemmM1(
    const __half* __restrict__ Ah, const __half* __restrict__ Bh, const __half* __restrict__ B2,
    float* __restrict__ Cf, __half* __restrict__ Oh, const float* __restrict__ bias,
    int N, int K, int NB, int nSplit, int nSegShift,
    int taps, long long tapStrideA, int lseg, long long segStride, int rowStride,
    long long offA, int epi, int4 segEnd, long long segUnit, long long zCfStride)
{
    gemm_body<1>(Ah, Bh, B2, Cf, Oh, bias, N, K, NB, nSplit, nSegShift,
                 taps, tapStrideA, lseg, segStride, rowStride, offA, epi, segEnd, segUnit, zCfStride);
}

// sum 4 split-K fp32 partials -> fp16 (fixed order, deterministic)
__global__ void cvt_dec(const float* __restrict__ scr, long long zStride,
                        __half* __restrict__ dst, long long n)
{
    for (long long i = blockIdx.x*256LL + threadIdx.x; i * 2 < n; i += (long long)gridDim.x*256LL) {
        long long e = i * 2;
        float2 a = *(const float2*)(scr + e);
        float2 b = *(const float2*)(scr + e + zStride);
        float2 c = *(const float2*)(scr + e + 2*zStride);
        float2 d = *(const float2*)(scr + e + 3*zStride);
        float v0 = ((a.x + b.x) + (c.x + d.x));
        float v1 = ((a.y + b.y) + (c.y + d.y));
        *(uint32_t*)(dst + e) = pack2h(v0, v1);
    }
}

// ================= fused 4-scale flash attention (fp16; 3-stage KV) =================
__global__ __launch_bounds__(128, 2) void attnF(
    const __half* __restrict__ Qh4, const __half* __restrict__ KVh,
    __half* __restrict__ Oh, const float* __restrict__ gw)
{
    extern __shared__ char smem[];
    uint32_t sb = smem_u32(smem);
    const int tid = threadIdx.x;
    const int w = tid >> 5, lane = tid & 31;
    const int b = blockIdx.z, h = blockIdx.y;
    const int q0 = blockIdx.x * 64;

    float w4[4];
#pragma unroll
    for (int s = 0; s < 4; s++) w4[s] = gw[s];

    const int r = tid >> 1, half_ = tid & 1;
    uint32_t dstOff[4];
#pragma unroll
    for (int j = 0; j < 4; j++) {
        uint32_t off = (uint32_t)(r * 128 + half_ * 64 + j * 16);
        dstOff[j] = off ^ ((off >> 3) & 0x70);
    }
    const uint32_t sQb[2] = { sb, sb + 8192 };
    const uint32_t kvb[3] = { sb + 16384, sb + 32768, sb + 49152 };

    const long long qrowbase = ((long long)(b * Ll + q0 + r)) * 4096 + h * 64 + half_ * 32;

    auto kvRow = [&](int cc) -> long long {
        int s2  = (cc < 16) ? 0 : (cc < 24) ? 1 : (cc < 28) ? 2 : 3;
        int bas = (s2 == 0) ? 0 : (s2 == 1) ? 16 : (s2 == 2) ? 24 : 28;
        int Ls2 = (s2 == 0) ? 1024 : (s2 == 1) ? 512 : (s2 == 2) ? 256 : 128;
        int ro2 = (s2 == 0) ? 0 : (s2 == 1) ? 4096 : (s2 == 2) ? 6144 : 7168;
        int kc2 = cc - bas;
        return ((long long)(ro2 + b * Ls2 + kc2 * 64 + r)) * 2048 + h * 64 + half_ * 32;
    };

    {
#pragma unroll
        for (int j = 0; j < 4; j++)
            CP16(sQb[0] + dstOff[j], Qh4 + qrowbase + j * 8);
        long long kr = kvRow(0);
#pragma unroll
        for (int j = 0; j < 4; j++) {
            CP16(kvb[0]        + dstOff[j], KVh + kr + j * 8);
            CP16(kvb[0] + 8192 + dstOff[j], KVh + kr + 1024 + j * 8);
        }
        CP_COMMIT();
        kr = kvRow(1);
#pragma unroll
        for (int j = 0; j < 4; j++) {
            CP16(kvb[1]        + dstOff[j], KVh + kr + j * 8);
            CP16(kvb[1] + 8192 + dstOff[j], KVh + kr + 1024 + j * 8);
        }
        CP_COMMIT();
    }

    const uint32_t qoffBase = (uint32_t)((w * 16 + (lane & 15)) * 128 + ((lane >> 4) & 1) * 16);
    const uint32_t krowb = (uint32_t)((lane & 7) + ((lane >> 4) & 1) * 8);
    const uint32_t kbyteb = (uint32_t)(((lane >> 3) & 1) * 16);
    const uint32_t vrowb = (uint32_t)((lane & 7) + ((lane >> 3) & 1) * 8);
    const uint32_t vbyteb = (uint32_t)(((lane >> 4) & 1) * 16);

    uint32_t qah[4][4];
    float oacc[8][4];
#pragma unroll
    for (int t = 0; t < 8; t++)
#pragma unroll
        for (int e = 0; e < 4; e++) oacc[t][e] = 0.f;
    float o[8][4];
    float m0v = -1e30f, m1v = -1e30f, l0 = 0.f, l1 = 0.f;

#pragma unroll 1
    for (int c = 0; c < 30; c++) {
        const int s  = (c < 16) ? 0 : (c < 24) ? 1 : (c < 28) ? 2 : 3;
        const int bas = (s == 0) ? 0 : (s == 1) ? 16 : (s == 2) ? 24 : 28;
        const int nch = (s == 0) ? 16 : (s == 1) ? 8 : (s == 2) ? 4 : 2;
        const int kc = c - bas;

        if (c == 29) CP_WAIT0(); else CP_WAIT1();
        __syncthreads();

        {
            bool doCommit = false;
            int cc = c + 2;
            if (cc < 30) {
                long long kr = kvRow(cc);
                uint32_t bs2 = kvb[cc % 3];
#pragma unroll
                for (int j = 0; j < 4; j++) {
                    CP16(bs2        + dstOff[j], KVh + kr + j * 8);
                    CP16(bs2 + 8192 + dstOff[j], KVh + kr + 1024 + j * 8);
                }
                doCommit = true;
            }
            if (kc == 0 && s < 3) {
                uint32_t qb2 = sQb[(s + 1) & 1];
                long long qsrc = qrowbase + (long long)(s + 1) * 1024;
#pragma unroll
                for (int j = 0; j < 4; j++)
                    CP16(qb2 + dstOff[j], Qh4 + qsrc + j * 8);
                doCommit = true;
            }
            if (doCommit) CP_COMMIT();
        }

        if (kc == 0) {
            uint32_t qb = sQb[s & 1];
#pragma unroll
            for (int k16 = 0; k16 < 4; k16++) {
                uint32_t off = qoffBase + k16 * 32;
                off ^= (off >> 3) & 0x70;
                LDSM4(qah[k16][0], qah[k16][1], qah[k16][2], qah[k16][3], qb + off);
            }
            m0v = -1e30f; m1v = -1e30f; l0 = 0.f; l1 = 0.f;
#pragma unroll
            for (int t = 0; t < 8; t++)
#pragma unroll
                for (int e = 0; e < 4; e++) o[t][e] = 0.f;
        }

        const uint32_t bs = kvb[c % 3];
        float sc[8][4];
#pragma unroll
        for (int t = 0; t < 8; t++)
#pragma unroll
            for (int e = 0; e < 4; e++) sc[t][e] = 0.f;
#pragma unroll
        for (int k16 = 0; k16 < 4; k16++) {
            uint32_t kh[8][2];
#pragma unroll
            for (int t4 = 0; t4 < 4; t4++) {
                uint32_t off = (t4 * 16 + krowb) * 128 + k16 * 32 + kbyteb;
                off ^= (off >> 3) & 0x70;
                LDSM4(kh[2*t4][0], kh[2*t4][1], kh[2*t4+1][0], kh[2*t4+1][1], bs + off);
            }
#pragma unroll
            for (int j = 0; j < 8; j++)
                MMA16816(sc[j], qah[k16], kh[j]);
        }

        float rmax0 = -1e30f, rmax1 = -1e30f;
#pragma unroll
        for (int t = 0; t < 8; t++) {
            sc[t][0] *= 0.125f; sc[t][1] *= 0.125f; sc[t][2] *= 0.125f; sc[t][3] *= 0.125f;
            rmax0 = fmaxf(rmax0, fmaxf(sc[t][0], sc[t][1]));
            rmax1 = fmaxf(rmax1, fmaxf(sc[t][2], sc[t][3]));
        }
        rmax0 = fmaxf(rmax0, __shfl_xor_sync(0xffffffffu, rmax0, 1));
        rmax0 = fmaxf(rmax0, __shfl_xor_sync(0xffffffffu, rmax0, 2));
        rmax1 = fmaxf(rmax1, __shfl_xor_sync(0xffffffffu, rmax1, 1));
        rmax1 = fmaxf(rmax1, __shfl_xor_sync(0xffffffffu, rmax1, 2));
        float mn0 = fmaxf(m0v, rmax0), mn1 = fmaxf(m1v, rmax1);
        float fac0 = __expf(m0v - mn0), fac1 = __expf(m1v - mn1);
        float rs0 = 0.f, rs1 = 0.f;
#pragma unroll
        for (int t = 0; t < 8; t++) {
            sc[t][0] = __expf(sc[t][0] - mn0); sc[t][1] = __expf(sc[t][1] - mn0);
            sc[t][2] = __expf(sc[t][2] - mn1); sc[t][3] = __expf(sc[t][3] - mn1);
            rs0 += sc[t][0] + sc[t][1];
            rs1 += sc[t][2] + sc[t][3];
        }
        rs0 += __shfl_xor_sync(0xffffffffu, rs0, 1);
        rs0 += __shfl_xor_sync(0xffffffffu, rs0, 2);
        rs1 += __shfl_xor_sync(0xffffffffu, rs1, 1);
        rs1 += __shfl_xor_sync(0xffffffffu, rs1, 2);
        l0 = l0 * fac0 + rs0; l1 = l1 * fac1 + rs1;
        m0v = mn0; m1v = mn1;
#pragma unroll
        for (int t = 0; t < 8; t++) {
            o[t][0] *= fac0; o[t][1] *= fac0; o[t][2] *= fac1; o[t][3] *= fac1;
        }

        // ---- O += P V (P hi only) ----
#pragma unroll
        for (int k16 = 0; k16 < 4; k16++) {
            uint32_t ph[4];
            int t = 2 * k16;
            ph[0] = pack2h(sc[t][0],   sc[t][1]);
            ph[1] = pack2h(sc[t][2],   sc[t][3]);
            ph[2] = pack2h(sc[t+1][0], sc[t+1][1]);
            ph[3] = pack2h(sc[t+1][2], sc[t+1][3]);
            uint32_t vh[8][2];
#pragma unroll
            for (int t4 = 0; t4 < 4; t4++) {
                uint32_t off = (k16 * 16 + vrowb) * 128 + t4 * 32 + vbyteb;
                off ^= (off >> 3) & 0x70;
                LDSM4T(vh[2*t4][0], vh[2*t4][1], vh[2*t4+1][0], vh[2*t4+1][1], bs + 8192 + off);
            }
#pragma unroll
            for (int t8 = 0; t8 < 8; t8++)
                MMA16816(o[t8], ph, vh[t8]);
        }

        if (kc == nch - 1) {
            float ws = w4[s];
            float inv0 = ws / l0, inv1 = ws / l1;
#pragma unroll
            for (int t = 0; t < 8; t++) {
                oacc[t][0] += o[t][0] * inv0;
                oacc[t][1] += o[t][1] * inv0;
                oacc[t][2] += o[t][2] * inv1;
                oacc[t][3] += o[t][3] * inv1;
            }
        }
    }

    int g = lane >> 2;
    int qrow0 = q0 + w * 16 + g;
    long long base0 = ((long long)(b * Ll + qrow0)) * Dd + h * 64;
    long long base1 = base0 + 8LL * Dd;
#pragma unroll
    for (int t = 0; t < 8; t++) {
        int d0 = t * 8 + (lane & 3) * 2;
        *(uint32_t*)(Oh + base0 + d0) = pack2h(oacc[t][0], oacc[t][1]);
        *(uint32_t*)(Oh + base1 + d0) = pack2h(oacc[t][2], oacc[t][3]);
    }
}

// ================= LayerNorm: out = LN(a + r), optional fp16 =================
__global__ __launch_bounds__(256) void ln_kernel(
    const float* __restrict__ a, const float* __restrict__ rr,
    const float* __restrict__ gamma, const float* __restrict__ beta,
    float* __restrict__ out, __half* __restrict__ oh)
{
    __shared__ float red[8], red2[8];
    __shared__ float smu, sinv;
    int row = blockIdx.x, tid = threadIdx.x;
    long long base = (long long)row * Dd;
    float4 va = ((const float4*)(a + base))[tid];
    float4 vr = ((const float4*)(rr + base))[tid];
    float x0 = va.x+vr.x, x1 = va.y+vr.y, x2 = va.z+vr.z, x3 = va.w+vr.w;
    float s  = x0+x1+x2+x3;
    float s2 = x0*x0 + x1*x1 + x2*x2 + x3*x3;
#pragma unroll
    for (int off = 16; off >= 1; off >>= 1) {
        s  += __shfl_xor_sync(0xffffffffu, s,  off);
        s2 += __shfl_xor_sync(0xffffffffu, s2, off);
    }
    int w = tid >> 5, lane = tid & 31;
    if (lane == 0) { red[w] = s; red2[w] = s2; }
    __syncthreads();
    if (tid == 0) {
        float S = 0.f, S2 = 0.f;
        for (int i = 0; i < 8; i++) { S += red[i]; S2 += red2[i]; }
        float mu = S * (1.f/Dd);
        smu = mu;
        sinv = rsqrtf(S2 * (1.f/Dd) - mu*mu + 1e-5f);
    }
    __syncthreads();
    float mu = smu, inv = sinv;
    float4 gg = ((const float4*)gamma)[tid];
    float4 bb = ((const float4*)beta)[tid];
    float y0 = (x0-mu)*inv*gg.x + bb.x;
    float y1 = (x1-mu)*inv*gg.y + bb.y;
    float y2 = (x2-mu)*inv*gg.z + bb.z;
    float y3 = (x3-mu)*inv*gg.w + bb.w;
    float4 y; y.x=y0; y.y=y1; y.z=y2; y.w=y3;
    ((float4*)(out + base))[tid] = y;
    if (oh) {
        ((uint32_t*)(oh + base))[tid*2]   = pack2h(y0, y1);
        ((uint32_t*)(oh + base))[tid*2+1] = pack2h(y2, y3);
    }
}

// ================= preprocessing kernels (vectorized, coalesced) =================
// pad+convert x: per-iter handles 4 contiguous d (float4 read, uint2 write)
__global__ void pad_split_kernel(const float* __restrict__ x)
{
    const long long total4 = (long long)Bb*(Ll+4)*Dd/4;
    for (long long i4 = blockIdx.x*256LL + threadIdx.x; i4 < total4; i4 += (long long)gridDim.x*256LL) {
        long long i = i4 * 4;
        int d = (int)(i & (Dd-1));
        long long t = i >> 10;
        int p = (int)(t % (Ll+4));
        int b = (int)(t / (Ll+4));
        uint2 oo;
        if (p >= 2 && p < Ll+2) {
            float4 v = *(const float4*)(x + (((long long)b*Ll + (p-2)) << 10) + d);
            oo.x = pack2h(v.x, v.y); oo.y = pack2h(v.z, v.w);
        } else {
            oo.x = 0u; oo.y = 0u;
        }
        *(uint2*)(g_xph + i) = oo;
    }
}

// W_dc [o][i][3] -> 3 planes [tap][o*D+i]; contiguous 12B reads, coalesced plane writes
__global__ void tdc_split(const float* __restrict__ W)
{
    const long long total = DDc;
    for (long long idx = blockIdx.x*256LL + threadIdx.x; idx < total; idx += (long long)gridDim.x*256LL) {
        const float* p = W + idx * 3;
        g_wdcth[idx]         = __float2half_rn(p[0]);
        g_wdcth[DDc + idx]   = __float2half_rn(p[1]);
        g_wdcth[2*DDc + idx] = __float2half_rn(p[2]);
    }
}

// W_dec [s][o][i][2] -> planes [(s*2+tap)][o*D+i]; float2 reads, coalesced writes
__global__ void tdec_split(const float* __restrict__ W)
{
    const long long total = 3*DDc;
    for (long long idx = blockIdx.x*256LL + threadIdx.x; idx < total; idx += (long long)gridDim.x*256LL) {
        int s = (int)(idx / DDc);
        long long rem = idx - (long long)s * DDc;
        float2 v = *(const float2*)(W + idx * 2);
        g_wdecth[(long long)(2*s)   * DDc + rem] = __float2half_rn(v.x);
        g_wdecth[(long long)(2*s+1) * DDc + rem] = __float2half_rn(v.y);
    }
}

struct CvtJobs {
    const float4* src[6];
    uint2* dst[6];
    long long n4[6];
};
__global__ void cvt16(CvtJobs J, long long tot4)
{
    for (long long i = blockIdx.x*256LL + threadIdx.x; i < tot4; i += (long long)gridDim.x*256LL) {
        long long rr = i; int j = 0;
#pragma unroll
        for (int t = 0; t < 5; t++) if (rr >= J.n4[j]) { rr -= J.n4[j]; j++; }
        float4 v = J.src[j][rr];
        uint2 oo; oo.x = pack2h(v.x, v.y); oo.y = pack2h(v.z, v.w);
        J.dst[j][rr] = oo;
    }
}

__global__ void agg_kernel(const float* __restrict__ logits, float* __restrict__ aux)
{
    float mx = -1e30f;
    for (int s = 0; s < Ss; s++) mx = fmaxf(mx, logits[s]);
    float e[Ss], sum = 0.f;
    for (int s = 0; s < Ss; s++) { e[s] = expf(logits[s] - mx); sum += e[s]; }
    float ent = 0.f;
    for (int s = 0; s < Ss; s++) {
        float w = e[s] / sum;
        g_w[s] = w;
        ent -= w * logf(w + 1e-9f);
    }
    if (aux) *aux = ent;
}

__global__ void fill0_kernel(float* p, long long n)
{
    for (long long i = blockIdx.x*256LL + threadIdx.x; i < n; i += (long long)gridDim.x*256LL)
        p[i] = 0.f;
}

// ================= launch =================
extern "C" void kernel_launch(void* const* d_in, const int* in_sizes, int n_in,
                              void* d_out, int out_size)
{
    const float* x     = (const float*)d_in[0];
    const float* W_dc  = (const float*)d_in[1];
    const float* b_dc  = (const float*)d_in[2];
    const float* W_dec = (const float*)d_in[3];
    const float* Wq    = (const float*)d_in[4];
    const float* Wk    = (const float*)d_in[5];
    const float* Wv    = (const float*)d_in[6];
    const float* Wo    = (const float*)d_in[7];
    const float* aggl  = (const float*)d_in[8];
    const float* g1    = (const float*)d_in[9];
    const float* be1   = (const float*)d_in[10];
    const float* g2    = (const float*)d_in[11];
    const float* be2   = (const float*)d_in[12];
    const float* W1    = (const float*)d_in[13];
    const float* b1    = (const float*)d_in[14];
    const float* W2    = (const float*)d_in[15];
    const float* b2    = (const float*)d_in[16];
    float* out = (float*)d_out;

    static int smem_set = 0;
    const int GEMM_SMEM = 3 * 32768;   // 96KB, 2 CTAs/SM
    const int ATTN_SMEM = 4 * 16384;   // 64KB, 2 CTAs/SM
    if (!smem_set) {
        cudaFuncSetAttribute(gemmM0, cudaFuncAttributeMaxDynamicSharedMemorySize, GEMM_SMEM);
        cudaFuncSetAttribute(gemmM1, cudaFuncAttributeMaxDynamicSharedMemorySize, GEMM_SMEM);
        cudaFuncSetAttribute(attnF,  cudaFuncAttributeMaxDynamicSharedMemorySize, ATTN_SMEM);
        smem_set = 1;
    }

#define SYM(v, s) cudaGetSymbolAddress((void**)&v, s)
    __half *xph,*sah,*q4h,*kvh,*ctxh,*x1h,*ffnh;
    __half *wdcth,*wdecth,*wq16,*wk16,*wv16,*wo16,*w116,*w216;
    float *x1,*tmp,*dec,*gw;
    SYM(xph,g_xph); SYM(sah,g_sah);
    SYM(q4h,g_q4h); SYM(kvh,g_kvh);
    SYM(ctxh,g_ctxh); SYM(x1h,g_x1h); SYM(ffnh,g_ffnh);
    SYM(wdcth,g_wdcth); SYM(wdecth,g_wdecth);
    SYM(wq16,g_wq16); SYM(wk16,g_wk16); SYM(wv16,g_wv16); SYM(wo16,g_wo16);
    SYM(w116,g_w116); SYM(w216,g_w216);
    SYM(x1,g_x1); SYM(tmp,g_tmp); SYM(dec,g_dec); SYM(gw,g_w);
#undef SYM

    const int BLD = Bb*Ll*Dd;
    const int4 NOSEG = make_int4(0x7fffffff, 0x7fffffff, 0x7fffffff, 0);
    const int NOSPLIT = 1 << 30;

    // ---- preprocessing (vectorized) ----
    tdc_split <<<1024, 256>>>(W_dc);
    tdec_split<<<2048, 256>>>(W_dec);
    {
        CvtJobs J;
        J.src[0] = (const float4*)Wq; J.dst[0] = (uint2*)wq16; J.n4[0] = 4*DDc/4;
        J.src[1] = (const float4*)Wk; J.dst[1] = (uint2*)wk16; J.n4[1] = 4*DDc/4;
        J.src[2] = (const float4*)Wv; J.dst[2] = (uint2*)wv16; J.n4[2] = DDc/4;
        J.src[3] = (const float4*)Wo; J.dst[3] = (uint2*)wo16; J.n4[3] = DDc/4;
        J.src[4] = (const float4*)W1; J.dst[4] = (uint2*)w116; J.n4[4] = (long long)Dd*Ff/4;
        J.src[5] = (const float4*)W2; J.dst[5] = (uint2*)w216; J.n4[5] = (long long)Dd*Ff/4;
        long long tot4 = J.n4[0]+J.n4[1]+J.n4[2]+J.n4[3]+J.n4[4]+J.n4[5];
        cvt16<<<2048, 256>>>(J, tot4);
    }
    pad_split_kernel<<<2048, 256>>>(x);
    if (out_size > BLD) {
        long long gap = (long long)out_size - BLD;
        fill0_kernel<<<256, 256>>>(out + BLD, gap);
        agg_kernel<<<1, 1>>>(aggl, out + out_size - 1);
    } else {
        agg_kernel<<<1, 1>>>(aggl, (float*)0);
    }

    // ---- conv GEMM (BT=0, z=1) ----
    gemmM0<<<dim3(Dd/128, (Bb*Ll)/128), 256, GEMM_SMEM>>>(
        xph, wdcth, (const __half*)0, 0, sah, b_dc,
        Dd, Dd, 0, NOSPLIT, 30,
        3, 2LL*Dd, Ll, (long long)(Ll+4)*Dd, Dd, 0, 1, NOSEG, 0, 0);

    // ---- hierarchical decomposition: split-K x4 + deterministic reduce ----
    {
        const long long inOff[3]  = {0, 4096, 6144};
        const long long outOff[3] = {4096, 6144, 7168};
        int Lin[3] = {1024, 512, 256};
        for (int s = 0; s < 3; s++) {
            int M = Bb*(Lin[s]/2);
            long long cnt = (long long)M * Dd;
            gemmM0<<<dim3(Dd/128, M/128, 4), 256, GEMM_SMEM>>>(
                sah + inOff[s]*Dd, wdecth + (long long)s*2*DDc, (const __half*)0,
                dec, 0, 0,
                Dd, Dd, 0, NOSPLIT, 30,
                2, (long long)Dd, Lin[s]/2, (long long)Lin[s]*Dd, 2*Dd, 0, 0, NOSEG, 0, cnt);
            cvt_dec<<<1024, 256>>>(dec, cnt, sah + outOff[s]*Dd, cnt);
        }
    }

    // ---- projection / FFN GEMMs (BT=1) ----
    gemmM1<<<dim3(4*Dd/128, (Bb*Ll)/128), 256, GEMM_SMEM>>>(
        sah, wq16, (const __half*)0, 0, q4h, 0,
        4*Dd, Dd, Dd, NOSPLIT, 10,
        1, 0, Bb*Ll, 0, Dd, 0, 0, NOSEG, DDc, 0);

    gemmM1<<<dim3(2048/128, SAR/128), 256, GEMM_SMEM>>>(
        sah, wk16, wv16, 0, kvh, 0,
        2048, Dd, Dd, 1024, 30,
        1, 0, SAR, 0, Dd, 0, 0,
        make_int4(4096, 6144, 7168, 0), DDc, 0);

    {
        dim3 ag(Ll/64, Hh, Bb);
        attnF<<<ag, 128, ATTN_SMEM>>>(q4h, kvh, ctxh, gw);
    }

    gemmM1<<<dim3(Dd/128, (Bb*Ll)/128), 256, GEMM_SMEM>>>(
        ctxh, wo16, (const __half*)0, tmp, 0, 0,
        Dd, Dd, Dd, NOSPLIT, 30,
        1, 0, Bb*Ll, 0, Dd, 0, 0, NOSEG, 0, 0);

    ln_kernel<<<Bb*Ll, 256>>>(x, tmp, g1, be1, x1, x1h);

    gemmM1<<<dim3(Ff/128, (Bb*Ll)/128), 256, GEMM_SMEM>>>(
        x1h, w116, (const __half*)0, 0, ffnh, b1,
        Ff, Dd, Ff, NOSPLIT, 30,
        1, 0, Bb*Ll, 0, Dd, 0, 2, NOSEG, 0, 0);
    gemmM1<<<dim3(Dd/128, (Bb*Ll)/128), 256, GEMM_SMEM>>>(
        ffnh, w216, (const __half*)0, tmp, 0, b2,
        Dd, Ff, Dd, NOSPLIT, 30,
        1, 0, Bb*Ll, 0, Ff, 0, 0, NOSEG, 0, 0);

    ln_kernel<<<Bb*Ll, 256>>>(x1, tmp, g2, be2, out, (__half*)0);
}

// round 16
// speedup vs baseline: 6.5438x; 1.0323x over previous
#include <cuda_runtime.h>
#include <cuda_fp16.h>
#include <math.h>
#include <stdint.h>

#define Bb 4
#define Ll 1024
#define Dd 1024
#define Hh 16
#define Ff 4096
#define Ss 4
#define DDc (1024LL*1024LL)
#define SAR 7680   // total scale-activation rows: 4096+2048+1024+512

// ================= static scratch (no allocations) =================
__device__ __align__(256) __half g_xph[Bb*(Ll+4)*Dd];
__device__ __align__(256) __half g_sah[SAR*Dd];                    // xc|s1|s2|s3
__device__ __align__(256) __half g_q4h[Bb*Ll*4*Dd];                // [4096][4096]
__device__ __align__(256) __half g_kvh[SAR*2048];                  // [7680][2048] K|V
__device__ __align__(256) __half g_ctxh[Bb*Ll*Dd];
__device__ __align__(256) __half g_x1h[Bb*Ll*Dd];
__device__ __align__(256) __half g_ffnh[Bb*Ll*Ff];
__device__ __align__(256) __half g_wdcth[3*1024*1024];             // [tap][N][K]
__device__ __align__(256) __half g_wdecth[6*1024*1024];            // [s*2+tap][N][K]
__device__ __align__(256) __half g_wq16[4*1024*1024];              // fp16 copies, natural [K][N]
__device__ __align__(256) __half g_wk16[4*1024*1024];
__device__ __align__(256) __half g_wv16[1024*1024];
__device__ __align__(256) __half g_wo16[1024*1024];
__device__ __align__(256) __half g_w116[1024*4096];
__device__ __align__(256) __half g_w216[4096*1024];
__device__ __align__(256) float g_x1[Bb*Ll*Dd];
__device__ __align__(256) float g_tmp[Bb*Ll*Dd];
__device__ __align__(256) float g_dec[4*2048*1024];                // split-K partials (32MB)
__device__ float g_w[Ss];

// ================= PTX helpers (base features only) =================
#define CP16(dst, src)    asm volatile("cp.async.cg.shared.global [%0], [%1], 16;" :: "r"(dst), "l"(src) : "memory")
#define CP_COMMIT()       asm volatile("cp.async.commit_group;" ::: "memory")
#define CP_WAIT1()        asm volatile("cp.async.wait_group 1;" ::: "memory")
#define CP_WAIT0()        asm volatile("cp.async.wait_group 0;" ::: "memory")

#define LDSM4(r0,r1,r2,r3,addr) \
    asm volatile("ldmatrix.sync.aligned.m8n8.x4.shared.b16 {%0,%1,%2,%3}, [%4];" \
        : "=r"(r0),"=r"(r1),"=r"(r2),"=r"(r3) : "r"(addr))
#define LDSM4T(r0,r1,r2,r3,addr) \
    asm volatile("ldmatrix.sync.aligned.m8n8.x4.trans.shared.b16 {%0,%1,%2,%3}, [%4];" \
        : "=r"(r0),"=r"(r1),"=r"(r2),"=r"(r3) : "r"(addr))
#define LDSM2(r0,r1,addr) \
    asm volatile("ldmatrix.sync.aligned.m8n8.x2.shared.b16 {%0,%1}, [%2];" \
        : "=r"(r0),"=r"(r1) : "r"(addr))
#define MMA16816(d, a, b) \
    asm volatile("mma.sync.aligned.m16n8k16.row.col.f32.f16.f16.f32 " \
        "{%0,%1,%2,%3}, {%4,%5,%6,%7}, {%8,%9}, {%0,%1,%2,%3};" \
        : "+f"((d)[0]),"+f"((d)[1]),"+f"((d)[2]),"+f"((d)[3]) \
        : "r"((a)[0]),"r"((a)[1]),"r"((a)[2]),"r"((a)[3]), "r"((b)[0]),"r"((b)[1]))

__device__ __forceinline__ uint32_t smem_u32(const void* p) {
    uint32_t a;
    asm("{ .reg .u64 t; cvta.to.shared.u64 t, %1; cvt.u32.u64 %0, t; }" : "=r"(a) : "l"(p));
    return a;
}

__device__ __forceinline__ uint32_t pack2h(float a, float b) {
    __half2 h2 = __floats2half2_rn(a, b);
    return *(uint32_t*)&h2;
}

// ================= mma.sync fp16 GEMM: 3-stage, optional B-trans, optional split-K =================
template<int BT>
__device__ __forceinline__ void gemm_body(
    const __half* __restrict__ Ah, const __half* __restrict__ Bh, const __half* __restrict__ B2,
    float* __restrict__ Cf, __half* __restrict__ Oh, const float* __restrict__ bias,
    int N, int K, int NB, int nSplit, int nSegShift,
    int taps, long long tapStrideA,
    int lseg, long long segStride, int rowStride, long long offA, int epi,
    int4 segEnd, long long segUnit, long long zCfStride)
{
    extern __shared__ char smem[];
    uint32_t sb = smem_u32(smem);
    const int tid = threadIdx.x;
    const int wid = tid >> 5, lane = tid & 31;
    const int m0 = blockIdx.y * 128, n0 = blockIdx.x * 128;

    const __half* Bsel;
    int ncol = n0;
    if (BT) {
        if (n0 >= nSplit) { Bsel = B2; ncol = n0 - nSplit; }
        else {
            int nseg = n0 >> nSegShift;
            int mseg = (m0 >= segEnd.x) + (m0 >= segEnd.y) + (m0 >= segEnd.z);
            Bsel = Bh + (long long)(nseg + mseg) * segUnit;
            ncol = n0 & ((1 << nSegShift) - 1);
        }
    } else {
        int mseg = (m0 >= segEnd.x) + (m0 >= segEnd.y) + (m0 >= segEnd.z);
        Bsel = Bh + (long long)mseg * segUnit;
    }

    const int r = tid >> 1, half_ = tid & 1;
    const long long mrow = m0 + r;
    const long long aoff0 = (mrow / lseg) * segStride + (mrow % lseg) * (long long)rowStride + offA + half_ * 32;
    uint32_t dstOffA[4];
#pragma unroll
    for (int j = 0; j < 4; j++) {
        uint32_t off = (uint32_t)(r * 128 + half_ * 64 + j * 16);
        dstOffA[j] = off ^ ((off >> 3) & 0x70);
    }
    const int brow = tid >> 2, bq = tid & 3;
    uint32_t bDst[4];
    long long boff0 = 0;
    if (BT) {
#pragma unroll
        for (int j = 0; j < 4; j++) {
            int bp = bq * 64 + j * 16;
            uint32_t raw = (uint32_t)(brow * 128 + (bp & 127));
            bDst[j] = (uint32_t)((bp >> 7) * 8192) + (raw ^ ((raw >> 3) & 0x70));
        }
        boff0 = (long long)brow * NB + ncol + bq * 32;
    } else {
        boff0 = (long long)(n0 + r) * K + half_ * 32;
    }

    const uint32_t bufBase[3] = { sb, sb + 32768, sb + 65536 };
    const int NCk = K >> 6;
    const int NCtot = NCk * taps;
    const int NCz = NCtot / (int)gridDim.z;
    const int c0 = (int)blockIdx.z * NCz;
    const int cEnd = c0 + NCz;
    const long long tapStrideB = (long long)N * K;

    auto issue = [&](int c) {
        uint32_t bs = bufBase[c % 3];
        int tap = c / NCk, kc = c - tap * NCk;
        long long ao = aoff0 + (long long)tap * tapStrideA + kc * 64;
#pragma unroll
        for (int j = 0; j < 4; j++) CP16(bs + dstOffA[j], Ah + ao + j * 8);
        if (BT) {
            long long bo = boff0 + (long long)c * 64 * NB;
#pragma unroll
            for (int j = 0; j < 4; j++) CP16(bs + 16384 + bDst[j], Bsel + bo + j * 8);
        } else {
            long long bo = boff0 + (long long)tap * tapStrideB + kc * 64;
#pragma unroll
            for (int j = 0; j < 4; j++) CP16(bs + 16384 + dstOffA[j], Bsel + bo + j * 8);
        }
        CP_COMMIT();
    };

    const int wm = wid & 1, wn = wid >> 1;
    const int arow = wm * 64 + (lane & 15);
    const uint32_t aRowOff = (uint32_t)(arow * 128);
    const uint32_t aXb = (uint32_t)((arow & 7) << 4);
    const uint32_t aHalf = (uint32_t)((lane >> 4) * 16);
    const uint32_t bRowOff = (uint32_t)((wn * 32 + (lane & 7)) * 128);
    const uint32_t bXb = (uint32_t)((lane & 7) << 4);
    const uint32_t bHalf = (uint32_t)(((lane >> 3) & 1) * 16);
    const uint32_t vrowb = (uint32_t)((lane & 7) + ((lane >> 3) & 1) * 8);
    const uint32_t vbyteb = (uint32_t)(((lane >> 4) & 1) * 16);
    const uint32_t warpNb = (uint32_t)((wn & 1) * 64);
    const uint32_t subSel = (uint32_t)((wn >> 1) * 8192);

    float acc[4][4][4];
#pragma unroll
    for (int i = 0; i < 4; i++)
#pragma unroll
        for (int j = 0; j < 4; j++)
#pragma unroll
            for (int e = 0; e < 4; e++) acc[i][j][e] = 0.f;

    issue(c0); issue(c0 + 1);

#pragma unroll 1
    for (int c = c0; c < cEnd; c++) {
        if (c == cEnd - 1) CP_WAIT0(); else CP_WAIT1();
        __syncthreads();
        if (c + 2 < cEnd) issue(c + 2);

        const uint32_t bs = bufBase[c % 3];
#pragma unroll
        for (int k16 = 0; k16 < 4; k16++) {
            const uint32_t aoff = aRowOff + ((k16 * 32 + aHalf) ^ aXb);
            uint32_t ah[4][4], bh[4][2];
#pragma unroll
            for (int i = 0; i < 4; i++)
                LDSM4(ah[i][0], ah[i][1], ah[i][2], ah[i][3], bs + i * 2048 + aoff);
            if (BT) {
                uint32_t subB = bs + 16384 + subSel;
#pragma unroll
                for (int t2 = 0; t2 < 2; t2++) {
                    uint32_t off = (k16 * 16 + vrowb) * 128 + warpNb + t2 * 32 + vbyteb;
                    off ^= (off >> 3) & 0x70;
                    LDSM4T(bh[2*t2][0], bh[2*t2][1], bh[2*t2+1][0], bh[2*t2+1][1], subB + off);
                }
            } else {
                const uint32_t boff = bRowOff + ((k16 * 32 + bHalf) ^ bXb);
#pragma unroll
                for (int j = 0; j < 4; j++)
                    LDSM2(bh[j][0], bh[j][1], bs + 16384 + j * 1024 + boff);
            }
#pragma unroll
            for (int i = 0; i < 4; i++)
#pragma unroll
                for (int j = 0; j < 4; j++)
                    MMA16816(acc[i][j], ah[i], bh[j]);
        }
    }

    if (Cf) Cf += (long long)blockIdx.z * zCfStride;
#pragma unroll
    for (int i = 0; i < 4; i++)
#pragma unroll
        for (int j = 0; j < 4; j++)
#pragma unroll
            for (int p = 0; p < 2; p++) {
                int rr = m0 + wm * 64 + i * 16 + (lane >> 2) + p * 8;
                int cc = n0 + wn * 32 + j * 8 + (lane & 3) * 2;
                float v0 = acc[i][j][p * 2];
                float v1 = acc[i][j][p * 2 + 1];
                if (bias) { v0 += bias[cc]; v1 += bias[cc + 1]; }
                if (epi == 1) { v0 = fmaxf(v0, 0.f); v1 = fmaxf(v1, 0.f); }
                else if (epi == 2) {
                    v0 = 0.5f * v0 * (1.f + erff(v0 * 0.70710678118654752f));
                    v1 = 0.5f * v1 * (1.f + erff(v1 * 0.70710678118654752f));
                }
                long long idx = (long long)rr * N + cc;
                if (Cf) { float2 f; f.x = v0; f.y = v1; *(float2*)(Cf + idx) = f; }
                if (Oh) *(uint32_t*)(Oh + idx) = pack2h(v0, v1);
            }
}

__global__ __launch_bounds__(256, 2) void gemmM0(
    const __half* __restrict__ Ah, const __half* __restrict__ Bh, const __half* __restrict__ B2,
    float* __restrict__ Cf, __half* __restrict__ Oh, const float* __restrict__ bias,
    int N, int K, int NB, int nSplit, int nSegShift,
    int taps, long long tapStrideA, int lseg, long long segStride, int rowStride,
    long long offA, int epi, int4 segEnd, long long segUnit, long long zCfStride)
{
    gemm_body<0>(Ah, Bh, B2, Cf, Oh, bias, N, K, NB, nSplit, nSegShift,
                 taps, tapStrideA, lseg, segStride, rowStride, offA, epi, segEnd, segUnit, zCfStride);
}

__global__ __launch_bounds__(256, 2) void gemmM1(
    const __half* __restrict__ Ah, const __half* __restrict__ Bh, const __half* __restrict__ B2,
    float* __restrict__ Cf, __half* __restrict__ Oh, const float* __restrict__ bias,
    int N, int K, int NB, int nSplit, int nSegShift,
    int taps, long long tapStrideA, int lseg, long long segStride, int rowStride,
    long long offA, int epi, int4 segEnd, long long segUnit, long long zCfStride)
{
    gemm_body<1>(Ah, Bh, B2, Cf, Oh, bias, N, K, NB, nSplit, nSegShift,
                 taps, tapStrideA, lseg, segStride, rowStride, offA, epi, segEnd, segUnit, zCfStride);
}

// sum 4 split-K fp32 partials -> fp16 (fixed order, deterministic)
__global__ void cvt_dec(const float* __restrict__ scr, long long zStride,
                        __half* __restrict__ dst, long long n)
{
    for (long long i = blockIdx.x*256LL + threadIdx.x; i * 2 < n; i += (long long)gridDim.x*256LL) {
        long long e = i * 2;
        float2 a = *(const float2*)(scr + e);
        float2 b = *(const float2*)(scr + e + zStride);
        float2 c = *(const float2*)(scr + e + 2*zStride);
        float2 d = *(const float2*)(scr + e + 3*zStride);
        float v0 = ((a.x + b.x) + (c.x + d.x));
        float v1 = ((a.y + b.y) + (c.y + d.y));
        *(uint32_t*)(dst + e) = pack2h(v0, v1);
    }
}

// ================= fused 4-scale flash attention (fp16; 3-stage KV) =================
__global__ __launch_bounds__(128, 3) void attnF(
    const __half* __restrict__ Qh4, const __half* __restrict__ KVh,
    __half* __restrict__ Oh, const float* __restrict__ gw)
{
    extern __shared__ char smem[];
    uint32_t sb = smem_u32(smem);
    const int tid = threadIdx.x;
    const int w = tid >> 5, lane = tid & 31;
    const int b = blockIdx.z, h = blockIdx.y;
    const int q0 = blockIdx.x * 64;

    float w4[4];
#pragma unroll
    for (int s = 0; s < 4; s++) w4[s] = gw[s];

    const int r = tid >> 1, half_ = tid & 1;
    uint32_t dstOff[4];
#pragma unroll
    for (int j = 0; j < 4; j++) {
        uint32_t off = (uint32_t)(r * 128 + half_ * 64 + j * 16);
        dstOff[j] = off ^ ((off >> 3) & 0x70);
    }
    const uint32_t sQb[2] = { sb, sb + 8192 };
    const uint32_t kvb[3] = { sb + 16384, sb + 32768, sb + 49152 };

    const long long qrowbase = ((long long)(b * Ll + q0 + r)) * 4096 + h * 64 + half_ * 32;

    auto kvRow = [&](int cc) -> long long {
        int s2  = (cc < 16) ? 0 : (cc < 24) ? 1 : (cc < 28) ? 2 : 3;
        int bas = (s2 == 0) ? 0 : (s2 == 1) ? 16 : (s2 == 2) ? 24 : 28;
        int Ls2 = (s2 == 0) ? 1024 : (s2 == 1) ? 512 : (s2 == 2) ? 256 : 128;
        int ro2 = (s2 == 0) ? 0 : (s2 == 1) ? 4096 : (s2 == 2) ? 6144 : 7168;
        int kc2 = cc - bas;
        return ((long long)(ro2 + b * Ls2 + kc2 * 64 + r)) * 2048 + h * 64 + half_ * 32;
    };

    {
#pragma unroll
        for (int j = 0; j < 4; j++)
            CP16(sQb[0] + dstOff[j], Qh4 + qrowbase + j * 8);
        long long kr = kvRow(0);
#pragma unroll
        for (int j = 0; j < 4; j++) {
            CP16(kvb[0]        + dstOff[j], KVh + kr + j * 8);
            CP16(kvb[0] + 8192 + dstOff[j], KVh + kr + 1024 + j * 8);
        }
        CP_COMMIT();
        kr = kvRow(1);
#pragma unroll
        for (int j = 0; j < 4; j++) {
            CP16(kvb[1]        + dstOff[j], KVh + kr + j * 8);
            CP16(kvb[1] + 8192 + dstOff[j], KVh + kr + 1024 + j * 8);
        }
        CP_COMMIT();
    }

    const uint32_t qoffBase = (uint32_t)((w * 16 + (lane & 15)) * 128 + ((lane >> 4) & 1) * 16);
    const uint32_t krowb = (uint32_t)((lane & 7) + ((lane >> 4) & 1) * 8);
    const uint32_t kbyteb = (uint32_t)(((lane >> 3) & 1) * 16);
    const uint32_t vrowb = (uint32_t)((lane & 7) + ((lane >> 3) & 1) * 8);
    const uint32_t vbyteb = (uint32_t)(((lane >> 4) & 1) * 16);

    uint32_t qah[4][4];
    float oacc[8][4];
#pragma unroll
    for (int t = 0; t < 8; t++)
#pragma unroll
        for (int e = 0; e < 4; e++) oacc[t][e] = 0.f;
    float o[8][4];
    float m0v = -1e30f, m1v = -1e30f, l0 = 0.f, l1 = 0.f;

#pragma unroll 1
    for (int c = 0; c < 30; c++) {
        const int s  = (c < 16) ? 0 : (c < 24) ? 1 : (c < 28) ? 2 : 3;
        const int bas = (s == 0) ? 0 : (s == 1) ? 16 : (s == 2) ? 24 : 28;
        const int nch = (s == 0) ? 16 : (s == 1) ? 8 : (s == 2) ? 4 : 2;
        const int kc = c - bas;

        if (c == 29) CP_WAIT0(); else CP_WAIT1();
        __syncthreads();

        {
            bool doCommit = false;
            int cc = c + 2;
            if (cc < 30) {
                long long kr = kvRow(cc);
                uint32_t bs2 = kvb[cc % 3];
#pragma unroll
                for (int j = 0; j < 4; j++) {
                    CP16(bs2        + dstOff[j], KVh + kr + j * 8);
                    CP16(bs2 + 8192 + dstOff[j], KVh + kr + 1024 + j * 8);
                }
                doCommit = true;
            }
            if (kc == 0 && s < 3) {
                uint32_t qb2 = sQb[(s + 1) & 1];
                long long qsrc = qrowbase + (long long)(s + 1) * 1024;
#pragma unroll
                for (int j = 0; j < 4; j++)
                    CP16(qb2 + dstOff[j], Qh4 + qsrc + j * 8);
                doCommit = true;
            }
            if (doCommit) CP_COMMIT();
        }

        if (kc == 0) {
            uint32_t qb = sQb[s & 1];
#pragma unroll
            for (int k16 = 0; k16 < 4; k16++) {
                uint32_t off = qoffBase + k16 * 32;
                off ^= (off >> 3) & 0x70;
                LDSM4(qah[k16][0], qah[k16][1], qah[k16][2], qah[k16][3], qb + off);
            }
            m0v = -1e30f; m1v = -1e30f; l0 = 0.f; l1 = 0.f;
#pragma unroll
            for (int t = 0; t < 8; t++)
#pragma unroll
                for (int e = 0; e < 4; e++) o[t][e] = 0.f;
        }

        const uint32_t bs = kvb[c % 3];
        float sc[8][4];
#pragma unroll
        for (int t = 0; t < 8; t++)
#pragma unroll
            for (int e = 0; e < 4; e++) sc[t][e] = 0.f;
#pragma unroll
        for (int k16 = 0; k16 < 4; k16++) {
            uint32_t kh[8][2];
#pragma unroll
            for (int t4 = 0; t4 < 4; t4++) {
                uint32_t off = (t4 * 16 + krowb) * 128 + k16 * 32 + kbyteb;
                off ^= (off >> 3) & 0x70;
                LDSM4(kh[2*t4][0], kh[2*t4][1], kh[2*t4+1][0], kh[2*t4+1][1], bs + off);
            }
#pragma unroll
            for (int j = 0; j < 8; j++)
                MMA16816(sc[j], qah[k16], kh[j]);
        }

        float rmax0 = -1e30f, rmax1 = -1e30f;
#pragma unroll
        for (int t = 0; t < 8; t++) {
            sc[t][0] *= 0.125f; sc[t][1] *= 0.125f; sc[t][2] *= 0.125f; sc[t][3] *= 0.125f;
            rmax0 = fmaxf(rmax0, fmaxf(sc[t][0], sc[t][1]));
            rmax1 = fmaxf(rmax1, fmaxf(sc[t][2], sc[t][3]));
        }
        rmax0 = fmaxf(rmax0, __shfl_xor_sync(0xffffffffu, rmax0, 1));
        rmax0 = fmaxf(rmax0, __shfl_xor_sync(0xffffffffu, rmax0, 2));
        rmax1 = fmaxf(rmax1, __shfl_xor_sync(0xffffffffu, rmax1, 1));
        rmax1 = fmaxf(rmax1, __shfl_xor_sync(0xffffffffu, rmax1, 2));
        float mn0 = fmaxf(m0v, rmax0), mn1 = fmaxf(m1v, rmax1);
        float fac0 = __expf(m0v - mn0), fac1 = __expf(m1v - mn1);
        float rs0 = 0.f, rs1 = 0.f;
#pragma unroll
        for (int t = 0; t < 8; t++) {
            sc[t][0] = __expf(sc[t][0] - mn0); sc[t][1] = __expf(sc[t][1] - mn0);
            sc[t][2] = __expf(sc[t][2] - mn1); sc[t][3] = __expf(sc[t][3] - mn1);
            rs0 += sc[t][0] + sc[t][1];
            rs1 += sc[t][2] + sc[t][3];
        }
        rs0 += __shfl_xor_sync(0xffffffffu, rs0, 1);
        rs0 += __shfl_xor_sync(0xffffffffu, rs0, 2);
        rs1 += __shfl_xor_sync(0xffffffffu, rs1, 1);
        rs1 += __shfl_xor_sync(0xffffffffu, rs1, 2);
        l0 = l0 * fac0 + rs0; l1 = l1 * fac1 + rs1;
        m0v = mn0; m1v = mn1;
#pragma unroll
        for (int t = 0; t < 8; t++) {
            o[t][0] *= fac0; o[t][1] *= fac0; o[t][2] *= fac1; o[t][3] *= fac1;
        }

        // ---- O += P V (P hi only) ----
#pragma unroll
        for (int k16 = 0; k16 < 4; k16++) {
            uint32_t ph[4];
            int t = 2 * k16;
            ph[0] = pack2h(sc[t][0],   sc[t][1]);
            ph[1] = pack2h(sc[t][2],   sc[t][3]);
            ph[2] = pack2h(sc[t+1][0], sc[t+1][1]);
            ph[3] = pack2h(sc[t+1][2], sc[t+1][3]);
            uint32_t vh[8][2];
#pragma unroll
            for (int t4 = 0; t4 < 4; t4++) {
                uint32_t off = (k16 * 16 + vrowb) * 128 + t4 * 32 + vbyteb;
                off ^= (off >> 3) & 0x70;
                LDSM4T(vh[2*t4][0], vh[2*t4][1], vh[2*t4+1][0], vh[2*t4+1][1], bs + 8192 + off);
            }
#pragma unroll
            for (int t8 = 0; t8 < 8; t8++)
                MMA16816(o[t8], ph, vh[t8]);
        }

        if (kc == nch - 1) {
            float ws = w4[s];
            float inv0 = ws / l0, inv1 = ws / l1;
#pragma unroll
            for (int t = 0; t < 8; t++) {
                oacc[t][0] += o[t][0] * inv0;
                oacc[t][1] += o[t][1] * inv0;
                oacc[t][2] += o[t][2] * inv1;
                oacc[t][3] += o[t][3] * inv1;
            }
        }
    }

    int g = lane >> 2;
    int qrow0 = q0 + w * 16 + g;
    long long base0 = ((long long)(b * Ll + qrow0)) * Dd + h * 64;
    long long base1 = base0 + 8LL * Dd;
#pragma unroll
    for (int t = 0; t < 8; t++) {
        int d0 = t * 8 + (lane & 3) * 2;
        *(uint32_t*)(Oh + base0 + d0) = pack2h(oacc[t][0], oacc[t][1]);
        *(uint32_t*)(Oh + base1 + d0) = pack2h(oacc[t][2], oacc[t][3]);
    }
}

// ================= LayerNorm: out = LN(a + r), optional fp16 =================
__global__ __launch_bounds__(256) void ln_kernel(
    const float* __restrict__ a, const float* __restrict__ rr,
    const float* __restrict__ gamma, const float* __restrict__ beta,
    float* __restrict__ out, __half* __restrict__ oh)
{
    __shared__ float red[8], red2[8];
    __shared__ float smu, sinv;
    int row = blockIdx.x, tid = threadIdx.x;
    long long base = (long long)row * Dd;
    float4 va = ((const float4*)(a + base))[tid];
    float4 vr = ((const float4*)(rr + base))[tid];
    float x0 = va.x+vr.x, x1 = va.y+vr.y, x2 = va.z+vr.z, x3 = va.w+vr.w;
    float s  = x0+x1+x2+x3;
    float s2 = x0*x0 + x1*x1 + x2*x2 + x3*x3;
#pragma unroll
    for (int off = 16; off >= 1; off >>= 1) {
        s  += __shfl_xor_sync(0xffffffffu, s,  off);
        s2 += __shfl_xor_sync(0xffffffffu, s2, off);
    }
    int w = tid >> 5, lane = tid & 31;
    if (lane == 0) { red[w] = s; red2[w] = s2; }
    __syncthreads();
    if (tid == 0) {
        float S = 0.f, S2 = 0.f;
        for (int i = 0; i < 8; i++) { S += red[i]; S2 += red2[i]; }
        float mu = S * (1.f/Dd);
        smu = mu;
        sinv = rsqrtf(S2 * (1.f/Dd) - mu*mu + 1e-5f);
    }
    __syncthreads();
    float mu = smu, inv = sinv;
    float4 gg = ((const float4*)gamma)[tid];
    float4 bb = ((const float4*)beta)[tid];
    float y0 = (x0-mu)*inv*gg.x + bb.x;
    float y1 = (x1-mu)*inv*gg.y + bb.y;
    float y2 = (x2-mu)*inv*gg.z + bb.z;
    float y3 = (x3-mu)*inv*gg.w + bb.w;
    float4 y; y.x=y0; y.y=y1; y.z=y2; y.w=y3;
    ((float4*)(out + base))[tid] = y;
    if (oh) {
        ((uint32_t*)(oh + base))[tid*2]   = pack2h(y0, y1);
        ((uint32_t*)(oh + base))[tid*2+1] = pack2h(y2, y3);
    }
}

// ================= fused preprocessing: tdc + tdec + weight-cvt + pad in ONE launch =================
struct CvtJobs {
    const float4* src[6];
    uint2* dst[6];
    long long n4[6];
};
__global__ void mega_preproc(const float* __restrict__ Wdc, const float* __restrict__ Wdec,
                             CvtJobs J, long long tot4, const float* __restrict__ x)
{
    const long long stride = (long long)gridDim.x * 256LL;
    const long long tid0 = blockIdx.x*256LL + threadIdx.x;

    // job 1: W_dc [o][i][3] -> 3 planes
    for (long long idx = tid0; idx < DDc; idx += stride) {
        const float* p = Wdc + idx * 3;
        g_wdcth[idx]         = __float2half_rn(p[0]);
        g_wdcth[DDc + idx]   = __float2half_rn(p[1]);
        g_wdcth[2*DDc + idx] = __float2half_rn(p[2]);
    }
    // job 2: W_dec [s][o][i][2] -> 6 planes
    for (long long idx = tid0; idx < 3*DDc; idx += stride) {
        int s = (int)(idx / DDc);
        long long rem = idx - (long long)s * DDc;
        float2 v = *(const float2*)(Wdec + idx * 2);
        g_wdecth[(long long)(2*s)   * DDc + rem] = __float2half_rn(v.x);
        g_wdecth[(long long)(2*s+1) * DDc + rem] = __float2half_rn(v.y);
    }
    // job 3: flat fp32->fp16 weight conversions
    for (long long i = tid0; i < tot4; i += stride) {
        long long rr = i; int j = 0;
#pragma unroll
        for (int t = 0; t < 5; t++) if (rr >= J.n4[j]) { rr -= J.n4[j]; j++; }
        float4 v = J.src[j][rr];
        uint2 oo; oo.x = pack2h(v.x, v.y); oo.y = pack2h(v.z, v.w);
        J.dst[j][rr] = oo;
    }
    // job 4: pad + convert x
    const long long total4 = (long long)Bb*(Ll+4)*Dd/4;
    for (long long i4 = tid0; i4 < total4; i4 += stride) {
        long long i = i4 * 4;
        int d = (int)(i & (Dd-1));
        long long t = i >> 10;
        int p = (int)(t % (Ll+4));
        int b = (int)(t / (Ll+4));
        uint2 oo;
        if (p >= 2 && p < Ll+2) {
            float4 v = *(const float4*)(x + (((long long)b*Ll + (p-2)) << 10) + d);
            oo.x = pack2h(v.x, v.y); oo.y = pack2h(v.z, v.w);
        } else {
            oo.x = 0u; oo.y = 0u;
        }
        *(uint2*)(g_xph + i) = oo;
    }
}

__global__ void agg_kernel(const float* __restrict__ logits, float* __restrict__ aux)
{
    float mx = -1e30f;
    for (int s = 0; s < Ss; s++) mx = fmaxf(mx, logits[s]);
    float e[Ss], sum = 0.f;
    for (int s = 0; s < Ss; s++) { e[s] = expf(logits[s] - mx); sum += e[s]; }
    float ent = 0.f;
    for (int s = 0; s < Ss; s++) {
        float w = e[s] / sum;
        g_w[s] = w;
        ent -= w * logf(w + 1e-9f);
    }
    if (aux) *aux = ent;
}

__global__ void fill0_kernel(float* p, long long n)
{
    for (long long i = blockIdx.x*256LL + threadIdx.x; i < n; i += (long long)gridDim.x*256LL)
        p[i] = 0.f;
}

// ================= launch =================
extern "C" void kernel_launch(void* const* d_in, const int* in_sizes, int n_in,
                              void* d_out, int out_size)
{
    const float* x     = (const float*)d_in[0];
    const float* W_dc  = (const float*)d_in[1];
    const float* b_dc  = (const float*)d_in[2];
    const float* W_dec = (const float*)d_in[3];
    const float* Wq    = (const float*)d_in[4];
    const float* Wk    = (const float*)d_in[5];
    const float* Wv    = (const float*)d_in[6];
    const float* Wo    = (const float*)d_in[7];
    const float* aggl  = (const float*)d_in[8];
    const float* g1    = (const float*)d_in[9];
    const float* be1   = (const float*)d_in[10];
    const float* g2    = (const float*)d_in[11];
    const float* be2   = (const float*)d_in[12];
    const float* W1    = (const float*)d_in[13];
    const float* b1    = (const float*)d_in[14];
    const float* W2    = (const float*)d_in[15];
    const float* b2    = (const float*)d_in[16];
    float* out = (float*)d_out;

    static int smem_set = 0;
    const int GEMM_SMEM = 3 * 32768;   // 96KB, 2 CTAs/SM
    const int ATTN_SMEM = 4 * 16384;   // 64KB, 3 CTAs/SM
    if (!smem_set) {
        cudaFuncSetAttribute(gemmM0, cudaFuncAttributeMaxDynamicSharedMemorySize, GEMM_SMEM);
        cudaFuncSetAttribute(gemmM1, cudaFuncAttributeMaxDynamicSharedMemorySize, GEMM_SMEM);
        cudaFuncSetAttribute(attnF,  cudaFuncAttributeMaxDynamicSharedMemorySize, ATTN_SMEM);
        smem_set = 1;
    }

#define SYM(v, s) cudaGetSymbolAddress((void**)&v, s)
    __half *xph,*sah,*q4h,*kvh,*ctxh,*x1h,*ffnh;
    __half *wdcth,*wdecth,*wq16,*wk16,*wv16,*wo16,*w116,*w216;
    float *x1,*tmp,*dec,*gw;
    SYM(xph,g_xph); SYM(sah,g_sah);
    SYM(q4h,g_q4h); SYM(kvh,g_kvh);
    SYM(ctxh,g_ctxh); SYM(x1h,g_x1h); SYM(ffnh,g_ffnh);
    SYM(wdcth,g_wdcth); SYM(wdecth,g_wdecth);
    SYM(wq16,g_wq16); SYM(wk16,g_wk16); SYM(wv16,g_wv16); SYM(wo16,g_wo16);
    SYM(w116,g_w116); SYM(w216,g_w216);
    SYM(x1,g_x1); SYM(tmp,g_tmp); SYM(dec,g_dec); SYM(gw,g_w);
#undef SYM

    const int BLD = Bb*Ll*Dd;
    const int4 NOSEG = make_int4(0x7fffffff, 0x7fffffff, 0x7fffffff, 0);
    const int NOSPLIT = 1 << 30;

    // ---- preprocessing: single fused launch ----
    {
        CvtJobs J;
        J.src[0] = (const float4*)Wq; J.dst[0] = (uint2*)wq16; J.n4[0] = 4*DDc/4;
        J.src[1] = (const float4*)Wk; J.dst[1] = (uint2*)wk16; J.n4[1] = 4*DDc/4;
        J.src[2] = (const float4*)Wv; J.dst[2] = (uint2*)wv16; J.n4[2] = DDc/4;
        J.src[3] = (const float4*)Wo; J.dst[3] = (uint2*)wo16; J.n4[3] = DDc/4;
        J.src[4] = (const float4*)W1; J.dst[4] = (uint2*)w116; J.n4[4] = (long long)Dd*Ff/4;
        J.src[5] = (const float4*)W2; J.dst[5] = (uint2*)w216; J.n4[5] = (long long)Dd*Ff/4;
        long long tot4 = J.n4[0]+J.n4[1]+J.n4[2]+J.n4[3]+J.n4[4]+J.n4[5];
        mega_preproc<<<2368, 256>>>(W_dc, W_dec, J, tot4, x);
    }
    if (out_size > BLD) {
        long long gap = (long long)out_size - BLD;
        fill0_kernel<<<256, 256>>>(out + BLD, gap);
        agg_kernel<<<1, 1>>>(aggl, out + out_size - 1);
    } else {
        agg_kernel<<<1, 1>>>(aggl, (float*)0);
    }

    // ---- conv GEMM (BT=0, z=1) ----
    gemmM0<<<dim3(Dd/128, (Bb*Ll)/128), 256, GEMM_SMEM>>>(
        xph, wdcth, (const __half*)0, 0, sah, b_dc,
        Dd, Dd, 0, NOSPLIT, 30,
        3, 2LL*Dd, Ll, (long long)(Ll+4)*Dd, Dd, 0, 1, NOSEG, 0, 0);

    // ---- hierarchical decomposition: split-K x4 + deterministic reduce ----
    {
        const long long inOff[3]  = {0, 4096, 6144};
        const long long outOff[3] = {4096, 6144, 7168};
        int Lin[3] = {1024, 512, 256};
        for (int s = 0; s < 3; s++) {
            int M = Bb*(Lin[s]/2);
            long long cnt = (long long)M * Dd;
            gemmM0<<<dim3(Dd/128, M/128, 4), 256, GEMM_SMEM>>>(
                sah + inOff[s]*Dd, wdecth + (long long)s*2*DDc, (const __half*)0,
                dec, 0, 0,
                Dd, Dd, 0, NOSPLIT, 30,
                2, (long long)Dd, Lin[s]/2, (long long)Lin[s]*Dd, 2*Dd, 0, 0, NOSEG, 0, cnt);
            cvt_dec<<<1024, 256>>>(dec, cnt, sah + outOff[s]*Dd, cnt);
        }
    }

    // ---- projection / FFN GEMMs (BT=1) ----
    gemmM1<<<dim3(4*Dd/128, (Bb*Ll)/128), 256, GEMM_SMEM>>>(
        sah, wq16, (const __half*)0, 0, q4h, 0,
        4*Dd, Dd, Dd, NOSPLIT, 10,
        1, 0, Bb*Ll, 0, Dd, 0, 0, NOSEG, DDc, 0);

    gemmM1<<<dim3(2048/128, SAR/128), 256, GEMM_SMEM>>>(
        sah, wk16, wv16, 0, kvh, 0,
        2048, Dd, Dd, 1024, 30,
        1, 0, SAR, 0, Dd, 0, 0,
        make_int4(4096, 6144, 7168, 0), DDc, 0);

    {
        dim3 ag(Ll/64, Hh, Bb);
        attnF<<<ag, 128, ATTN_SMEM>>>(q4h, kvh, ctxh, gw);
    }

    gemmM1<<<dim3(Dd/128, (Bb*Ll)/128), 256, GEMM_SMEM>>>(
        ctxh, wo16, (const __half*)0, tmp, 0, 0,
        Dd, Dd, Dd, NOSPLIT, 30,
        1, 0, Bb*Ll, 0, Dd, 0, 0, NOSEG, 0, 0);

    ln_kernel<<<Bb*Ll, 256>>>(x, tmp, g1, be1, x1, x1h);

    gemmM1<<<dim3(Ff/128, (Bb*Ll)/128), 256, GEMM_SMEM>>>(
        x1h, w116, (const __half*)0, 0, ffnh, b1,
        Ff, Dd, Ff, NOSPLIT, 30,
        1, 0, Bb*Ll, 0, Dd, 0, 2, NOSEG, 0, 0);
    gemmM1<<<dim3(Dd/128, (Bb*Ll)/128), 256, GEMM_SMEM>>>(
        ffnh, w216, (const __half*)0, tmp, 0, b2,
        Dd, Ff, Dd, NOSPLIT, 30,
        1, 0, Bb*Ll, 0, Ff, 0, 0, NOSEG, 0, 0);

    ln_kernel<<<Bb*Ll, 256>>>(x1, tmp, g2, be2, out, (__half*)0);
}